// round 1
// baseline (speedup 1.0000x reference)
#include <cuda_runtime.h>
#include <math.h>

#define B_SZ   4
#define SEQ    2048
#define DMODEL 1024
#define NH     16
#define DH     64
#define ROWS   (B_SZ*SEQ)     // 8192
#define N_QKV  (3*DMODEL)     // 3072

// Scratch (allocation-free: device globals)
__device__ float g_K[B_SZ*NH*SEQ*DH];   // [bh][s][d]
__device__ float g_Q[B_SZ*NH*SEQ*DH];
__device__ float g_V[B_SZ*NH*SEQ*DH];
__device__ float g_O[ROWS*DMODEL];      // [b*S + s][h*DH + d]

// ---------------------------------------------------------------------------
// SGEMM 128x128x16 tile, 256 threads, 8x8 micro-tile.
// Kernel 1: X[8192,1024] @ W_in[1024,3072] + b_in -> scatter into K/Q/V scratch
// ---------------------------------------------------------------------------
__global__ __launch_bounds__(256) void gemm_qkv_kernel(
    const float* __restrict__ A,      // x flattened [8192,1024]
    const float* __restrict__ B,      // w_in [1024,3072]
    const float* __restrict__ bias)   // b_in [3072]
{
    __shared__ float AsT[16][128];
    __shared__ float Bs[16][128];

    const int N = N_QKV;
    int tid = threadIdx.x;
    int tx = tid & 15, ty = tid >> 4;
    int m0 = blockIdx.y * 128, n0 = blockIdx.x * 128;

    float acc[8][8];
#pragma unroll
    for (int i = 0; i < 8; i++)
#pragma unroll
        for (int j = 0; j < 8; j++) acc[i][j] = 0.f;

    int arow = tid >> 1, acol = (tid & 1) * 8;
    int brow = tid >> 4, bcol = (tid & 15) * 8;
    const float* Ap = A + (m0 + arow) * DMODEL + acol;
    const float* Bp = B + brow * N + n0 + bcol;

    for (int k0 = 0; k0 < DMODEL; k0 += 16) {
        float4 a0 = *(const float4*)(Ap + k0);
        float4 a1 = *(const float4*)(Ap + k0 + 4);
        float4 b0 = *(const float4*)(Bp + k0 * N);
        float4 b1 = *(const float4*)(Bp + k0 * N + 4);
        __syncthreads();
        AsT[acol + 0][arow] = a0.x; AsT[acol + 1][arow] = a0.y;
        AsT[acol + 2][arow] = a0.z; AsT[acol + 3][arow] = a0.w;
        AsT[acol + 4][arow] = a1.x; AsT[acol + 5][arow] = a1.y;
        AsT[acol + 6][arow] = a1.z; AsT[acol + 7][arow] = a1.w;
        *(float4*)&Bs[brow][bcol]     = b0;
        *(float4*)&Bs[brow][bcol + 4] = b1;
        __syncthreads();
#pragma unroll
        for (int kk = 0; kk < 16; kk++) {
            float a[8], b[8];
            *(float4*)(a)     = *(const float4*)&AsT[kk][ty * 8];
            *(float4*)(a + 4) = *(const float4*)&AsT[kk][ty * 8 + 4];
            *(float4*)(b)     = *(const float4*)&Bs[kk][tx * 8];
            *(float4*)(b + 4) = *(const float4*)&Bs[kk][tx * 8 + 4];
#pragma unroll
            for (int i = 0; i < 8; i++)
#pragma unroll
                for (int j = 0; j < 8; j++) acc[i][j] += a[i] * b[j];
        }
    }

    // Epilogue: add bias, scatter to K/Q/V in [bh][s][d] layout.
    // split order in reference is (k, q, v).
#pragma unroll
    for (int i = 0; i < 8; i++) {
        int m = m0 + ty * 8 + i;
        int bb = m >> 11, s = m & (SEQ - 1);
#pragma unroll
        for (int j = 0; j < 8; j++) {
            int n = n0 + tx * 8 + j;
            float v = acc[i][j] + bias[n];
            int chunk = n >> 10;
            int c = n & (DMODEL - 1);
            int h = c >> 6, d = c & (DH - 1);
            float* dst = (chunk == 0) ? g_K : (chunk == 1 ? g_Q : g_V);
            dst[(((bb << 4) + h) * SEQ + s) * DH + d] = v;
        }
    }
}

// ---------------------------------------------------------------------------
// Kernel 3: O[8192,1024] @ W_out[1024,1024] + b_out -> d_out
// ---------------------------------------------------------------------------
__global__ __launch_bounds__(256) void gemm_out_kernel(
    const float* __restrict__ B,      // w_out [1024,1024]
    const float* __restrict__ bias,   // b_out [1024]
    float* __restrict__ C)            // out [8192,1024]
{
    __shared__ float AsT[16][128];
    __shared__ float Bs[16][128];

    const int N = DMODEL;
    int tid = threadIdx.x;
    int tx = tid & 15, ty = tid >> 4;
    int m0 = blockIdx.y * 128, n0 = blockIdx.x * 128;

    float acc[8][8];
#pragma unroll
    for (int i = 0; i < 8; i++)
#pragma unroll
        for (int j = 0; j < 8; j++) acc[i][j] = 0.f;

    int arow = tid >> 1, acol = (tid & 1) * 8;
    int brow = tid >> 4, bcol = (tid & 15) * 8;
    const float* Ap = g_O + (m0 + arow) * DMODEL + acol;
    const float* Bp = B + brow * N + n0 + bcol;

    for (int k0 = 0; k0 < DMODEL; k0 += 16) {
        float4 a0 = *(const float4*)(Ap + k0);
        float4 a1 = *(const float4*)(Ap + k0 + 4);
        float4 b0 = *(const float4*)(Bp + k0 * N);
        float4 b1 = *(const float4*)(Bp + k0 * N + 4);
        __syncthreads();
        AsT[acol + 0][arow] = a0.x; AsT[acol + 1][arow] = a0.y;
        AsT[acol + 2][arow] = a0.z; AsT[acol + 3][arow] = a0.w;
        AsT[acol + 4][arow] = a1.x; AsT[acol + 5][arow] = a1.y;
        AsT[acol + 6][arow] = a1.z; AsT[acol + 7][arow] = a1.w;
        *(float4*)&Bs[brow][bcol]     = b0;
        *(float4*)&Bs[brow][bcol + 4] = b1;
        __syncthreads();
#pragma unroll
        for (int kk = 0; kk < 16; kk++) {
            float a[8], b[8];
            *(float4*)(a)     = *(const float4*)&AsT[kk][ty * 8];
            *(float4*)(a + 4) = *(const float4*)&AsT[kk][ty * 8 + 4];
            *(float4*)(b)     = *(const float4*)&Bs[kk][tx * 8];
            *(float4*)(b + 4) = *(const float4*)&Bs[kk][tx * 8 + 4];
#pragma unroll
            for (int i = 0; i < 8; i++)
#pragma unroll
                for (int j = 0; j < 8; j++) acc[i][j] += a[i] * b[j];
        }
    }

#pragma unroll
    for (int i = 0; i < 8; i++) {
        int m = m0 + ty * 8 + i;
        float out[8];
#pragma unroll
        for (int j = 0; j < 8; j++) out[j] = acc[i][j] + bias[n0 + tx * 8 + j];
        *(float4*)&C[m * DMODEL + n0 + tx * 8]     = *(float4*)(out);
        *(float4*)&C[m * DMODEL + n0 + tx * 8 + 4] = *(float4*)(out + 4);
    }
}

// ---------------------------------------------------------------------------
// Kernel 2: flash attention, fp32, per-CTA: one (b,h) x 64-query tile.
// 64x64 score tiles, online softmax, 4x4 micro-tiles, 256 threads.
// ---------------------------------------------------------------------------
#define SDP 65   // padded shared stride
#define ATTN_SMEM (4 * 64 * SDP * 4)

__global__ __launch_bounds__(256) void attn_kernel()
{
    extern __shared__ float sm[];
    float* Qs = sm;
    float* Ks = sm + 64 * SDP;
    float* Vs = sm + 2 * 64 * SDP;
    float* Ps = sm + 3 * 64 * SDP;

    int tid = threadIdx.x;
    int tx = tid & 15, ty = tid >> 4;
    int bh = blockIdx.y;
    int q0 = blockIdx.x * 64;

    int lrow = tid >> 4;            // 0..15
    int lcol = (tid & 15) * 4;      // 0..60

    // Load Q tile [64 x 64]
    const float* qbase = g_Q + (bh * SEQ + q0) * DH;
#pragma unroll
    for (int r = 0; r < 4; r++) {
        int row = lrow + r * 16;
        float4 v = *(const float4*)(qbase + row * DH + lcol);
        Qs[row * SDP + lcol + 0] = v.x; Qs[row * SDP + lcol + 1] = v.y;
        Qs[row * SDP + lcol + 2] = v.z; Qs[row * SDP + lcol + 3] = v.w;
    }

    float m_i[4], l_i[4], o[4][4];
#pragma unroll
    for (int i = 0; i < 4; i++) {
        m_i[i] = -INFINITY; l_i[i] = 0.f;
#pragma unroll
        for (int j = 0; j < 4; j++) o[i][j] = 0.f;
    }
    const float scale = 0.125f;   // 1/sqrt(64)

    for (int kt = 0; kt < SEQ; kt += 64) {
        const float* kbase = g_K + (bh * SEQ + kt) * DH;
        const float* vbase = g_V + (bh * SEQ + kt) * DH;
        float4 kv[4], vv[4];
#pragma unroll
        for (int r = 0; r < 4; r++) {
            int row = lrow + r * 16;
            kv[r] = *(const float4*)(kbase + row * DH + lcol);
            vv[r] = *(const float4*)(vbase + row * DH + lcol);
        }
        __syncthreads();   // prior PV done (and, first iter, Q stores complete)
#pragma unroll
        for (int r = 0; r < 4; r++) {
            int row = lrow + r * 16;
            Ks[row * SDP + lcol + 0] = kv[r].x; Ks[row * SDP + lcol + 1] = kv[r].y;
            Ks[row * SDP + lcol + 2] = kv[r].z; Ks[row * SDP + lcol + 3] = kv[r].w;
            Vs[row * SDP + lcol + 0] = vv[r].x; Vs[row * SDP + lcol + 1] = vv[r].y;
            Vs[row * SDP + lcol + 2] = vv[r].z; Vs[row * SDP + lcol + 3] = vv[r].w;
        }
        __syncthreads();

        // S = Q * K^T  (64x64x64)
        float s[4][4];
#pragma unroll
        for (int i = 0; i < 4; i++)
#pragma unroll
            for (int j = 0; j < 4; j++) s[i][j] = 0.f;
#pragma unroll 16
        for (int d = 0; d < DH; d++) {
            float a[4], b[4];
#pragma unroll
            for (int i = 0; i < 4; i++) a[i] = Qs[(ty * 4 + i) * SDP + d];
#pragma unroll
            for (int j = 0; j < 4; j++) b[j] = Ks[(tx * 4 + j) * SDP + d];
#pragma unroll
            for (int i = 0; i < 4; i++)
#pragma unroll
                for (int j = 0; j < 4; j++) s[i][j] += a[i] * b[j];
        }

        // Online softmax per query row (row spread across 16 lanes of a half-warp)
#pragma unroll
        for (int i = 0; i < 4; i++) {
#pragma unroll
            for (int j = 0; j < 4; j++) s[i][j] *= scale;
            float tm = fmaxf(fmaxf(s[i][0], s[i][1]), fmaxf(s[i][2], s[i][3]));
            tm = fmaxf(tm, __shfl_xor_sync(0xffffffffu, tm, 1));
            tm = fmaxf(tm, __shfl_xor_sync(0xffffffffu, tm, 2));
            tm = fmaxf(tm, __shfl_xor_sync(0xffffffffu, tm, 4));
            tm = fmaxf(tm, __shfl_xor_sync(0xffffffffu, tm, 8));
            float mnew = fmaxf(m_i[i], tm);
            float alpha = __expf(m_i[i] - mnew);
            float rs = 0.f;
#pragma unroll
            for (int j = 0; j < 4; j++) {
                float p = __expf(s[i][j] - mnew);
                Ps[(ty * 4 + i) * SDP + tx * 4 + j] = p;
                rs += p;
            }
            rs += __shfl_xor_sync(0xffffffffu, rs, 1);
            rs += __shfl_xor_sync(0xffffffffu, rs, 2);
            rs += __shfl_xor_sync(0xffffffffu, rs, 4);
            rs += __shfl_xor_sync(0xffffffffu, rs, 8);
            l_i[i] = l_i[i] * alpha + rs;
            m_i[i] = mnew;
#pragma unroll
            for (int j = 0; j < 4; j++) o[i][j] *= alpha;
        }
        __syncthreads();

        // O += P * V  (64x64x64)
#pragma unroll 16
        for (int n = 0; n < 64; n++) {
            float a[4], b[4];
#pragma unroll
            for (int i = 0; i < 4; i++) a[i] = Ps[(ty * 4 + i) * SDP + n];
#pragma unroll
            for (int j = 0; j < 4; j++) b[j] = Vs[n * SDP + tx * 4 + j];
#pragma unroll
            for (int i = 0; i < 4; i++)
#pragma unroll
                for (int j = 0; j < 4; j++) o[i][j] += a[i] * b[j];
        }
    }

    // Write O, merging heads: [b][s][h*64+d]
    int b = bh >> 4, h = bh & (NH - 1);
#pragma unroll
    for (int i = 0; i < 4; i++) {
        float inv = 1.0f / l_i[i];
        int q = q0 + ty * 4 + i;
        float* dst = g_O + (b * SEQ + q) * DMODEL + h * DH + tx * 4;
#pragma unroll
        for (int j = 0; j < 4; j++) dst[j] = o[i][j] * inv;
    }
}

// ---------------------------------------------------------------------------
extern "C" void kernel_launch(void* const* d_in, const int* in_sizes, int n_in,
                              void* d_out, int out_size) {
    (void)in_sizes; (void)n_in; (void)out_size;
    const float* x     = (const float*)d_in[0];
    const float* w_in  = (const float*)d_in[1];
    const float* b_in  = (const float*)d_in[2];
    const float* w_out = (const float*)d_in[3];
    const float* b_out = (const float*)d_in[4];
    float* out = (float*)d_out;

    cudaFuncSetAttribute(attn_kernel,
                         cudaFuncAttributeMaxDynamicSharedMemorySize, ATTN_SMEM);

    // GEMM1: QKV projection + scatter  (M=8192, N=3072)
    gemm_qkv_kernel<<<dim3(N_QKV / 128, ROWS / 128), 256>>>(x, w_in, b_in);
    // Attention: 64 (b,h) x 32 query tiles
    attn_kernel<<<dim3(SEQ / 64, B_SZ * NH), 256, ATTN_SMEM>>>();
    // GEMM2: output projection  (M=8192, N=1024)
    gemm_out_kernel<<<dim3(DMODEL / 128, ROWS / 128), 256>>>(w_out, b_out, out);
}

// round 3
// speedup vs baseline: 1.3451x; 1.3451x over previous
#include <cuda_runtime.h>
#include <math.h>
#include <cstdint>

#define B_SZ   4
#define SEQ    2048
#define DMODEL 1024
#define NH     16
#define DH     64
#define ROWS   (B_SZ*SEQ)     // 8192
#define N_QKV  (3*DMODEL)     // 3072

// Scratch (allocation-free: device globals)
__device__ float g_K[B_SZ*NH*SEQ*DH];   // [bh][s][d]
__device__ float g_Q[B_SZ*NH*SEQ*DH];
__device__ float g_V[B_SZ*NH*SEQ*DH];
__device__ float g_O[ROWS*DMODEL];      // [b*S + s][h*DH + d]

// ============================================================================
// Helpers: tf32 mma.sync (portable sm_80+ path; tcgen05 is sm_103a-gated and
// this harness compiles plain sm_103), cp.async
// ============================================================================
__device__ __forceinline__ uint32_t f2tf(float f) {
    uint32_t r; asm("cvt.rna.tf32.f32 %0, %1;" : "=r"(r) : "f"(f)); return r;
}
__device__ __forceinline__ void mma_tf32(float c[4],
    uint32_t a0, uint32_t a1, uint32_t a2, uint32_t a3,
    uint32_t b0, uint32_t b1)
{
    asm volatile(
        "mma.sync.aligned.m16n8k8.row.col.f32.tf32.tf32.f32 "
        "{%0,%1,%2,%3}, {%4,%5,%6,%7}, {%8,%9}, {%0,%1,%2,%3};"
        : "+f"(c[0]), "+f"(c[1]), "+f"(c[2]), "+f"(c[3])
        : "r"(a0), "r"(a1), "r"(a2), "r"(a3), "r"(b0), "r"(b1));
}
__device__ __forceinline__ uint32_t smem_u32(const void* p) {
    uint32_t a;
    asm("{ .reg .u64 t; cvta.to.shared.u64 t, %1; cvt.u32.u64 %0, t; }"
        : "=r"(a) : "l"(p));
    return a;
}
#define CP_ASYNC16(dst_u32, src_ptr) \
    asm volatile("cp.async.cg.shared.global [%0], [%1], 16;" \
                 :: "r"(dst_u32), "l"(src_ptr) : "memory")
#define CP_COMMIT  asm volatile("cp.async.commit_group;" ::: "memory")
#define CP_WAIT1   asm volatile("cp.async.wait_group 1;" ::: "memory")

// ============================================================================
// tf32 mma.sync GEMM: C[M,N] = A[M,1024] @ W[1024,N] + bias
// CTA tile 128x128, 8 warps (2x4), warp tile 64x32, K-chunk 32, 2-stage cp.async.
// mode 0: scatter into g_K/g_Q/g_V ([bh][s][d], split order k,q,v)
// mode 1: write Cout row-major [M, DMODEL]
// ============================================================================
#define A_STRIDE 36    // floats; 36%32=4 -> A-fragment lds conflict-free
#define B_STRIDE 136   // floats; 136%32=8 -> B-fragment lds conflict-free
#define A_TILE_F (128 * A_STRIDE)          // 4608 floats
#define B_TILE_F (32 * B_STRIDE)           // 4352 floats
#define STAGE_F  (A_TILE_F + B_TILE_F)     // 8960 floats
#define GSM_BYTES (2 * STAGE_F * 4)        // 71680 B

__global__ __launch_bounds__(256, 2) void gemm_tf32_kernel(
    const float* __restrict__ A,     // [M, 1024]
    const float* __restrict__ W,     // [1024, ldn]
    const float* __restrict__ bias,  // [ldn]
    float* __restrict__ Cout,
    int ldn, int mode)
{
    extern __shared__ float sm[];
    int tid  = threadIdx.x;
    int wid  = tid >> 5, lane = tid & 31;
    int m0 = blockIdx.y * 128, n0 = blockIdx.x * 128;
    int warp_m = (wid & 1) * 64;       // 2 warps along M
    int warp_n = (wid >> 1) * 32;      // 4 warps along N

    // loader mappings
    int a_row = tid >> 1, a_c0 = (tid & 1) * 4;      // + q*8, q=0..3
    int b_row = tid >> 3, b_c0 = (tid & 7) * 16;     // + q*4, q=0..3
    const float* a_src = A + (m0 + a_row) * DMODEL;
    const float* b_src = W + b_row * ldn + n0;

    float acc[4][4][4];
#pragma unroll
    for (int i = 0; i < 4; i++)
#pragma unroll
        for (int j = 0; j < 4; j++)
#pragma unroll
            for (int k = 0; k < 4; k++) acc[i][j][k] = 0.f;

    // ---- stage loader ----
    auto load_stage = [&](int s, int c) {
        float* As = sm + s * STAGE_F;
        float* Bs = As + A_TILE_F;
        uint32_t as_u = smem_u32(As), bs_u = smem_u32(Bs);
        int kc = c * 32;
#pragma unroll
        for (int q = 0; q < 4; q++) {
            int col = a_c0 + q * 8;
            CP_ASYNC16(as_u + (a_row * A_STRIDE + col) * 4, a_src + kc + col);
        }
#pragma unroll
        for (int q = 0; q < 4; q++) {
            int col = b_c0 + q * 4;
            CP_ASYNC16(bs_u + (b_row * B_STRIDE + col) * 4,
                       b_src + (size_t)kc * ldn + col);
        }
    };

    load_stage(0, 0);
    CP_COMMIT;

    for (int c = 0; c < 32; c++) {
        int s = c & 1;
        if (c + 1 < 32) load_stage(s ^ 1, c + 1);
        CP_COMMIT;
        CP_WAIT1;
        __syncthreads();

        const float* As = sm + s * STAGE_F;
        const float* Bs = As + A_TILE_F;
#pragma unroll
        for (int k8 = 0; k8 < 4; k8++) {
            int kb = k8 * 8;
            uint32_t af[4][4], bf[4][2];
#pragma unroll
            for (int mt = 0; mt < 4; mt++) {
                const float* p = As + (warp_m + mt * 16 + (lane >> 2)) * A_STRIDE
                               + kb + (lane & 3);
                af[mt][0] = f2tf(p[0]);
                af[mt][1] = f2tf(p[8 * A_STRIDE]);
                af[mt][2] = f2tf(p[4]);
                af[mt][3] = f2tf(p[8 * A_STRIDE + 4]);
            }
#pragma unroll
            for (int nt = 0; nt < 4; nt++) {
                const float* p = Bs + (kb + (lane & 3)) * B_STRIDE
                               + warp_n + nt * 8 + (lane >> 2);
                bf[nt][0] = f2tf(p[0]);
                bf[nt][1] = f2tf(p[4 * B_STRIDE]);
            }
#pragma unroll
            for (int mt = 0; mt < 4; mt++)
#pragma unroll
                for (int nt = 0; nt < 4; nt++)
                    mma_tf32(acc[mt][nt], af[mt][0], af[mt][1], af[mt][2], af[mt][3],
                             bf[nt][0], bf[nt][1]);
        }
        __syncthreads();
    }

    // ---- epilogue: bias + store ----
    int crow = lane >> 2, ccol2 = (lane & 3) * 2;
#pragma unroll
    for (int mt = 0; mt < 4; mt++) {
#pragma unroll
        for (int nt = 0; nt < 4; nt++) {
            int n = n0 + warp_n + nt * 8 + ccol2;
            float bx = bias[n], by = bias[n + 1];
#pragma unroll
            for (int half = 0; half < 2; half++) {
                int m = m0 + warp_m + mt * 16 + crow + half * 8;
                float2 v;
                v.x = acc[mt][nt][half * 2 + 0] + bx;
                v.y = acc[mt][nt][half * 2 + 1] + by;
                if (mode == 1) {
                    *(float2*)(Cout + (size_t)m * DMODEL + n) = v;
                } else {
                    int b = m >> 11, srow = m & (SEQ - 1);
                    int chunk = n >> 10;
                    int cc = n & (DMODEL - 1);
                    int h = cc >> 6, d0 = cc & (DH - 1);
                    float* base = (chunk == 0) ? g_K : (chunk == 1 ? g_Q : g_V);
                    *(float2*)(base + (((b << 4) + h) * SEQ + srow) * DH + d0) = v;
                }
            }
        }
    }
}

// ---------------------------------------------------------------------------
// Kernel 2: flash attention, fp32, per-CTA: one (b,h) x 64-query tile.
// (unchanged from R1)
// ---------------------------------------------------------------------------
#define SDP 65   // padded shared stride
#define ATTN_SMEM (4 * 64 * SDP * 4)

__global__ __launch_bounds__(256) void attn_kernel()
{
    extern __shared__ float sm[];
    float* Qs = sm;
    float* Ks = sm + 64 * SDP;
    float* Vs = sm + 2 * 64 * SDP;
    float* Ps = sm + 3 * 64 * SDP;

    int tid = threadIdx.x;
    int tx = tid & 15, ty = tid >> 4;
    int bh = blockIdx.y;
    int q0 = blockIdx.x * 64;

    int lrow = tid >> 4;            // 0..15
    int lcol = (tid & 15) * 4;      // 0..60

    const float* qbase = g_Q + (bh * SEQ + q0) * DH;
#pragma unroll
    for (int r = 0; r < 4; r++) {
        int row = lrow + r * 16;
        float4 v = *(const float4*)(qbase + row * DH + lcol);
        Qs[row * SDP + lcol + 0] = v.x; Qs[row * SDP + lcol + 1] = v.y;
        Qs[row * SDP + lcol + 2] = v.z; Qs[row * SDP + lcol + 3] = v.w;
    }

    float m_i[4], l_i[4], o[4][4];
#pragma unroll
    for (int i = 0; i < 4; i++) {
        m_i[i] = -INFINITY; l_i[i] = 0.f;
#pragma unroll
        for (int j = 0; j < 4; j++) o[i][j] = 0.f;
    }
    const float scale = 0.125f;   // 1/sqrt(64)

    for (int kt = 0; kt < SEQ; kt += 64) {
        const float* kbase = g_K + (bh * SEQ + kt) * DH;
        const float* vbase = g_V + (bh * SEQ + kt) * DH;
        float4 kv[4], vv[4];
#pragma unroll
        for (int r = 0; r < 4; r++) {
            int row = lrow + r * 16;
            kv[r] = *(const float4*)(kbase + row * DH + lcol);
            vv[r] = *(const float4*)(vbase + row * DH + lcol);
        }
        __syncthreads();
#pragma unroll
        for (int r = 0; r < 4; r++) {
            int row = lrow + r * 16;
            Ks[row * SDP + lcol + 0] = kv[r].x; Ks[row * SDP + lcol + 1] = kv[r].y;
            Ks[row * SDP + lcol + 2] = kv[r].z; Ks[row * SDP + lcol + 3] = kv[r].w;
            Vs[row * SDP + lcol + 0] = vv[r].x; Vs[row * SDP + lcol + 1] = vv[r].y;
            Vs[row * SDP + lcol + 2] = vv[r].z; Vs[row * SDP + lcol + 3] = vv[r].w;
        }
        __syncthreads();

        float s[4][4];
#pragma unroll
        for (int i = 0; i < 4; i++)
#pragma unroll
            for (int j = 0; j < 4; j++) s[i][j] = 0.f;
#pragma unroll 16
        for (int d = 0; d < DH; d++) {
            float a[4], b[4];
#pragma unroll
            for (int i = 0; i < 4; i++) a[i] = Qs[(ty * 4 + i) * SDP + d];
#pragma unroll
            for (int j = 0; j < 4; j++) b[j] = Ks[(tx * 4 + j) * SDP + d];
#pragma unroll
            for (int i = 0; i < 4; i++)
#pragma unroll
                for (int j = 0; j < 4; j++) s[i][j] += a[i] * b[j];
        }

#pragma unroll
        for (int i = 0; i < 4; i++) {
#pragma unroll
            for (int j = 0; j < 4; j++) s[i][j] *= scale;
            float tm = fmaxf(fmaxf(s[i][0], s[i][1]), fmaxf(s[i][2], s[i][3]));
            tm = fmaxf(tm, __shfl_xor_sync(0xffffffffu, tm, 1));
            tm = fmaxf(tm, __shfl_xor_sync(0xffffffffu, tm, 2));
            tm = fmaxf(tm, __shfl_xor_sync(0xffffffffu, tm, 4));
            tm = fmaxf(tm, __shfl_xor_sync(0xffffffffu, tm, 8));
            float mnew = fmaxf(m_i[i], tm);
            float alpha = __expf(m_i[i] - mnew);
            float rs = 0.f;
#pragma unroll
            for (int j = 0; j < 4; j++) {
                float p = __expf(s[i][j] - mnew);
                Ps[(ty * 4 + i) * SDP + tx * 4 + j] = p;
                rs += p;
            }
            rs += __shfl_xor_sync(0xffffffffu, rs, 1);
            rs += __shfl_xor_sync(0xffffffffu, rs, 2);
            rs += __shfl_xor_sync(0xffffffffu, rs, 4);
            rs += __shfl_xor_sync(0xffffffffu, rs, 8);
            l_i[i] = l_i[i] * alpha + rs;
            m_i[i] = mnew;
#pragma unroll
            for (int j = 0; j < 4; j++) o[i][j] *= alpha;
        }
        __syncthreads();

#pragma unroll 16
        for (int n = 0; n < 64; n++) {
            float a[4], b[4];
#pragma unroll
            for (int i = 0; i < 4; i++) a[i] = Ps[(ty * 4 + i) * SDP + n];
#pragma unroll
            for (int j = 0; j < 4; j++) b[j] = Vs[n * SDP + tx * 4 + j];
#pragma unroll
            for (int i = 0; i < 4; i++)
#pragma unroll
                for (int j = 0; j < 4; j++) o[i][j] += a[i] * b[j];
        }
    }

    int b = bh >> 4, h = bh & (NH - 1);
#pragma unroll
    for (int i = 0; i < 4; i++) {
        float inv = 1.0f / l_i[i];
        int q = q0 + ty * 4 + i;
        float* dst = g_O + (b * SEQ + q) * DMODEL + h * DH + tx * 4;
#pragma unroll
        for (int j = 0; j < 4; j++) dst[j] = o[i][j] * inv;
    }
}

// ---------------------------------------------------------------------------
extern "C" void kernel_launch(void* const* d_in, const int* in_sizes, int n_in,
                              void* d_out, int out_size) {
    (void)in_sizes; (void)n_in; (void)out_size;
    const float* x     = (const float*)d_in[0];
    const float* w_in  = (const float*)d_in[1];
    const float* b_in  = (const float*)d_in[2];
    const float* w_out = (const float*)d_in[3];
    const float* b_out = (const float*)d_in[4];
    float* out = (float*)d_out;

    cudaFuncSetAttribute(gemm_tf32_kernel,
                         cudaFuncAttributeMaxDynamicSharedMemorySize, GSM_BYTES);
    cudaFuncSetAttribute(attn_kernel,
                         cudaFuncAttributeMaxDynamicSharedMemorySize, ATTN_SMEM);

    float* gO_ptr = nullptr;
    cudaGetSymbolAddress((void**)&gO_ptr, g_O);

    // GEMM1: QKV projection + scatter  (M=8192, N=3072)
    gemm_tf32_kernel<<<dim3(N_QKV / 128, ROWS / 128), 256, GSM_BYTES>>>(
        x, w_in, b_in, nullptr, N_QKV, 0);
    // Attention: 64 (b,h) x 32 query tiles
    attn_kernel<<<dim3(SEQ / 64, B_SZ * NH), 256, ATTN_SMEM>>>();
    // GEMM2: output projection  (M=8192, N=1024)
    gemm_tf32_kernel<<<dim3(DMODEL / 128, ROWS / 128), 256, GSM_BYTES>>>(
        gO_ptr, w_out, b_out, out, DMODEL, 1);
}

// round 4
// speedup vs baseline: 1.9993x; 1.4864x over previous
#include <cuda_runtime.h>
#include <math.h>
#include <cstdint>

#define B_SZ   4
#define SEQ    2048
#define DMODEL 1024
#define NH     16
#define DH     64
#define ROWS   (B_SZ*SEQ)     // 8192
#define N_QKV  (3*DMODEL)     // 3072

// Scratch (allocation-free: device globals)
__device__ float g_K[B_SZ*NH*SEQ*DH];   // [bh][s][d]
__device__ float g_Q[B_SZ*NH*SEQ*DH];
__device__ float g_V[B_SZ*NH*SEQ*DH];
__device__ float g_O[ROWS*DMODEL];      // [b*S + s][h*DH + d]

// ============================================================================
// Helpers: tf32 mma.sync (portable sm_80+ path; tcgen05 is sm_103a-gated and
// this harness compiles plain sm_103), cp.async
// ============================================================================
__device__ __forceinline__ uint32_t f2tf(float f) {
    uint32_t r; asm("cvt.rna.tf32.f32 %0, %1;" : "=r"(r) : "f"(f)); return r;
}
__device__ __forceinline__ void mma_tf32(float c[4],
    uint32_t a0, uint32_t a1, uint32_t a2, uint32_t a3,
    uint32_t b0, uint32_t b1)
{
    asm volatile(
        "mma.sync.aligned.m16n8k8.row.col.f32.tf32.tf32.f32 "
        "{%0,%1,%2,%3}, {%4,%5,%6,%7}, {%8,%9}, {%0,%1,%2,%3};"
        : "+f"(c[0]), "+f"(c[1]), "+f"(c[2]), "+f"(c[3])
        : "r"(a0), "r"(a1), "r"(a2), "r"(a3), "r"(b0), "r"(b1));
}
__device__ __forceinline__ uint32_t smem_u32(const void* p) {
    uint32_t a;
    asm("{ .reg .u64 t; cvta.to.shared.u64 t, %1; cvt.u32.u64 %0, t; }"
        : "=r"(a) : "l"(p));
    return a;
}
#define CP_ASYNC16(dst_u32, src_ptr) \
    asm volatile("cp.async.cg.shared.global [%0], [%1], 16;" \
                 :: "r"(dst_u32), "l"(src_ptr) : "memory")
#define CP_COMMIT  asm volatile("cp.async.commit_group;" ::: "memory")
#define CP_WAIT1   asm volatile("cp.async.wait_group 1;" ::: "memory")

// ============================================================================
// tf32 mma.sync GEMM (unchanged from R3): C[M,N] = A[M,1024] @ W[1024,N] + bias
// ============================================================================
#define A_STRIDE 36
#define B_STRIDE 136
#define A_TILE_F (128 * A_STRIDE)
#define B_TILE_F (32 * B_STRIDE)
#define STAGE_F  (A_TILE_F + B_TILE_F)
#define GSM_BYTES (2 * STAGE_F * 4)

__global__ __launch_bounds__(256, 2) void gemm_tf32_kernel(
    const float* __restrict__ A,
    const float* __restrict__ W,
    const float* __restrict__ bias,
    float* __restrict__ Cout,
    int ldn, int mode)
{
    extern __shared__ float sm[];
    int tid  = threadIdx.x;
    int wid  = tid >> 5, lane = tid & 31;
    int m0 = blockIdx.y * 128, n0 = blockIdx.x * 128;
    int warp_m = (wid & 1) * 64;
    int warp_n = (wid >> 1) * 32;

    int a_row = tid >> 1, a_c0 = (tid & 1) * 4;
    int b_row = tid >> 3, b_c0 = (tid & 7) * 16;
    const float* a_src = A + (m0 + a_row) * DMODEL;
    const float* b_src = W + b_row * ldn + n0;

    float acc[4][4][4];
#pragma unroll
    for (int i = 0; i < 4; i++)
#pragma unroll
        for (int j = 0; j < 4; j++)
#pragma unroll
            for (int k = 0; k < 4; k++) acc[i][j][k] = 0.f;

    auto load_stage = [&](int s, int c) {
        float* As = sm + s * STAGE_F;
        float* Bs = As + A_TILE_F;
        uint32_t as_u = smem_u32(As), bs_u = smem_u32(Bs);
        int kc = c * 32;
#pragma unroll
        for (int q = 0; q < 4; q++) {
            int col = a_c0 + q * 8;
            CP_ASYNC16(as_u + (a_row * A_STRIDE + col) * 4, a_src + kc + col);
        }
#pragma unroll
        for (int q = 0; q < 4; q++) {
            int col = b_c0 + q * 4;
            CP_ASYNC16(bs_u + (b_row * B_STRIDE + col) * 4,
                       b_src + (size_t)kc * ldn + col);
        }
    };

    load_stage(0, 0);
    CP_COMMIT;

    for (int c = 0; c < 32; c++) {
        int s = c & 1;
        if (c + 1 < 32) load_stage(s ^ 1, c + 1);
        CP_COMMIT;
        CP_WAIT1;
        __syncthreads();

        const float* As = sm + s * STAGE_F;
        const float* Bs = As + A_TILE_F;
#pragma unroll
        for (int k8 = 0; k8 < 4; k8++) {
            int kb = k8 * 8;
            uint32_t af[4][4], bf[4][2];
#pragma unroll
            for (int mt = 0; mt < 4; mt++) {
                const float* p = As + (warp_m + mt * 16 + (lane >> 2)) * A_STRIDE
                               + kb + (lane & 3);
                af[mt][0] = f2tf(p[0]);
                af[mt][1] = f2tf(p[8 * A_STRIDE]);
                af[mt][2] = f2tf(p[4]);
                af[mt][3] = f2tf(p[8 * A_STRIDE + 4]);
            }
#pragma unroll
            for (int nt = 0; nt < 4; nt++) {
                const float* p = Bs + (kb + (lane & 3)) * B_STRIDE
                               + warp_n + nt * 8 + (lane >> 2);
                bf[nt][0] = f2tf(p[0]);
                bf[nt][1] = f2tf(p[4 * B_STRIDE]);
            }
#pragma unroll
            for (int mt = 0; mt < 4; mt++)
#pragma unroll
                for (int nt = 0; nt < 4; nt++)
                    mma_tf32(acc[mt][nt], af[mt][0], af[mt][1], af[mt][2], af[mt][3],
                             bf[nt][0], bf[nt][1]);
        }
        __syncthreads();
    }

    int crow = lane >> 2, ccol2 = (lane & 3) * 2;
#pragma unroll
    for (int mt = 0; mt < 4; mt++) {
#pragma unroll
        for (int nt = 0; nt < 4; nt++) {
            int n = n0 + warp_n + nt * 8 + ccol2;
            float bx = bias[n], by = bias[n + 1];
#pragma unroll
            for (int half = 0; half < 2; half++) {
                int m = m0 + warp_m + mt * 16 + crow + half * 8;
                float2 v;
                v.x = acc[mt][nt][half * 2 + 0] + bx;
                v.y = acc[mt][nt][half * 2 + 1] + by;
                if (mode == 1) {
                    *(float2*)(Cout + (size_t)m * DMODEL + n) = v;
                } else {
                    int b = m >> 11, srow = m & (SEQ - 1);
                    int chunk = n >> 10;
                    int cc = n & (DMODEL - 1);
                    int h = cc >> 6, d0 = cc & (DH - 1);
                    float* base = (chunk == 0) ? g_K : (chunk == 1 ? g_Q : g_V);
                    *(float2*)(base + (((b << 4) + h) * SEQ + srow) * DH + d0) = v;
                }
            }
        }
    }
}

// ============================================================================
// Flash attention, tf32 mma.sync. Br=128, Bc=64, 8 warps x 16 q-rows.
// QK^T uses 3xTF32 split (hi*hi + hi*lo + lo*hi); PV plain tf32.
// ============================================================================
#define QS 68   // Q/K/P smem stride (words): 4*quad+lane -> conflict-free frags
#define VS 72   // V smem stride: 8*k+quad -> conflict-free frags
// word offsets
#define QH_OFF 0
#define QL_OFF 8704                    // 128*68
#define KH_OFF 17408
#define KL_OFF 21760                   // +64*68
#define V_OFF  26112
#define P_OFF  30720                   // +64*72
#define AT_BYTES ((30720 + 8704) * 4)  // 157696 B

__global__ __launch_bounds__(256, 1) void attn_mma_kernel()
{
    extern __shared__ uint32_t smw[];
    uint32_t* Qh = smw + QH_OFF;
    uint32_t* Ql = smw + QL_OFF;
    uint32_t* Kh = smw + KH_OFF;
    uint32_t* Kl = smw + KL_OFF;
    uint32_t* Vt = smw + V_OFF;
    uint32_t* Pt = smw + P_OFF;

    int tid = threadIdx.x;
    int wid = tid >> 5, lane = tid & 31;
    int bh = blockIdx.y;
    int q0 = blockIdx.x * 128;

    const float* Qg = g_Q + ((size_t)bh * SEQ + q0) * DH;
    const float* Kg = g_K + (size_t)bh * SEQ * DH;
    const float* Vg = g_V + (size_t)bh * SEQ * DH;

    // ---- load Q tile [128x64], split hi/lo into smem (once) ----
    {
        int row = tid >> 1, cb = (tid & 1) * 32;
        const float* src = Qg + row * DH + cb;
#pragma unroll
        for (int q = 0; q < 8; q++) {
            float4 v = *(const float4*)(src + q * 4);
            float xs[4] = {v.x, v.y, v.z, v.w};
#pragma unroll
            for (int j = 0; j < 4; j++) {
                uint32_t h = f2tf(xs[j]);
                Qh[row * QS + cb + q * 4 + j] = h;
                Ql[row * QS + cb + q * 4 + j] = f2tf(xs[j] - __uint_as_float(h));
            }
        }
    }

    // ---- prefetch K/V tile 0 into registers ----
    int krow = tid >> 2, kcb = (tid & 3) * 16;
    float4 kpre[4], vpre[4];
#pragma unroll
    for (int q = 0; q < 4; q++) {
        kpre[q] = *(const float4*)(Kg + krow * DH + kcb + q * 4);
        vpre[q] = *(const float4*)(Vg + krow * DH + kcb + q * 4);
    }

    float m0v = -INFINITY, m1v = -INFINITY, l0v = 0.f, l1v = 0.f;
    float o[8][4];
#pragma unroll
    for (int nt = 0; nt < 8; nt++)
#pragma unroll
        for (int j = 0; j < 4; j++) o[nt][j] = 0.f;

    int r0 = wid * 16 + (lane >> 2);  // query row (first half)
    int kq = lane & 3;                // k-quad index within fragment
    int nq = lane >> 2;               // n index within fragment

    for (int kt = 0; kt < SEQ / 64; kt++) {
        __syncthreads();   // all warps done reading previous K/V smem
        // ---- convert-store K (hi/lo) and V (tf32) ----
#pragma unroll
        for (int q = 0; q < 4; q++) {
            float kx[4] = {kpre[q].x, kpre[q].y, kpre[q].z, kpre[q].w};
            float vx[4] = {vpre[q].x, vpre[q].y, vpre[q].z, vpre[q].w};
#pragma unroll
            for (int j = 0; j < 4; j++) {
                int c = kcb + q * 4 + j;
                uint32_t h = f2tf(kx[j]);
                Kh[krow * QS + c] = h;
                Kl[krow * QS + c] = f2tf(kx[j] - __uint_as_float(h));
                Vt[krow * VS + c] = f2tf(vx[j]);
            }
        }
        // ---- prefetch next tile (overlaps with mma below) ----
        if (kt + 1 < SEQ / 64) {
            const float* kn = Kg + ((kt + 1) * 64 + krow) * DH + kcb;
            const float* vn = Vg + ((kt + 1) * 64 + krow) * DH + kcb;
#pragma unroll
            for (int q = 0; q < 4; q++) {
                kpre[q] = *(const float4*)(kn + q * 4);
                vpre[q] = *(const float4*)(vn + q * 4);
            }
        }
        __syncthreads();

        // ---- S = Q K^T (3xTF32 split) ----
        float s[8][4];
#pragma unroll
        for (int nt = 0; nt < 8; nt++)
#pragma unroll
            for (int j = 0; j < 4; j++) s[nt][j] = 0.f;
#pragma unroll
        for (int k8 = 0; k8 < 8; k8++) {
            int kb = k8 * 8;
            uint32_t ah0 = Qh[r0 * QS + kb + kq];
            uint32_t ah1 = Qh[(r0 + 8) * QS + kb + kq];
            uint32_t ah2 = Qh[r0 * QS + kb + kq + 4];
            uint32_t ah3 = Qh[(r0 + 8) * QS + kb + kq + 4];
            uint32_t al0 = Ql[r0 * QS + kb + kq];
            uint32_t al1 = Ql[(r0 + 8) * QS + kb + kq];
            uint32_t al2 = Ql[r0 * QS + kb + kq + 4];
            uint32_t al3 = Ql[(r0 + 8) * QS + kb + kq + 4];
#pragma unroll
            for (int nt = 0; nt < 8; nt++) {
                int n = nt * 8 + nq;
                uint32_t bh0 = Kh[n * QS + kb + kq];
                uint32_t bh1 = Kh[n * QS + kb + kq + 4];
                uint32_t bl0 = Kl[n * QS + kb + kq];
                uint32_t bl1 = Kl[n * QS + kb + kq + 4];
                mma_tf32(s[nt], ah0, ah1, ah2, ah3, bh0, bh1);
                mma_tf32(s[nt], ah0, ah1, ah2, ah3, bl0, bl1);
                mma_tf32(s[nt], al0, al1, al2, al3, bh0, bh1);
            }
        }

        // ---- online softmax (rows r0 and r0+8; scale 1/8) ----
        float mx0 = s[0][0], mx1 = s[0][2];
#pragma unroll
        for (int nt = 0; nt < 8; nt++) {
            mx0 = fmaxf(mx0, fmaxf(s[nt][0], s[nt][1]));
            mx1 = fmaxf(mx1, fmaxf(s[nt][2], s[nt][3]));
        }
        mx0 = fmaxf(mx0, __shfl_xor_sync(0xffffffffu, mx0, 1));
        mx0 = fmaxf(mx0, __shfl_xor_sync(0xffffffffu, mx0, 2));
        mx1 = fmaxf(mx1, __shfl_xor_sync(0xffffffffu, mx1, 1));
        mx1 = fmaxf(mx1, __shfl_xor_sync(0xffffffffu, mx1, 2));
        float mn0 = fmaxf(m0v, mx0 * 0.125f);
        float mn1 = fmaxf(m1v, mx1 * 0.125f);
        float alf0 = __expf(m0v - mn0), alf1 = __expf(m1v - mn1);
        m0v = mn0; m1v = mn1;
        __syncwarp();   // PV reads of Pt (prev tile) done before overwrite
        float rs0 = 0.f, rs1 = 0.f;
#pragma unroll
        for (int nt = 0; nt < 8; nt++) {
            float p0 = __expf(s[nt][0] * 0.125f - mn0);
            float p1 = __expf(s[nt][1] * 0.125f - mn0);
            float p2 = __expf(s[nt][2] * 0.125f - mn1);
            float p3 = __expf(s[nt][3] * 0.125f - mn1);
            rs0 += p0 + p1; rs1 += p2 + p3;
            int cb = nt * 8 + 2 * kq;
            Pt[r0 * QS + cb]           = f2tf(p0);
            Pt[r0 * QS + cb + 1]       = f2tf(p1);
            Pt[(r0 + 8) * QS + cb]     = f2tf(p2);
            Pt[(r0 + 8) * QS + cb + 1] = f2tf(p3);
            o[nt][0] *= alf0; o[nt][1] *= alf0;
            o[nt][2] *= alf1; o[nt][3] *= alf1;
        }
        rs0 += __shfl_xor_sync(0xffffffffu, rs0, 1);
        rs0 += __shfl_xor_sync(0xffffffffu, rs0, 2);
        rs1 += __shfl_xor_sync(0xffffffffu, rs1, 1);
        rs1 += __shfl_xor_sync(0xffffffffu, rs1, 2);
        l0v = l0v * alf0 + rs0;
        l1v = l1v * alf1 + rs1;
        __syncwarp();   // Pt stores visible to all lanes

        // ---- O += P V (plain tf32) ----
#pragma unroll
        for (int k8 = 0; k8 < 8; k8++) {
            int kb = k8 * 8;
            uint32_t pa0 = Pt[r0 * QS + kb + kq];
            uint32_t pa1 = Pt[(r0 + 8) * QS + kb + kq];
            uint32_t pa2 = Pt[r0 * QS + kb + kq + 4];
            uint32_t pa3 = Pt[(r0 + 8) * QS + kb + kq + 4];
#pragma unroll
            for (int nt = 0; nt < 8; nt++) {
                int n = nt * 8 + nq;
                uint32_t vb0 = Vt[(kb + kq) * VS + n];
                uint32_t vb1 = Vt[(kb + kq + 4) * VS + n];
                mma_tf32(o[nt], pa0, pa1, pa2, pa3, vb0, vb1);
            }
        }
    }

    // ---- epilogue: normalize, merge heads into g_O ----
    float inv0 = 1.f / l0v, inv1 = 1.f / l1v;
    int b = bh >> 4, h = bh & (NH - 1);
    int q = q0 + r0;
    float* dst0 = g_O + ((size_t)(b * SEQ + q)) * DMODEL + h * DH;
    float* dst1 = dst0 + 8 * DMODEL;
#pragma unroll
    for (int nt = 0; nt < 8; nt++) {
        int cb = nt * 8 + 2 * kq;
        float2 v0; v0.x = o[nt][0] * inv0; v0.y = o[nt][1] * inv0;
        float2 v1; v1.x = o[nt][2] * inv1; v1.y = o[nt][3] * inv1;
        *(float2*)(dst0 + cb) = v0;
        *(float2*)(dst1 + cb) = v1;
    }
}

// ---------------------------------------------------------------------------
extern "C" void kernel_launch(void* const* d_in, const int* in_sizes, int n_in,
                              void* d_out, int out_size) {
    (void)in_sizes; (void)n_in; (void)out_size;
    const float* x     = (const float*)d_in[0];
    const float* w_in  = (const float*)d_in[1];
    const float* b_in  = (const float*)d_in[2];
    const float* w_out = (const float*)d_in[3];
    const float* b_out = (const float*)d_in[4];
    float* out = (float*)d_out;

    cudaFuncSetAttribute(gemm_tf32_kernel,
                         cudaFuncAttributeMaxDynamicSharedMemorySize, GSM_BYTES);
    cudaFuncSetAttribute(attn_mma_kernel,
                         cudaFuncAttributeMaxDynamicSharedMemorySize, AT_BYTES);

    float* gO_ptr = nullptr;
    cudaGetSymbolAddress((void**)&gO_ptr, g_O);

    // GEMM1: QKV projection + scatter  (M=8192, N=3072)
    gemm_tf32_kernel<<<dim3(N_QKV / 128, ROWS / 128), 256, GSM_BYTES>>>(
        x, w_in, b_in, nullptr, N_QKV, 0);
    // Attention: 16 q-tiles x 64 (b,h)
    attn_mma_kernel<<<dim3(SEQ / 128, B_SZ * NH), 256, AT_BYTES>>>();
    // GEMM2: output projection  (M=8192, N=1024)
    gemm_tf32_kernel<<<dim3(DMODEL / 128, ROWS / 128), 256, GSM_BYTES>>>(
        gO_ptr, w_out, b_out, out, DMODEL, 1);
}

// round 5
// speedup vs baseline: 2.1938x; 1.0973x over previous
#include <cuda_runtime.h>
#include <math.h>
#include <cstdint>

#define B_SZ   4
#define SEQ    2048
#define DMODEL 1024
#define NH     16
#define DH     64
#define ROWS   (B_SZ*SEQ)     // 8192
#define N_QKV  (3*DMODEL)     // 3072

// Scratch (allocation-free: device globals)
__device__ float g_Qh[B_SZ*NH*SEQ*DH];  // tf32-hi of Q, [bh][s][d]
__device__ float g_Ql[B_SZ*NH*SEQ*DH];  // tf32-lo of Q
__device__ float g_Kh[B_SZ*NH*SEQ*DH];
__device__ float g_Kl[B_SZ*NH*SEQ*DH];
__device__ float g_Vt[B_SZ*NH*SEQ*DH];  // tf32(V)
__device__ float g_O[ROWS*DMODEL];      // attention out (tf32-rounded), [b*S+s][h*DH+d]
__device__ float g_xc[ROWS*DMODEL];     // tf32-rounded x
__device__ float g_w1c[DMODEL*N_QKV];   // tf32-rounded w_in
__device__ float g_w2c[DMODEL*DMODEL];  // tf32-rounded w_out

// ============================================================================
// Helpers
// ============================================================================
__device__ __forceinline__ uint32_t f2tf(float f) {
    uint32_t r; asm("cvt.rna.tf32.f32 %0, %1;" : "=r"(r) : "f"(f)); return r;
}
__device__ __forceinline__ float rndtf(float f) { return __uint_as_float(f2tf(f)); }
__device__ __forceinline__ void mma_tf32(float c[4],
    uint32_t a0, uint32_t a1, uint32_t a2, uint32_t a3,
    uint32_t b0, uint32_t b1)
{
    asm volatile(
        "mma.sync.aligned.m16n8k8.row.col.f32.tf32.tf32.f32 "
        "{%0,%1,%2,%3}, {%4,%5,%6,%7}, {%8,%9}, {%0,%1,%2,%3};"
        : "+f"(c[0]), "+f"(c[1]), "+f"(c[2]), "+f"(c[3])
        : "r"(a0), "r"(a1), "r"(a2), "r"(a3), "r"(b0), "r"(b1));
}
__device__ __forceinline__ uint32_t smem_u32(const void* p) {
    uint32_t a;
    asm("{ .reg .u64 t; cvta.to.shared.u64 t, %1; cvt.u32.u64 %0, t; }"
        : "=r"(a) : "l"(p));
    return a;
}
#define CP_ASYNC16(dst_u32, src_ptr) \
    asm volatile("cp.async.cg.shared.global [%0], [%1], 16;" \
                 :: "r"(dst_u32), "l"(src_ptr) : "memory")
#define CP_COMMIT  asm volatile("cp.async.commit_group;" ::: "memory")
#define CP_WAIT1   asm volatile("cp.async.wait_group 1;" ::: "memory")

// ============================================================================
// Elementwise tf32 rounding: dst = rna_tf32(src)
// ============================================================================
__global__ __launch_bounds__(256) void cvt_tf32_kernel(
    const float4* __restrict__ src, float4* __restrict__ dst, int n4)
{
    int i = blockIdx.x * blockDim.x + threadIdx.x;
    if (i < n4) {
        float4 v = src[i];
        v.x = rndtf(v.x); v.y = rndtf(v.y); v.z = rndtf(v.z); v.w = rndtf(v.w);
        dst[i] = v;
    }
}

// ============================================================================
// tf32 mma.sync GEMM (inputs pre-rounded to tf32 -> no cvt in hot loop)
// CTA 128x128, 8 warps (2x4), warp 64x32, K-chunk 32, 2-stage cp.async.
// mode 0: split-scatter into g_Kh/Kl, g_Qh/Ql, g_Vt   mode 1: Cout row-major
// ============================================================================
#define A_STRIDE 36
#define B_STRIDE 136
#define A_TILE_F (128 * A_STRIDE)
#define B_TILE_F (32 * B_STRIDE)
#define STAGE_F  (A_TILE_F + B_TILE_F)
#define GSM_BYTES (2 * STAGE_F * 4)

__global__ __launch_bounds__(256, 2) void gemm_tf32_kernel(
    const float* __restrict__ A,
    const float* __restrict__ W,
    const float* __restrict__ bias,
    float* __restrict__ Cout,
    int ldn, int mode)
{
    extern __shared__ float sm[];
    int tid  = threadIdx.x;
    int wid  = tid >> 5, lane = tid & 31;
    int m0 = blockIdx.y * 128, n0 = blockIdx.x * 128;
    int warp_m = (wid & 1) * 64;
    int warp_n = (wid >> 1) * 32;

    int a_row = tid >> 1, a_c0 = (tid & 1) * 4;
    int b_row = tid >> 3, b_c0 = (tid & 7) * 16;
    const float* a_src = A + (m0 + a_row) * DMODEL;
    const float* b_src = W + b_row * ldn + n0;

    float acc[4][4][4];
#pragma unroll
    for (int i = 0; i < 4; i++)
#pragma unroll
        for (int j = 0; j < 4; j++)
#pragma unroll
            for (int k = 0; k < 4; k++) acc[i][j][k] = 0.f;

    auto load_stage = [&](int s, int c) {
        float* As = sm + s * STAGE_F;
        float* Bs = As + A_TILE_F;
        uint32_t as_u = smem_u32(As), bs_u = smem_u32(Bs);
        int kc = c * 32;
#pragma unroll
        for (int q = 0; q < 4; q++) {
            int col = a_c0 + q * 8;
            CP_ASYNC16(as_u + (a_row * A_STRIDE + col) * 4, a_src + kc + col);
        }
#pragma unroll
        for (int q = 0; q < 4; q++) {
            int col = b_c0 + q * 4;
            CP_ASYNC16(bs_u + (b_row * B_STRIDE + col) * 4,
                       b_src + (size_t)kc * ldn + col);
        }
    };

    load_stage(0, 0);
    CP_COMMIT;

    for (int c = 0; c < 32; c++) {
        int s = c & 1;
        if (c + 1 < 32) load_stage(s ^ 1, c + 1);
        CP_COMMIT;
        CP_WAIT1;
        __syncthreads();

        const float* As = sm + s * STAGE_F;
        const float* Bs = As + A_TILE_F;
#pragma unroll
        for (int k8 = 0; k8 < 4; k8++) {
            int kb = k8 * 8;
            uint32_t af[4][4], bf[4][2];
#pragma unroll
            for (int mt = 0; mt < 4; mt++) {
                const float* p = As + (warp_m + mt * 16 + (lane >> 2)) * A_STRIDE
                               + kb + (lane & 3);
                af[mt][0] = __float_as_uint(p[0]);
                af[mt][1] = __float_as_uint(p[8 * A_STRIDE]);
                af[mt][2] = __float_as_uint(p[4]);
                af[mt][3] = __float_as_uint(p[8 * A_STRIDE + 4]);
            }
#pragma unroll
            for (int nt = 0; nt < 4; nt++) {
                const float* p = Bs + (kb + (lane & 3)) * B_STRIDE
                               + warp_n + nt * 8 + (lane >> 2);
                bf[nt][0] = __float_as_uint(p[0]);
                bf[nt][1] = __float_as_uint(p[4 * B_STRIDE]);
            }
#pragma unroll
            for (int mt = 0; mt < 4; mt++)
#pragma unroll
                for (int nt = 0; nt < 4; nt++)
                    mma_tf32(acc[mt][nt], af[mt][0], af[mt][1], af[mt][2], af[mt][3],
                             bf[nt][0], bf[nt][1]);
        }
        __syncthreads();
    }

    int crow = lane >> 2, ccol2 = (lane & 3) * 2;
#pragma unroll
    for (int mt = 0; mt < 4; mt++) {
#pragma unroll
        for (int nt = 0; nt < 4; nt++) {
            int n = n0 + warp_n + nt * 8 + ccol2;
            float bx = bias[n], by = bias[n + 1];
#pragma unroll
            for (int half = 0; half < 2; half++) {
                int m = m0 + warp_m + mt * 16 + crow + half * 8;
                float2 v;
                v.x = acc[mt][nt][half * 2 + 0] + bx;
                v.y = acc[mt][nt][half * 2 + 1] + by;
                if (mode == 1) {
                    *(float2*)(Cout + (size_t)m * DMODEL + n) = v;
                } else {
                    int b = m >> 11, srow = m & (SEQ - 1);
                    int chunk = n >> 10;
                    int cc = n & (DMODEL - 1);
                    int h = cc >> 6, d0 = cc & (DH - 1);
                    size_t off = (((size_t)(b << 4) + h) * SEQ + srow) * DH + d0;
                    if (chunk == 2) {        // V -> tf32
                        float2 t; t.x = rndtf(v.x); t.y = rndtf(v.y);
                        *(float2*)(g_Vt + off) = t;
                    } else {                 // K or Q -> hi/lo split
                        float hx = rndtf(v.x), hy = rndtf(v.y);
                        float2 hi; hi.x = hx; hi.y = hy;
                        float2 lo; lo.x = rndtf(v.x - hx); lo.y = rndtf(v.y - hy);
                        if (chunk == 0) {
                            *(float2*)(g_Kh + off) = hi;
                            *(float2*)(g_Kl + off) = lo;
                        } else {
                            *(float2*)(g_Qh + off) = hi;
                            *(float2*)(g_Ql + off) = lo;
                        }
                    }
                }
            }
        }
    }
}

// ============================================================================
// Flash attention, tf32 mma.sync. Br=128, Bc=64, 8 warps x 16 q-rows.
// Pre-split operands; cp.async double-buffered K/V; no cvt in the mainloop.
// ============================================================================
#define QS 68   // Q/K/P smem stride (words)
#define VS 72   // V smem stride
// word offsets in smem
#define QH_OFF 0
#define QL_OFF 8704                    // 128*68
#define P_OFF  17408
#define KH_OFF 26112                   // + s*4352  (64*68)
#define KL_OFF 34816
#define V_OFF  43520                   // + s*4608  (64*72)
#define AT_WORDS (43520 + 2*4608)
#define AT_BYTES (AT_WORDS * 4)        // 210944 B

__global__ __launch_bounds__(256, 1) void attn_mma_kernel()
{
    extern __shared__ uint32_t smw[];
    int tid = threadIdx.x;
    int wid = tid >> 5, lane = tid & 31;
    int bh = blockIdx.y;
    int q0 = blockIdx.x * 128;

    const float* QhG = g_Qh + ((size_t)bh * SEQ + q0) * DH;
    const float* QlG = g_Ql + ((size_t)bh * SEQ + q0) * DH;
    const float* KhG = g_Kh + (size_t)bh * SEQ * DH;
    const float* KlG = g_Kl + (size_t)bh * SEQ * DH;
    const float* VtG = g_Vt + (size_t)bh * SEQ * DH;

    uint32_t smb = smem_u32(smw);

    // ---- Q tile [128x64] hi+lo via cp.async ----
    {
        int row = tid >> 1, cb = (tid & 1) * 32;
#pragma unroll
        for (int q = 0; q < 8; q++) {
            int c = cb + q * 4;
            CP_ASYNC16(smb + (QH_OFF + row * QS + c) * 4, QhG + row * DH + c);
            CP_ASYNC16(smb + (QL_OFF + row * QS + c) * 4, QlG + row * DH + c);
        }
    }
    // ---- K/V tile loader ----
    int krow = tid >> 2, kcb = (tid & 3) * 16;
    auto load_kv = [&](int s, int kt) {
        const float* kh = KhG + ((size_t)kt * 64 + krow) * DH + kcb;
        const float* kl = KlG + ((size_t)kt * 64 + krow) * DH + kcb;
        const float* vt = VtG + ((size_t)kt * 64 + krow) * DH + kcb;
#pragma unroll
        for (int q = 0; q < 4; q++) {
            int c = q * 4;
            CP_ASYNC16(smb + (KH_OFF + s * 4352 + krow * QS + kcb + c) * 4, kh + c);
            CP_ASYNC16(smb + (KL_OFF + s * 4352 + krow * QS + kcb + c) * 4, kl + c);
            CP_ASYNC16(smb + (V_OFF  + s * 4608 + krow * VS + kcb + c) * 4, vt + c);
        }
    };

    load_kv(0, 0);
    CP_COMMIT;           // group: Q + KV0
    load_kv(1, 1);
    CP_COMMIT;           // group: KV1

    float m0v = -INFINITY, m1v = -INFINITY, l0v = 0.f, l1v = 0.f;
    float o[8][4];
#pragma unroll
    for (int nt = 0; nt < 8; nt++)
#pragma unroll
        for (int j = 0; j < 4; j++) o[nt][j] = 0.f;

    int r0 = wid * 16 + (lane >> 2);  // query row (first half)
    int kq = lane & 3;
    int nq = lane >> 2;

    const uint32_t* Qh = smw + QH_OFF;
    const uint32_t* Ql = smw + QL_OFF;
    uint32_t* Pt = smw + P_OFF;

    for (int kt = 0; kt < SEQ / 64; kt++) {
        int s = kt & 1;
        CP_WAIT1;            // tile kt resident (kt+1 may still be in flight)
        __syncthreads();

        const uint32_t* Kh = smw + KH_OFF + s * 4352;
        const uint32_t* Kl = smw + KL_OFF + s * 4352;
        const uint32_t* Vt = smw + V_OFF  + s * 4608;

        // ---- S = Q K^T (3xTF32 split) ----
        float sc[8][4];
#pragma unroll
        for (int nt = 0; nt < 8; nt++)
#pragma unroll
            for (int j = 0; j < 4; j++) sc[nt][j] = 0.f;
#pragma unroll
        for (int k8 = 0; k8 < 8; k8++) {
            int kb = k8 * 8;
            uint32_t ah0 = Qh[r0 * QS + kb + kq];
            uint32_t ah1 = Qh[(r0 + 8) * QS + kb + kq];
            uint32_t ah2 = Qh[r0 * QS + kb + kq + 4];
            uint32_t ah3 = Qh[(r0 + 8) * QS + kb + kq + 4];
            uint32_t al0 = Ql[r0 * QS + kb + kq];
            uint32_t al1 = Ql[(r0 + 8) * QS + kb + kq];
            uint32_t al2 = Ql[r0 * QS + kb + kq + 4];
            uint32_t al3 = Ql[(r0 + 8) * QS + kb + kq + 4];
#pragma unroll
            for (int nt = 0; nt < 8; nt++) {
                int n = nt * 8 + nq;
                uint32_t bh0 = Kh[n * QS + kb + kq];
                uint32_t bh1 = Kh[n * QS + kb + kq + 4];
                uint32_t bl0 = Kl[n * QS + kb + kq];
                uint32_t bl1 = Kl[n * QS + kb + kq + 4];
                mma_tf32(sc[nt], ah0, ah1, ah2, ah3, bh0, bh1);
                mma_tf32(sc[nt], ah0, ah1, ah2, ah3, bl0, bl1);
                mma_tf32(sc[nt], al0, al1, al2, al3, bh0, bh1);
            }
        }

        // ---- online softmax (rows r0, r0+8; scale 1/8) ----
        float mx0 = sc[0][0], mx1 = sc[0][2];
#pragma unroll
        for (int nt = 0; nt < 8; nt++) {
            mx0 = fmaxf(mx0, fmaxf(sc[nt][0], sc[nt][1]));
            mx1 = fmaxf(mx1, fmaxf(sc[nt][2], sc[nt][3]));
        }
        mx0 = fmaxf(mx0, __shfl_xor_sync(0xffffffffu, mx0, 1));
        mx0 = fmaxf(mx0, __shfl_xor_sync(0xffffffffu, mx0, 2));
        mx1 = fmaxf(mx1, __shfl_xor_sync(0xffffffffu, mx1, 1));
        mx1 = fmaxf(mx1, __shfl_xor_sync(0xffffffffu, mx1, 2));
        float mn0 = fmaxf(m0v, mx0 * 0.125f);
        float mn1 = fmaxf(m1v, mx1 * 0.125f);
        float alf0 = __expf(m0v - mn0), alf1 = __expf(m1v - mn1);
        m0v = mn0; m1v = mn1;
        __syncwarp();
        float rs0 = 0.f, rs1 = 0.f;
#pragma unroll
        for (int nt = 0; nt < 8; nt++) {
            float p0 = __expf(sc[nt][0] * 0.125f - mn0);
            float p1 = __expf(sc[nt][1] * 0.125f - mn0);
            float p2 = __expf(sc[nt][2] * 0.125f - mn1);
            float p3 = __expf(sc[nt][3] * 0.125f - mn1);
            rs0 += p0 + p1; rs1 += p2 + p3;
            int cb = nt * 8 + 2 * kq;
            Pt[r0 * QS + cb]           = f2tf(p0);
            Pt[r0 * QS + cb + 1]       = f2tf(p1);
            Pt[(r0 + 8) * QS + cb]     = f2tf(p2);
            Pt[(r0 + 8) * QS + cb + 1] = f2tf(p3);
            o[nt][0] *= alf0; o[nt][1] *= alf0;
            o[nt][2] *= alf1; o[nt][3] *= alf1;
        }
        rs0 += __shfl_xor_sync(0xffffffffu, rs0, 1);
        rs0 += __shfl_xor_sync(0xffffffffu, rs0, 2);
        rs1 += __shfl_xor_sync(0xffffffffu, rs1, 1);
        rs1 += __shfl_xor_sync(0xffffffffu, rs1, 2);
        l0v = l0v * alf0 + rs0;
        l1v = l1v * alf1 + rs1;
        __syncwarp();

        // ---- O += P V ----
#pragma unroll
        for (int k8 = 0; k8 < 8; k8++) {
            int kb = k8 * 8;
            uint32_t pa0 = Pt[r0 * QS + kb + kq];
            uint32_t pa1 = Pt[(r0 + 8) * QS + kb + kq];
            uint32_t pa2 = Pt[r0 * QS + kb + kq + 4];
            uint32_t pa3 = Pt[(r0 + 8) * QS + kb + kq + 4];
#pragma unroll
            for (int nt = 0; nt < 8; nt++) {
                int n = nt * 8 + nq;
                uint32_t vb0 = Vt[(kb + kq) * VS + n];
                uint32_t vb1 = Vt[(kb + kq + 4) * VS + n];
                mma_tf32(o[nt], pa0, pa1, pa2, pa3, vb0, vb1);
            }
        }

        __syncthreads();               // all warps done with buffer s
        if (kt + 2 < SEQ / 64) {
            load_kv(s, kt + 2);        // refill buffer s for tile kt+2
            CP_COMMIT;
        }
    }

    // ---- epilogue: normalize, round to tf32 (GEMM2 input), merge heads ----
    float inv0 = 1.f / l0v, inv1 = 1.f / l1v;
    int b = bh >> 4, h = bh & (NH - 1);
    int q = q0 + r0;
    float* dst0 = g_O + ((size_t)(b * SEQ + q)) * DMODEL + h * DH;
    float* dst1 = dst0 + 8 * DMODEL;
#pragma unroll
    for (int nt = 0; nt < 8; nt++) {
        int cb = nt * 8 + 2 * kq;
        float2 v0; v0.x = rndtf(o[nt][0] * inv0); v0.y = rndtf(o[nt][1] * inv0);
        float2 v1; v1.x = rndtf(o[nt][2] * inv1); v1.y = rndtf(o[nt][3] * inv1);
        *(float2*)(dst0 + cb) = v0;
        *(float2*)(dst1 + cb) = v1;
    }
}

// ---------------------------------------------------------------------------
extern "C" void kernel_launch(void* const* d_in, const int* in_sizes, int n_in,
                              void* d_out, int out_size) {
    (void)in_sizes; (void)n_in; (void)out_size;
    const float* x     = (const float*)d_in[0];
    const float* w_in  = (const float*)d_in[1];
    const float* b_in  = (const float*)d_in[2];
    const float* w_out = (const float*)d_in[3];
    const float* b_out = (const float*)d_in[4];
    float* out = (float*)d_out;

    cudaFuncSetAttribute(gemm_tf32_kernel,
                         cudaFuncAttributeMaxDynamicSharedMemorySize, GSM_BYTES);
    cudaFuncSetAttribute(attn_mma_kernel,
                         cudaFuncAttributeMaxDynamicSharedMemorySize, AT_BYTES);

    float *gO_ptr, *gxc, *gw1c, *gw2c;
    cudaGetSymbolAddress((void**)&gO_ptr, g_O);
    cudaGetSymbolAddress((void**)&gxc,  g_xc);
    cudaGetSymbolAddress((void**)&gw1c, g_w1c);
    cudaGetSymbolAddress((void**)&gw2c, g_w2c);

    // Pre-round GEMM inputs to tf32 (hot loops then use raw bits)
    {
        int n4 = ROWS * DMODEL / 4;
        cvt_tf32_kernel<<<(n4 + 255) / 256, 256>>>((const float4*)x, (float4*)gxc, n4);
        n4 = DMODEL * N_QKV / 4;
        cvt_tf32_kernel<<<(n4 + 255) / 256, 256>>>((const float4*)w_in, (float4*)gw1c, n4);
        n4 = DMODEL * DMODEL / 4;
        cvt_tf32_kernel<<<(n4 + 255) / 256, 256>>>((const float4*)w_out, (float4*)gw2c, n4);
    }

    // GEMM1: QKV projection + split-scatter  (M=8192, N=3072)
    gemm_tf32_kernel<<<dim3(N_QKV / 128, ROWS / 128), 256, GSM_BYTES>>>(
        gxc, gw1c, b_in, nullptr, N_QKV, 0);
    // Attention: 16 q-tiles x 64 (b,h)
    attn_mma_kernel<<<dim3(SEQ / 128, B_SZ * NH), 256, AT_BYTES>>>();
    // GEMM2: output projection  (M=8192, N=1024)
    gemm_tf32_kernel<<<dim3(DMODEL / 128, ROWS / 128), 256, GSM_BYTES>>>(
        gO_ptr, gw2c, b_out, out, DMODEL, 1);
}

// round 6
// speedup vs baseline: 2.6819x; 1.2225x over previous
#include <cuda_runtime.h>
#include <cuda_bf16.h>
#include <math.h>
#include <cstdint>

#define B_SZ   4
#define SEQ    2048
#define DMODEL 1024
#define NH     16
#define DH     64
#define ROWS   (B_SZ*SEQ)     // 8192
#define N_QKV  (3*DMODEL)     // 3072

// Scratch (allocation-free: device globals)
__device__ __nv_bfloat16 g_Qhb[B_SZ*NH*SEQ*DH];  // bf16-hi of Q, [bh][s][d]
__device__ __nv_bfloat16 g_Qlb[B_SZ*NH*SEQ*DH];  // bf16-lo of Q
__device__ __nv_bfloat16 g_Khb[B_SZ*NH*SEQ*DH];
__device__ __nv_bfloat16 g_Klb[B_SZ*NH*SEQ*DH];
__device__ float g_Vt[B_SZ*NH*SEQ*DH];  // tf32(V)
__device__ float g_O[ROWS*DMODEL];      // attention out (tf32-rounded)
__device__ float g_xc[ROWS*DMODEL];     // tf32-rounded x
__device__ float g_w1c[DMODEL*N_QKV];   // tf32-rounded w_in
__device__ float g_w2c[DMODEL*DMODEL];  // tf32-rounded w_out

// ============================================================================
// Helpers
// ============================================================================
__device__ __forceinline__ uint32_t f2tf(float f) {
    uint32_t r; asm("cvt.rna.tf32.f32 %0, %1;" : "=r"(r) : "f"(f)); return r;
}
__device__ __forceinline__ float rndtf(float f) { return __uint_as_float(f2tf(f)); }
__device__ __forceinline__ void mma_tf32(float c[4],
    uint32_t a0, uint32_t a1, uint32_t a2, uint32_t a3,
    uint32_t b0, uint32_t b1)
{
    asm volatile(
        "mma.sync.aligned.m16n8k8.row.col.f32.tf32.tf32.f32 "
        "{%0,%1,%2,%3}, {%4,%5,%6,%7}, {%8,%9}, {%0,%1,%2,%3};"
        : "+f"(c[0]), "+f"(c[1]), "+f"(c[2]), "+f"(c[3])
        : "r"(a0), "r"(a1), "r"(a2), "r"(a3), "r"(b0), "r"(b1));
}
__device__ __forceinline__ void mma_bf16(float c[4],
    uint32_t a0, uint32_t a1, uint32_t a2, uint32_t a3,
    uint32_t b0, uint32_t b1)
{
    asm volatile(
        "mma.sync.aligned.m16n8k16.row.col.f32.bf16.bf16.f32 "
        "{%0,%1,%2,%3}, {%4,%5,%6,%7}, {%8,%9}, {%0,%1,%2,%3};"
        : "+f"(c[0]), "+f"(c[1]), "+f"(c[2]), "+f"(c[3])
        : "r"(a0), "r"(a1), "r"(a2), "r"(a3), "r"(b0), "r"(b1));
}
__device__ __forceinline__ uint32_t smem_u32(const void* p) {
    uint32_t a;
    asm("{ .reg .u64 t; cvta.to.shared.u64 t, %1; cvt.u32.u64 %0, t; }"
        : "=r"(a) : "l"(p));
    return a;
}
#define CP_ASYNC16(dst_u32, src_ptr) \
    asm volatile("cp.async.cg.shared.global [%0], [%1], 16;" \
                 :: "r"(dst_u32), "l"(src_ptr) : "memory")
#define CP_COMMIT  asm volatile("cp.async.commit_group;" ::: "memory")
#define CP_WAIT1   asm volatile("cp.async.wait_group 1;" ::: "memory")
#define CP_WAIT2   asm volatile("cp.async.wait_group 2;" ::: "memory")

// ============================================================================
// Elementwise tf32 rounding
// ============================================================================
__global__ __launch_bounds__(256) void cvt_tf32_kernel(
    const float4* __restrict__ src, float4* __restrict__ dst, int n4)
{
    int i = blockIdx.x * blockDim.x + threadIdx.x;
    if (i < n4) {
        float4 v = src[i];
        v.x = rndtf(v.x); v.y = rndtf(v.y); v.z = rndtf(v.z); v.w = rndtf(v.w);
        dst[i] = v;
    }
}

// ============================================================================
// tf32 mma.sync GEMM, 3-stage cp.async pipeline.
// mode 0: split-scatter (Q/K -> bf16 hi/lo, V -> tf32)   mode 1: Cout fp32
// ============================================================================
#define A_STRIDE 36
#define B_STRIDE 136
#define A_TILE_F (128 * A_STRIDE)
#define B_TILE_F (32 * B_STRIDE)
#define STAGE_F  (A_TILE_F + B_TILE_F)
#define GSM_BYTES (3 * STAGE_F * 4)

__global__ __launch_bounds__(256, 2) void gemm_tf32_kernel(
    const float* __restrict__ A,
    const float* __restrict__ W,
    const float* __restrict__ bias,
    float* __restrict__ Cout,
    int ldn, int mode)
{
    extern __shared__ float sm[];
    int tid  = threadIdx.x;
    int wid  = tid >> 5, lane = tid & 31;
    int m0 = blockIdx.y * 128, n0 = blockIdx.x * 128;
    int warp_m = (wid & 1) * 64;
    int warp_n = (wid >> 1) * 32;

    int a_row = tid >> 1, a_c0 = (tid & 1) * 4;
    int b_row = tid >> 3, b_c0 = (tid & 7) * 16;
    const float* a_src = A + (m0 + a_row) * DMODEL;
    const float* b_src = W + b_row * ldn + n0;

    float acc[4][4][4];
#pragma unroll
    for (int i = 0; i < 4; i++)
#pragma unroll
        for (int j = 0; j < 4; j++)
#pragma unroll
            for (int k = 0; k < 4; k++) acc[i][j][k] = 0.f;

    auto load_stage = [&](int s, int c) {
        float* As = sm + s * STAGE_F;
        float* Bs = As + A_TILE_F;
        uint32_t as_u = smem_u32(As), bs_u = smem_u32(Bs);
        int kc = c * 32;
#pragma unroll
        for (int q = 0; q < 4; q++) {
            int col = a_c0 + q * 8;
            CP_ASYNC16(as_u + (a_row * A_STRIDE + col) * 4, a_src + kc + col);
        }
#pragma unroll
        for (int q = 0; q < 4; q++) {
            int col = b_c0 + q * 4;
            CP_ASYNC16(bs_u + (b_row * B_STRIDE + col) * 4,
                       b_src + (size_t)kc * ldn + col);
        }
    };

    load_stage(0, 0); CP_COMMIT;
    load_stage(1, 1); CP_COMMIT;
    load_stage(2, 2); CP_COMMIT;

    for (int c = 0; c < 32; c++) {
        int s = c % 3;
        CP_WAIT2;
        __syncthreads();

        const float* As = sm + s * STAGE_F;
        const float* Bs = As + A_TILE_F;
#pragma unroll
        for (int k8 = 0; k8 < 4; k8++) {
            int kb = k8 * 8;
            uint32_t af[4][4], bf[4][2];
#pragma unroll
            for (int mt = 0; mt < 4; mt++) {
                const float* p = As + (warp_m + mt * 16 + (lane >> 2)) * A_STRIDE
                               + kb + (lane & 3);
                af[mt][0] = __float_as_uint(p[0]);
                af[mt][1] = __float_as_uint(p[8 * A_STRIDE]);
                af[mt][2] = __float_as_uint(p[4]);
                af[mt][3] = __float_as_uint(p[8 * A_STRIDE + 4]);
            }
#pragma unroll
            for (int nt = 0; nt < 4; nt++) {
                const float* p = Bs + (kb + (lane & 3)) * B_STRIDE
                               + warp_n + nt * 8 + (lane >> 2);
                bf[nt][0] = __float_as_uint(p[0]);
                bf[nt][1] = __float_as_uint(p[4 * B_STRIDE]);
            }
#pragma unroll
            for (int mt = 0; mt < 4; mt++)
#pragma unroll
                for (int nt = 0; nt < 4; nt++)
                    mma_tf32(acc[mt][nt], af[mt][0], af[mt][1], af[mt][2], af[mt][3],
                             bf[nt][0], bf[nt][1]);
        }
        __syncthreads();
        if (c + 3 < 32) load_stage(s, c + 3);
        CP_COMMIT;
    }

    int crow = lane >> 2, ccol2 = (lane & 3) * 2;
#pragma unroll
    for (int mt = 0; mt < 4; mt++) {
#pragma unroll
        for (int nt = 0; nt < 4; nt++) {
            int n = n0 + warp_n + nt * 8 + ccol2;
            float bx = bias[n], by = bias[n + 1];
#pragma unroll
            for (int half = 0; half < 2; half++) {
                int m = m0 + warp_m + mt * 16 + crow + half * 8;
                float2 v;
                v.x = acc[mt][nt][half * 2 + 0] + bx;
                v.y = acc[mt][nt][half * 2 + 1] + by;
                if (mode == 1) {
                    *(float2*)(Cout + (size_t)m * DMODEL + n) = v;
                } else {
                    int b = m >> 11, srow = m & (SEQ - 1);
                    int chunk = n >> 10;
                    int cc = n & (DMODEL - 1);
                    int h = cc >> 6, d0 = cc & (DH - 1);
                    size_t off = (((size_t)(b << 4) + h) * SEQ + srow) * DH + d0;
                    if (chunk == 2) {        // V -> tf32
                        float2 t; t.x = rndtf(v.x); t.y = rndtf(v.y);
                        *(float2*)(g_Vt + off) = t;
                    } else {                 // K or Q -> bf16 hi/lo split
                        __nv_bfloat16 hx = __float2bfloat16_rn(v.x);
                        __nv_bfloat16 hy = __float2bfloat16_rn(v.y);
                        __nv_bfloat16 lx = __float2bfloat16_rn(v.x - __bfloat162float(hx));
                        __nv_bfloat16 ly = __float2bfloat16_rn(v.y - __bfloat162float(hy));
                        __nv_bfloat162 hi; hi.x = hx; hi.y = hy;
                        __nv_bfloat162 lo; lo.x = lx; lo.y = ly;
                        if (chunk == 0) {
                            *(__nv_bfloat162*)(g_Khb + off) = hi;
                            *(__nv_bfloat162*)(g_Klb + off) = lo;
                        } else {
                            *(__nv_bfloat162*)(g_Qhb + off) = hi;
                            *(__nv_bfloat162*)(g_Qlb + off) = lo;
                        }
                    }
                }
            }
        }
    }
}

// ============================================================================
// Flash attention. Br=128, Bc=64, 8 warps x 16 q-rows.
// QK^T: 3-term bf16 split via m16n8k16. PV: tf32 m16n8k8.
// ============================================================================
// 32-bit-word smem offsets
#define QSW 36   // Q/K row stride in words (72 bf16)
#define PS  68   // P stride (words)
#define VS  72   // V stride (words)
#define QH_OFF 0
#define QL_OFF 4608                    // 128*36
#define P_OFF  9216
#define KH_OFF 17920                   // + s*2304  (64*36)
#define KL_OFF 22528
#define V_OFF  27136                   // + s*4608  (64*72)
#define AT_WORDS (27136 + 2*4608)
#define AT_BYTES (AT_WORDS * 4)        // 145408 B

__global__ __launch_bounds__(256, 1) void attn_mma_kernel()
{
    extern __shared__ uint32_t smw[];
    int tid = threadIdx.x;
    int wid = tid >> 5, lane = tid & 31;
    int bh = blockIdx.y;
    int q0 = blockIdx.x * 128;

    const __nv_bfloat16* QhG = g_Qhb + ((size_t)bh * SEQ + q0) * DH;
    const __nv_bfloat16* QlG = g_Qlb + ((size_t)bh * SEQ + q0) * DH;
    const __nv_bfloat16* KhG = g_Khb + (size_t)bh * SEQ * DH;
    const __nv_bfloat16* KlG = g_Klb + (size_t)bh * SEQ * DH;
    const float* VtG = g_Vt + (size_t)bh * SEQ * DH;

    uint32_t smb = smem_u32(smw);

    // ---- Q tile [128x64] bf16 hi+lo via cp.async ----
    {
        int row = tid >> 1, half = (tid & 1);
#pragma unroll
        for (int q = 0; q < 4; q++) {
            int eo = half * 32 + q * 8;           // bf16 element offset in row
            CP_ASYNC16(smb + QH_OFF * 4 + row * 144 + half * 64 + q * 16,
                       QhG + row * DH + eo);
            CP_ASYNC16(smb + QL_OFF * 4 + row * 144 + half * 64 + q * 16,
                       QlG + row * DH + eo);
        }
    }
    // ---- K (bf16 hi/lo) + V (tf32) tile loader ----
    int krow = tid >> 2, kc4 = (tid & 3);
    auto load_kv = [&](int s, int kt) {
        const __nv_bfloat16* kh = KhG + ((size_t)kt * 64 + krow) * DH;
        const __nv_bfloat16* kl = KlG + ((size_t)kt * 64 + krow) * DH;
        const float* vt = VtG + ((size_t)kt * 64 + krow) * DH;
#pragma unroll
        for (int q = 0; q < 2; q++) {
            int eo = kc4 * 16 + q * 8;
            CP_ASYNC16(smb + (KH_OFF + s * 2304) * 4 + krow * 144 + kc4 * 32 + q * 16,
                       kh + eo);
            CP_ASYNC16(smb + (KL_OFF + s * 2304) * 4 + krow * 144 + kc4 * 32 + q * 16,
                       kl + eo);
        }
#pragma unroll
        for (int q = 0; q < 4; q++) {
            int fo = kc4 * 16 + q * 4;
            CP_ASYNC16(smb + (V_OFF + s * 4608) * 4 + krow * 288 + kc4 * 64 + q * 16,
                       vt + fo);
        }
    };

    load_kv(0, 0);
    CP_COMMIT;           // group: Q + KV0
    load_kv(1, 1);
    CP_COMMIT;           // group: KV1

    float m0v = -INFINITY, m1v = -INFINITY, l0v = 0.f, l1v = 0.f;
    float o[8][4];
#pragma unroll
    for (int nt = 0; nt < 8; nt++)
#pragma unroll
        for (int j = 0; j < 4; j++) o[nt][j] = 0.f;

    int r0 = wid * 16 + (lane >> 2);  // query row (first half)
    int kq = lane & 3;
    int nq = lane >> 2;

    const uint32_t* Qh = smw + QH_OFF;
    const uint32_t* Ql = smw + QL_OFF;
    uint32_t* Pt = smw + P_OFF;

    for (int kt = 0; kt < SEQ / 64; kt++) {
        int s = kt & 1;
        CP_WAIT1;
        __syncthreads();

        const uint32_t* Kh = smw + KH_OFF + s * 2304;
        const uint32_t* Kl = smw + KL_OFF + s * 2304;
        const uint32_t* Vt = smw + V_OFF  + s * 4608;

        // ---- S = Q K^T, bf16 3-term split, m16n8k16 ----
        float sc[8][4];
#pragma unroll
        for (int nt = 0; nt < 8; nt++)
#pragma unroll
            for (int j = 0; j < 4; j++) sc[nt][j] = 0.f;
#pragma unroll
        for (int ks = 0; ks < 4; ks++) {
            int kb = ks * 8;   // word offset of this k16 block
            uint32_t ah0 = Qh[r0 * QSW + kb + kq];
            uint32_t ah1 = Qh[(r0 + 8) * QSW + kb + kq];
            uint32_t ah2 = Qh[r0 * QSW + kb + kq + 4];
            uint32_t ah3 = Qh[(r0 + 8) * QSW + kb + kq + 4];
            uint32_t al0 = Ql[r0 * QSW + kb + kq];
            uint32_t al1 = Ql[(r0 + 8) * QSW + kb + kq];
            uint32_t al2 = Ql[r0 * QSW + kb + kq + 4];
            uint32_t al3 = Ql[(r0 + 8) * QSW + kb + kq + 4];
#pragma unroll
            for (int nt = 0; nt < 8; nt++) {
                int n = nt * 8 + nq;
                uint32_t bh0 = Kh[n * QSW + kb + kq];
                uint32_t bh1 = Kh[n * QSW + kb + kq + 4];
                uint32_t bl0 = Kl[n * QSW + kb + kq];
                uint32_t bl1 = Kl[n * QSW + kb + kq + 4];
                mma_bf16(sc[nt], ah0, ah1, ah2, ah3, bh0, bh1);
                mma_bf16(sc[nt], ah0, ah1, ah2, ah3, bl0, bl1);
                mma_bf16(sc[nt], al0, al1, al2, al3, bh0, bh1);
            }
        }

        // ---- online softmax (rows r0, r0+8; scale 1/8) ----
        float mx0 = sc[0][0], mx1 = sc[0][2];
#pragma unroll
        for (int nt = 0; nt < 8; nt++) {
            mx0 = fmaxf(mx0, fmaxf(sc[nt][0], sc[nt][1]));
            mx1 = fmaxf(mx1, fmaxf(sc[nt][2], sc[nt][3]));
        }
        mx0 = fmaxf(mx0, __shfl_xor_sync(0xffffffffu, mx0, 1));
        mx0 = fmaxf(mx0, __shfl_xor_sync(0xffffffffu, mx0, 2));
        mx1 = fmaxf(mx1, __shfl_xor_sync(0xffffffffu, mx1, 1));
        mx1 = fmaxf(mx1, __shfl_xor_sync(0xffffffffu, mx1, 2));
        float mn0 = fmaxf(m0v, mx0 * 0.125f);
        float mn1 = fmaxf(m1v, mx1 * 0.125f);
        float alf0 = __expf(m0v - mn0), alf1 = __expf(m1v - mn1);
        m0v = mn0; m1v = mn1;
        __syncwarp();
        float rs0 = 0.f, rs1 = 0.f;
#pragma unroll
        for (int nt = 0; nt < 8; nt++) {
            float p0 = __expf(sc[nt][0] * 0.125f - mn0);
            float p1 = __expf(sc[nt][1] * 0.125f - mn0);
            float p2 = __expf(sc[nt][2] * 0.125f - mn1);
            float p3 = __expf(sc[nt][3] * 0.125f - mn1);
            rs0 += p0 + p1; rs1 += p2 + p3;
            int cb = nt * 8 + 2 * kq;
            Pt[r0 * PS + cb]           = f2tf(p0);
            Pt[r0 * PS + cb + 1]       = f2tf(p1);
            Pt[(r0 + 8) * PS + cb]     = f2tf(p2);
            Pt[(r0 + 8) * PS + cb + 1] = f2tf(p3);
            o[nt][0] *= alf0; o[nt][1] *= alf0;
            o[nt][2] *= alf1; o[nt][3] *= alf1;
        }
        rs0 += __shfl_xor_sync(0xffffffffu, rs0, 1);
        rs0 += __shfl_xor_sync(0xffffffffu, rs0, 2);
        rs1 += __shfl_xor_sync(0xffffffffu, rs1, 1);
        rs1 += __shfl_xor_sync(0xffffffffu, rs1, 2);
        l0v = l0v * alf0 + rs0;
        l1v = l1v * alf1 + rs1;
        __syncwarp();

        // ---- O += P V (tf32 m16n8k8) ----
#pragma unroll
        for (int k8 = 0; k8 < 8; k8++) {
            int kb = k8 * 8;
            uint32_t pa0 = Pt[r0 * PS + kb + kq];
            uint32_t pa1 = Pt[(r0 + 8) * PS + kb + kq];
            uint32_t pa2 = Pt[r0 * PS + kb + kq + 4];
            uint32_t pa3 = Pt[(r0 + 8) * PS + kb + kq + 4];
#pragma unroll
            for (int nt = 0; nt < 8; nt++) {
                int n = nt * 8 + nq;
                uint32_t vb0 = Vt[(kb + kq) * VS + n];
                uint32_t vb1 = Vt[(kb + kq + 4) * VS + n];
                mma_tf32(o[nt], pa0, pa1, pa2, pa3, vb0, vb1);
            }
        }

        __syncthreads();
        if (kt + 2 < SEQ / 64) {
            load_kv(s, kt + 2);
            CP_COMMIT;
        }
    }

    // ---- epilogue: normalize, round to tf32, merge heads ----
    float inv0 = 1.f / l0v, inv1 = 1.f / l1v;
    int b = bh >> 4, h = bh & (NH - 1);
    int q = q0 + r0;
    float* dst0 = g_O + ((size_t)(b * SEQ + q)) * DMODEL + h * DH;
    float* dst1 = dst0 + 8 * DMODEL;
#pragma unroll
    for (int nt = 0; nt < 8; nt++) {
        int cb = nt * 8 + 2 * kq;
        float2 v0; v0.x = rndtf(o[nt][0] * inv0); v0.y = rndtf(o[nt][1] * inv0);
        float2 v1; v1.x = rndtf(o[nt][2] * inv1); v1.y = rndtf(o[nt][3] * inv1);
        *(float2*)(dst0 + cb) = v0;
        *(float2*)(dst1 + cb) = v1;
    }
}

// ---------------------------------------------------------------------------
extern "C" void kernel_launch(void* const* d_in, const int* in_sizes, int n_in,
                              void* d_out, int out_size) {
    (void)in_sizes; (void)n_in; (void)out_size;
    const float* x     = (const float*)d_in[0];
    const float* w_in  = (const float*)d_in[1];
    const float* b_in  = (const float*)d_in[2];
    const float* w_out = (const float*)d_in[3];
    const float* b_out = (const float*)d_in[4];
    float* out = (float*)d_out;

    cudaFuncSetAttribute(gemm_tf32_kernel,
                         cudaFuncAttributeMaxDynamicSharedMemorySize, GSM_BYTES);
    cudaFuncSetAttribute(attn_mma_kernel,
                         cudaFuncAttributeMaxDynamicSharedMemorySize, AT_BYTES);

    float *gO_ptr, *gxc, *gw1c, *gw2c;
    cudaGetSymbolAddress((void**)&gO_ptr, g_O);
    cudaGetSymbolAddress((void**)&gxc,  g_xc);
    cudaGetSymbolAddress((void**)&gw1c, g_w1c);
    cudaGetSymbolAddress((void**)&gw2c, g_w2c);

    // Pre-round GEMM inputs to tf32
    {
        int n4 = ROWS * DMODEL / 4;
        cvt_tf32_kernel<<<(n4 + 255) / 256, 256>>>((const float4*)x, (float4*)gxc, n4);
        n4 = DMODEL * N_QKV / 4;
        cvt_tf32_kernel<<<(n4 + 255) / 256, 256>>>((const float4*)w_in, (float4*)gw1c, n4);
        n4 = DMODEL * DMODEL / 4;
        cvt_tf32_kernel<<<(n4 + 255) / 256, 256>>>((const float4*)w_out, (float4*)gw2c, n4);
    }

    // GEMM1: QKV projection + split-scatter  (M=8192, N=3072)
    gemm_tf32_kernel<<<dim3(N_QKV / 128, ROWS / 128), 256, GSM_BYTES>>>(
        gxc, gw1c, b_in, nullptr, N_QKV, 0);
    // Attention: 16 q-tiles x 64 (b,h)
    attn_mma_kernel<<<dim3(SEQ / 128, B_SZ * NH), 256, AT_BYTES>>>();
    // GEMM2: output projection  (M=8192, N=1024)
    gemm_tf32_kernel<<<dim3(DMODEL / 128, ROWS / 128), 256, GSM_BYTES>>>(
        gO_ptr, gw2c, b_out, out, DMODEL, 1);
}

// round 8
// speedup vs baseline: 3.0417x; 1.1341x over previous
#include <cuda_runtime.h>
#include <cuda_bf16.h>
#include <cuda_fp16.h>
#include <math.h>
#include <cstdint>

#define B_SZ   4
#define SEQ    2048
#define DMODEL 1024
#define NH     16
#define DH     64
#define ROWS   (B_SZ*SEQ)     // 8192
#define N_QKV  (3*DMODEL)     // 3072

// Scratch (allocation-free: device globals)
__device__ __nv_bfloat16 g_Qhb[B_SZ*NH*SEQ*DH];  // bf16-hi of Q, [bh][s][d]
__device__ __nv_bfloat16 g_Qlb[B_SZ*NH*SEQ*DH];  // bf16-lo of Q
__device__ __nv_bfloat16 g_Khb[B_SZ*NH*SEQ*DH];
__device__ __nv_bfloat16 g_Klb[B_SZ*NH*SEQ*DH];
__device__ __half g_Vh[B_SZ*NH*SEQ*DH];          // fp16(V), TRANSPOSED [bh][d][s]
__device__ float g_O[ROWS*DMODEL];      // attention out (tf32-rounded)
__device__ float g_xc[ROWS*DMODEL];     // tf32-rounded x
__device__ float g_w1c[DMODEL*N_QKV];   // tf32-rounded w_in
__device__ float g_w2c[DMODEL*DMODEL];  // tf32-rounded w_out

// ============================================================================
// Helpers
// ============================================================================
__device__ __forceinline__ uint32_t f2tf(float f) {
    uint32_t r; asm("cvt.rna.tf32.f32 %0, %1;" : "=r"(r) : "f"(f)); return r;
}
__device__ __forceinline__ float rndtf(float f) { return __uint_as_float(f2tf(f)); }
__device__ __forceinline__ uint32_t pack_h2(float x, float y) {
    __half2 h = __floats2half2_rn(x, y);
    return *reinterpret_cast<uint32_t*>(&h);
}
__device__ __forceinline__ void mma_tf32(float c[4],
    uint32_t a0, uint32_t a1, uint32_t a2, uint32_t a3,
    uint32_t b0, uint32_t b1)
{
    asm volatile(
        "mma.sync.aligned.m16n8k8.row.col.f32.tf32.tf32.f32 "
        "{%0,%1,%2,%3}, {%4,%5,%6,%7}, {%8,%9}, {%0,%1,%2,%3};"
        : "+f"(c[0]), "+f"(c[1]), "+f"(c[2]), "+f"(c[3])
        : "r"(a0), "r"(a1), "r"(a2), "r"(a3), "r"(b0), "r"(b1));
}
__device__ __forceinline__ void mma_bf16(float c[4],
    uint32_t a0, uint32_t a1, uint32_t a2, uint32_t a3,
    uint32_t b0, uint32_t b1)
{
    asm volatile(
        "mma.sync.aligned.m16n8k16.row.col.f32.bf16.bf16.f32 "
        "{%0,%1,%2,%3}, {%4,%5,%6,%7}, {%8,%9}, {%0,%1,%2,%3};"
        : "+f"(c[0]), "+f"(c[1]), "+f"(c[2]), "+f"(c[3])
        : "r"(a0), "r"(a1), "r"(a2), "r"(a3), "r"(b0), "r"(b1));
}
__device__ __forceinline__ void mma_f16(float c[4],
    uint32_t a0, uint32_t a1, uint32_t a2, uint32_t a3,
    uint32_t b0, uint32_t b1)
{
    asm volatile(
        "mma.sync.aligned.m16n8k16.row.col.f32.f16.f16.f32 "
        "{%0,%1,%2,%3}, {%4,%5,%6,%7}, {%8,%9}, {%0,%1,%2,%3};"
        : "+f"(c[0]), "+f"(c[1]), "+f"(c[2]), "+f"(c[3])
        : "r"(a0), "r"(a1), "r"(a2), "r"(a3), "r"(b0), "r"(b1));
}
__device__ __forceinline__ uint32_t smem_u32(const void* p) {
    uint32_t a;
    asm("{ .reg .u64 t; cvta.to.shared.u64 t, %1; cvt.u32.u64 %0, t; }"
        : "=r"(a) : "l"(p));
    return a;
}
#define CP_ASYNC16(dst_u32, src_ptr) \
    asm volatile("cp.async.cg.shared.global [%0], [%1], 16;" \
                 :: "r"(dst_u32), "l"(src_ptr) : "memory")
#define CP_COMMIT  asm volatile("cp.async.commit_group;" ::: "memory")
#define CP_WAIT1   asm volatile("cp.async.wait_group 1;" ::: "memory")
#define CP_WAIT2   asm volatile("cp.async.wait_group 2;" ::: "memory")

// ============================================================================
// Elementwise tf32 rounding
// ============================================================================
__global__ __launch_bounds__(256) void cvt_tf32_kernel(
    const float4* __restrict__ src, float4* __restrict__ dst, int n4)
{
    int i = blockIdx.x * blockDim.x + threadIdx.x;
    if (i < n4) {
        float4 v = src[i];
        v.x = rndtf(v.x); v.y = rndtf(v.y); v.z = rndtf(v.z); v.w = rndtf(v.w);
        dst[i] = v;
    }
}

// ============================================================================
// tf32 mma.sync GEMM: CTA 128x128, 128 threads (4 warps of 64x64), 3-stage.
// mode 0: split-scatter (Q/K -> bf16 hi/lo, V -> fp16 transposed)
// mode 1: Cout fp32 row-major
// ============================================================================
#define A_STRIDE 36
#define B_STRIDE 136
#define A_TILE_F (128 * A_STRIDE)
#define B_TILE_F (32 * B_STRIDE)
#define STAGE_F  (A_TILE_F + B_TILE_F)
#define GSM_BYTES (3 * STAGE_F * 4)     // 107520

__global__ __launch_bounds__(128, 2) void gemm_tf32_kernel(
    const float* __restrict__ A,
    const float* __restrict__ W,
    const float* __restrict__ bias,
    float* __restrict__ Cout,
    int ldn, int mode)
{
    extern __shared__ float sm[];
    int tid  = threadIdx.x;
    int wid  = tid >> 5, lane = tid & 31;
    int m0 = blockIdx.y * 128, n0 = blockIdx.x * 128;
    int warp_m = (wid & 1) * 64;
    int warp_n = (wid >> 1) * 64;

    const float* a_src = A + (m0 + tid) * DMODEL;
    const float* b_src = W + (tid >> 2) * ldn + n0 + (tid & 3) * 32;

    float acc[4][8][4];
#pragma unroll
    for (int i = 0; i < 4; i++)
#pragma unroll
        for (int j = 0; j < 8; j++)
#pragma unroll
            for (int k = 0; k < 4; k++) acc[i][j][k] = 0.f;

    auto load_stage = [&](int s, int c) {
        float* As = sm + s * STAGE_F;
        float* Bs = As + A_TILE_F;
        uint32_t as_u = smem_u32(As), bs_u = smem_u32(Bs);
        int kc = c * 32;
#pragma unroll
        for (int q = 0; q < 8; q++)
            CP_ASYNC16(as_u + (tid * A_STRIDE + q * 4) * 4, a_src + kc + q * 4);
#pragma unroll
        for (int q = 0; q < 8; q++)
            CP_ASYNC16(bs_u + ((tid >> 2) * B_STRIDE + (tid & 3) * 32 + q * 4) * 4,
                       b_src + (size_t)kc * ldn + q * 4);
    };

    load_stage(0, 0); CP_COMMIT;
    load_stage(1, 1); CP_COMMIT;
    load_stage(2, 2); CP_COMMIT;

    for (int c = 0; c < 32; c++) {
        int s = c % 3;
        CP_WAIT2;
        __syncthreads();

        const float* As = sm + s * STAGE_F;
        const float* Bs = As + A_TILE_F;
#pragma unroll
        for (int k8 = 0; k8 < 4; k8++) {
            int kb = k8 * 8;
            uint32_t af[4][4], bf[8][2];
#pragma unroll
            for (int mt = 0; mt < 4; mt++) {
                const float* p = As + (warp_m + mt * 16 + (lane >> 2)) * A_STRIDE
                               + kb + (lane & 3);
                af[mt][0] = __float_as_uint(p[0]);
                af[mt][1] = __float_as_uint(p[8 * A_STRIDE]);
                af[mt][2] = __float_as_uint(p[4]);
                af[mt][3] = __float_as_uint(p[8 * A_STRIDE + 4]);
            }
#pragma unroll
            for (int nt = 0; nt < 8; nt++) {
                const float* p = Bs + (kb + (lane & 3)) * B_STRIDE
                               + warp_n + nt * 8 + (lane >> 2);
                bf[nt][0] = __float_as_uint(p[0]);
                bf[nt][1] = __float_as_uint(p[4 * B_STRIDE]);
            }
#pragma unroll
            for (int mt = 0; mt < 4; mt++)
#pragma unroll
                for (int nt = 0; nt < 8; nt++)
                    mma_tf32(acc[mt][nt], af[mt][0], af[mt][1], af[mt][2], af[mt][3],
                             bf[nt][0], bf[nt][1]);
        }
        __syncthreads();
        if (c + 3 < 32) { load_stage(s, c + 3); }
        CP_COMMIT;
    }

    int crow = lane >> 2, ccol2 = (lane & 3) * 2;
#pragma unroll
    for (int mt = 0; mt < 4; mt++) {
#pragma unroll
        for (int nt = 0; nt < 8; nt++) {
            int n = n0 + warp_n + nt * 8 + ccol2;
            float bx = bias[n], by = bias[n + 1];
#pragma unroll
            for (int half = 0; half < 2; half++) {
                int m = m0 + warp_m + mt * 16 + crow + half * 8;
                float2 v;
                v.x = acc[mt][nt][half * 2 + 0] + bx;
                v.y = acc[mt][nt][half * 2 + 1] + by;
                if (mode == 1) {
                    *(float2*)(Cout + (size_t)m * DMODEL + n) = v;
                } else {
                    int b = m >> 11, srow = m & (SEQ - 1);
                    int chunk = n >> 10;
                    int cc = n & (DMODEL - 1);
                    int h = cc >> 6, d0 = cc & (DH - 1);
                    if (chunk == 2) {        // V -> fp16, transposed [bh][d][s]
                        size_t base = ((size_t)(b << 4) + h) * DH;
                        g_Vh[(base + d0) * SEQ + srow]     = __float2half_rn(v.x);
                        g_Vh[(base + d0 + 1) * SEQ + srow] = __float2half_rn(v.y);
                    } else {                 // K or Q -> bf16 hi/lo split
                        size_t off = (((size_t)(b << 4) + h) * SEQ + srow) * DH + d0;
                        __nv_bfloat16 hx = __float2bfloat16_rn(v.x);
                        __nv_bfloat16 hy = __float2bfloat16_rn(v.y);
                        __nv_bfloat16 lx = __float2bfloat16_rn(v.x - __bfloat162float(hx));
                        __nv_bfloat16 ly = __float2bfloat16_rn(v.y - __bfloat162float(hy));
                        __nv_bfloat162 hi; hi.x = hx; hi.y = hy;
                        __nv_bfloat162 lo; lo.x = lx; lo.y = ly;
                        if (chunk == 0) {
                            *(__nv_bfloat162*)(g_Khb + off) = hi;
                            *(__nv_bfloat162*)(g_Klb + off) = lo;
                        } else {
                            *(__nv_bfloat162*)(g_Qhb + off) = hi;
                            *(__nv_bfloat162*)(g_Qlb + off) = lo;
                        }
                    }
                }
            }
        }
    }
}

// ============================================================================
// Flash attention. Br=128, Bc=64, 8 warps x 16 q-rows, 2 CTAs/SM.
// QK^T: 3-term bf16 split (m16n8k16). PV: fp16 m16n8k16, P register-resident.
// ============================================================================
#define QSW 36   // Q/K/V row stride in words (72 halves)
#define QH_OFF 0
#define QL_OFF 4608                    // 128*36
#define KH_OFF 9216                    // + s*2304  (64*36)
#define KL_OFF 13824
#define V_OFF  18432
#define AT_WORDS 23040
#define AT_BYTES (AT_WORDS * 4)        // 92160 B

__global__ __launch_bounds__(256, 2) void attn_mma_kernel()
{
    extern __shared__ uint32_t smw[];
    int tid = threadIdx.x;
    int wid = tid >> 5, lane = tid & 31;
    int bh = blockIdx.y;
    int q0 = blockIdx.x * 128;

    const __nv_bfloat16* QhG = g_Qhb + ((size_t)bh * SEQ + q0) * DH;
    const __nv_bfloat16* QlG = g_Qlb + ((size_t)bh * SEQ + q0) * DH;
    const __nv_bfloat16* KhG = g_Khb + (size_t)bh * SEQ * DH;
    const __nv_bfloat16* KlG = g_Klb + (size_t)bh * SEQ * DH;
    const __half* VhG = g_Vh + (size_t)bh * SEQ * DH;   // [d][s]

    uint32_t smb = smem_u32(smw);

    // ---- Q tile [128x64] bf16 hi+lo via cp.async ----
    {
        int row = tid >> 1, half = (tid & 1);
#pragma unroll
        for (int q = 0; q < 4; q++) {
            int eo = half * 32 + q * 8;
            CP_ASYNC16(smb + QH_OFF * 4 + row * 144 + half * 64 + q * 16,
                       QhG + row * DH + eo);
            CP_ASYNC16(smb + QL_OFF * 4 + row * 144 + half * 64 + q * 16,
                       QlG + row * DH + eo);
        }
    }
    // ---- K (bf16 hi/lo) + V (fp16, [d][s]) tile loader ----
    int krow = tid >> 2, kc4 = tid & 3;
    auto load_kv = [&](int s, int kt) {
        const __nv_bfloat16* kh = KhG + ((size_t)kt * 64 + krow) * DH;
        const __nv_bfloat16* kl = KlG + ((size_t)kt * 64 + krow) * DH;
        const __half* vp = VhG + (size_t)krow * SEQ + kt * 64;
#pragma unroll
        for (int q = 0; q < 2; q++) {
            int eo = kc4 * 16 + q * 8;
            CP_ASYNC16(smb + (KH_OFF + s * 2304) * 4 + krow * 144 + kc4 * 32 + q * 16,
                       kh + eo);
            CP_ASYNC16(smb + (KL_OFF + s * 2304) * 4 + krow * 144 + kc4 * 32 + q * 16,
                       kl + eo);
            CP_ASYNC16(smb + (V_OFF + s * 2304) * 4 + krow * 144 + kc4 * 32 + q * 16,
                       vp + eo);
        }
    };

    load_kv(0, 0);
    CP_COMMIT;           // group: Q + KV0
    load_kv(1, 1);
    CP_COMMIT;           // group: KV1

    float m0v = -INFINITY, m1v = -INFINITY, l0v = 0.f, l1v = 0.f;
    float o[8][4];
#pragma unroll
    for (int nt = 0; nt < 8; nt++)
#pragma unroll
        for (int j = 0; j < 4; j++) o[nt][j] = 0.f;

    int r0 = wid * 16 + (lane >> 2);  // query row (first half)
    int kq = lane & 3;
    int nq = lane >> 2;

    const uint32_t* Qh = smw + QH_OFF;
    const uint32_t* Ql = smw + QL_OFF;

    for (int kt = 0; kt < SEQ / 64; kt++) {
        int s = kt & 1;
        CP_WAIT1;
        __syncthreads();

        const uint32_t* Kh = smw + KH_OFF + s * 2304;
        const uint32_t* Kl = smw + KL_OFF + s * 2304;
        const uint32_t* Vs = smw + V_OFF  + s * 2304;

        // ---- S = Q K^T, bf16 3-term split, m16n8k16 ----
        float sc[8][4];
#pragma unroll
        for (int nt = 0; nt < 8; nt++)
#pragma unroll
            for (int j = 0; j < 4; j++) sc[nt][j] = 0.f;
#pragma unroll
        for (int ks = 0; ks < 4; ks++) {
            int kb = ks * 8;
            uint32_t ah0 = Qh[r0 * QSW + kb + kq];
            uint32_t ah1 = Qh[(r0 + 8) * QSW + kb + kq];
            uint32_t ah2 = Qh[r0 * QSW + kb + kq + 4];
            uint32_t ah3 = Qh[(r0 + 8) * QSW + kb + kq + 4];
            uint32_t al0 = Ql[r0 * QSW + kb + kq];
            uint32_t al1 = Ql[(r0 + 8) * QSW + kb + kq];
            uint32_t al2 = Ql[r0 * QSW + kb + kq + 4];
            uint32_t al3 = Ql[(r0 + 8) * QSW + kb + kq + 4];
#pragma unroll
            for (int nt = 0; nt < 8; nt++) {
                int n = nt * 8 + nq;
                uint32_t bh0 = Kh[n * QSW + kb + kq];
                uint32_t bh1 = Kh[n * QSW + kb + kq + 4];
                uint32_t bl0 = Kl[n * QSW + kb + kq];
                uint32_t bl1 = Kl[n * QSW + kb + kq + 4];
                mma_bf16(sc[nt], ah0, ah1, ah2, ah3, bh0, bh1);
                mma_bf16(sc[nt], ah0, ah1, ah2, ah3, bl0, bl1);
                mma_bf16(sc[nt], al0, al1, al2, al3, bh0, bh1);
            }
        }

        // ---- online softmax (rows r0, r0+8; scale 1/8); P -> fp16 regs ----
        float mx0 = sc[0][0], mx1 = sc[0][2];
#pragma unroll
        for (int nt = 0; nt < 8; nt++) {
            mx0 = fmaxf(mx0, fmaxf(sc[nt][0], sc[nt][1]));
            mx1 = fmaxf(mx1, fmaxf(sc[nt][2], sc[nt][3]));
        }
        mx0 = fmaxf(mx0, __shfl_xor_sync(0xffffffffu, mx0, 1));
        mx0 = fmaxf(mx0, __shfl_xor_sync(0xffffffffu, mx0, 2));
        mx1 = fmaxf(mx1, __shfl_xor_sync(0xffffffffu, mx1, 1));
        mx1 = fmaxf(mx1, __shfl_xor_sync(0xffffffffu, mx1, 2));
        float mn0 = fmaxf(m0v, mx0 * 0.125f);
        float mn1 = fmaxf(m1v, mx1 * 0.125f);
        float alf0 = __expf(m0v - mn0), alf1 = __expf(m1v - mn1);
        m0v = mn0; m1v = mn1;
        float rs0 = 0.f, rs1 = 0.f;
        uint32_t pa[4][4];
#pragma unroll
        for (int nt = 0; nt < 8; nt++) {
            float p0 = __expf(sc[nt][0] * 0.125f - mn0);
            float p1 = __expf(sc[nt][1] * 0.125f - mn0);
            float p2 = __expf(sc[nt][2] * 0.125f - mn1);
            float p3 = __expf(sc[nt][3] * 0.125f - mn1);
            rs0 += p0 + p1; rs1 += p2 + p3;
            int t = nt >> 1, hi = (nt & 1) * 2;
            pa[t][hi]     = pack_h2(p0, p1);
            pa[t][hi + 1] = pack_h2(p2, p3);
            o[nt][0] *= alf0; o[nt][1] *= alf0;
            o[nt][2] *= alf1; o[nt][3] *= alf1;
        }
        rs0 += __shfl_xor_sync(0xffffffffu, rs0, 1);
        rs0 += __shfl_xor_sync(0xffffffffu, rs0, 2);
        rs1 += __shfl_xor_sync(0xffffffffu, rs1, 1);
        rs1 += __shfl_xor_sync(0xffffffffu, rs1, 2);
        l0v = l0v * alf0 + rs0;
        l1v = l1v * alf1 + rs1;

        // ---- O += P V  (fp16 m16n8k16, P from registers) ----
#pragma unroll
        for (int t = 0; t < 4; t++) {
#pragma unroll
            for (int nt = 0; nt < 8; nt++) {
                int n = nt * 8 + nq;            // d column
                uint32_t vb0 = Vs[n * QSW + t * 8 + kq];
                uint32_t vb1 = Vs[n * QSW + t * 8 + kq + 4];
                mma_f16(o[nt], pa[t][0], pa[t][1], pa[t][2], pa[t][3], vb0, vb1);
            }
        }

        __syncthreads();
        if (kt + 2 < SEQ / 64) {
            load_kv(s, kt + 2);
            CP_COMMIT;
        }
    }

    // ---- epilogue: normalize, round to tf32, merge heads ----
    float inv0 = 1.f / l0v, inv1 = 1.f / l1v;
    int b = bh >> 4, h = bh & (NH - 1);
    int q = q0 + r0;
    float* dst0 = g_O + ((size_t)(b * SEQ + q)) * DMODEL + h * DH;
    float* dst1 = dst0 + 8 * DMODEL;
#pragma unroll
    for (int nt = 0; nt < 8; nt++) {
        int cb = nt * 8 + 2 * kq;
        float2 v0; v0.x = rndtf(o[nt][0] * inv0); v0.y = rndtf(o[nt][1] * inv0);
        float2 v1; v1.x = rndtf(o[nt][2] * inv1); v1.y = rndtf(o[nt][3] * inv1);
        *(float2*)(dst0 + cb) = v0;
        *(float2*)(dst1 + cb) = v1;
    }
}

// ---------------------------------------------------------------------------
extern "C" void kernel_launch(void* const* d_in, const int* in_sizes, int n_in,
                              void* d_out, int out_size) {
    (void)in_sizes; (void)n_in; (void)out_size;
    const float* x     = (const float*)d_in[0];
    const float* w_in  = (const float*)d_in[1];
    const float* b_in  = (const float*)d_in[2];
    const float* w_out = (const float*)d_in[3];
    const float* b_out = (const float*)d_in[4];
    float* out = (float*)d_out;

    cudaFuncSetAttribute(gemm_tf32_kernel,
                         cudaFuncAttributeMaxDynamicSharedMemorySize, GSM_BYTES);
    cudaFuncSetAttribute(attn_mma_kernel,
                         cudaFuncAttributeMaxDynamicSharedMemorySize, AT_BYTES);

    float *gO_ptr, *gxc, *gw1c, *gw2c;
    cudaGetSymbolAddress((void**)&gO_ptr, g_O);
    cudaGetSymbolAddress((void**)&gxc,  g_xc);
    cudaGetSymbolAddress((void**)&gw1c, g_w1c);
    cudaGetSymbolAddress((void**)&gw2c, g_w2c);

    // Pre-round GEMM inputs to tf32
    {
        int n4 = ROWS * DMODEL / 4;
        cvt_tf32_kernel<<<(n4 + 255) / 256, 256>>>((const float4*)x, (float4*)gxc, n4);
        n4 = DMODEL * N_QKV / 4;
        cvt_tf32_kernel<<<(n4 + 255) / 256, 256>>>((const float4*)w_in, (float4*)gw1c, n4);
        n4 = DMODEL * DMODEL / 4;
        cvt_tf32_kernel<<<(n4 + 255) / 256, 256>>>((const float4*)w_out, (float4*)gw2c, n4);
    }

    // GEMM1: QKV projection + split-scatter  (M=8192, N=3072)
    gemm_tf32_kernel<<<dim3(N_QKV / 128, ROWS / 128), 128, GSM_BYTES>>>(
        gxc, gw1c, b_in, nullptr, N_QKV, 0);
    // Attention: 16 q-tiles x 64 (b,h)
    attn_mma_kernel<<<dim3(SEQ / 128, B_SZ * NH), 256, AT_BYTES>>>();
    // GEMM2: output projection  (M=8192, N=1024)
    gemm_tf32_kernel<<<dim3(DMODEL / 128, ROWS / 128), 128, GSM_BYTES>>>(
        gO_ptr, gw2c, b_out, out, DMODEL, 1);
}

// round 10
// speedup vs baseline: 5.2368x; 1.7217x over previous
#include <cuda_runtime.h>
#include <cuda_bf16.h>
#include <cuda_fp16.h>
#include <math.h>
#include <cstdint>

#define B_SZ   4
#define SEQ    2048
#define DMODEL 1024
#define NH     16
#define DH     64
#define ROWS   (B_SZ*SEQ)     // 8192
#define N_QKV  (3*DMODEL)     // 3072

// Scratch (allocation-free: device globals)
__device__ __nv_bfloat16 g_Qhb[B_SZ*NH*SEQ*DH];  // bf16-hi of Q, [bh][s][d]
__device__ __nv_bfloat16 g_Qlb[B_SZ*NH*SEQ*DH];  // bf16-lo of Q
__device__ __nv_bfloat16 g_Khb[B_SZ*NH*SEQ*DH];
__device__ __nv_bfloat16 g_Klb[B_SZ*NH*SEQ*DH];
__device__ __half g_Vh[B_SZ*NH*SEQ*DH];          // fp16(V), TRANSPOSED [bh][d][s]
__device__ __half g_Oh[ROWS*DMODEL];    // attention out fp16 (GEMM2 A)
__device__ __half g_xh[ROWS*DMODEL];    // fp16(x), [m][k]
__device__ __half g_w1t[N_QKV*DMODEL];  // fp16(w_in^T), [n][k]
__device__ __half g_w2t[DMODEL*DMODEL]; // fp16(w_out^T), [n][k]

// ============================================================================
// Helpers
// ============================================================================
__device__ __forceinline__ uint32_t pack_h2(float x, float y) {
    __half2 h = __floats2half2_rn(x, y);
    return *reinterpret_cast<uint32_t*>(&h);
}
__device__ __forceinline__ void mma_bf16(float c[4],
    uint32_t a0, uint32_t a1, uint32_t a2, uint32_t a3,
    uint32_t b0, uint32_t b1)
{
    asm volatile(
        "mma.sync.aligned.m16n8k16.row.col.f32.bf16.bf16.f32 "
        "{%0,%1,%2,%3}, {%4,%5,%6,%7}, {%8,%9}, {%0,%1,%2,%3};"
        : "+f"(c[0]), "+f"(c[1]), "+f"(c[2]), "+f"(c[3])
        : "r"(a0), "r"(a1), "r"(a2), "r"(a3), "r"(b0), "r"(b1));
}
__device__ __forceinline__ void mma_f16(float c[4],
    uint32_t a0, uint32_t a1, uint32_t a2, uint32_t a3,
    uint32_t b0, uint32_t b1)
{
    asm volatile(
        "mma.sync.aligned.m16n8k16.row.col.f32.f16.f16.f32 "
        "{%0,%1,%2,%3}, {%4,%5,%6,%7}, {%8,%9}, {%0,%1,%2,%3};"
        : "+f"(c[0]), "+f"(c[1]), "+f"(c[2]), "+f"(c[3])
        : "r"(a0), "r"(a1), "r"(a2), "r"(a3), "r"(b0), "r"(b1));
}
__device__ __forceinline__ uint32_t smem_u32(const void* p) {
    uint32_t a;
    asm("{ .reg .u64 t; cvta.to.shared.u64 t, %1; cvt.u32.u64 %0, t; }"
        : "=r"(a) : "l"(p));
    return a;
}
#define LDSM_X4(r0, r1, r2, r3, addr) \
    asm volatile("ldmatrix.sync.aligned.m8n8.x4.shared.b16 {%0,%1,%2,%3}, [%4];" \
        : "=r"(r0), "=r"(r1), "=r"(r2), "=r"(r3) : "r"(addr))
#define CP_ASYNC16(dst_u32, src_ptr) \
    asm volatile("cp.async.cg.shared.global [%0], [%1], 16;" \
                 :: "r"(dst_u32), "l"(src_ptr) : "memory")
#define CP_COMMIT  asm volatile("cp.async.commit_group;" ::: "memory")
#define CP_WAIT1   asm volatile("cp.async.wait_group 1;" ::: "memory")
#define CP_WAIT2   asm volatile("cp.async.wait_group 2;" ::: "memory")

// ============================================================================
// Pre-kernels: fp16 convert (x) and transpose+convert (weights)
// ============================================================================
__global__ __launch_bounds__(256) void cvt_h_kernel(
    const float4* __restrict__ src, uint2* __restrict__ dst, int n4)
{
    int i = blockIdx.x * blockDim.x + threadIdx.x;
    if (i < n4) {
        float4 v = src[i];
        uint2 o;
        o.x = pack_h2(v.x, v.y);
        o.y = pack_h2(v.z, v.w);
        dst[i] = o;
    }
}

// dst[n][k] = fp16(src[k][n]);  K,N multiples of 32
__global__ __launch_bounds__(256) void transp_h_kernel(
    const float* __restrict__ src, __half* __restrict__ dst, int K, int N)
{
    __shared__ float tile[32][33];
    int k0 = blockIdx.y * 32, n0 = blockIdx.x * 32;
    int tx = threadIdx.x & 31, ty = threadIdx.x >> 5;   // 32 x 8
#pragma unroll
    for (int i = 0; i < 32; i += 8)
        tile[ty + i][tx] = src[(size_t)(k0 + ty + i) * N + n0 + tx];
    __syncthreads();
#pragma unroll
    for (int i = 0; i < 32; i += 8)
        dst[(size_t)(n0 + ty + i) * K + k0 + tx] = __float2half_rn(tile[tx][ty + i]);
}

// ============================================================================
// fp16 mma.sync GEMM: C[M,N] = A[M,1024] @ Wt[N,1024]^T + bias
// CTA 128x128, 256 thr (8 warps of 64x32), K-chunk 32, 3-stage, ldmatrix.
// mode 0: split-scatter (Q/K -> bf16 hi/lo, V -> fp16 transposed)
// mode 1: Cout fp32 row-major
// ============================================================================
#define HS 40                          // half stride per row (80 B)
#define TILE_H (128 * HS)              // halves per A or B tile
#define STAGE_B (2 * TILE_H * 2)       // bytes per stage: 20480
#define GSM_BYTES (3 * STAGE_B)        // 61440

__global__ __launch_bounds__(256, 2) void gemm_h_kernel(
    const __half* __restrict__ A,      // [M,1024]
    const __half* __restrict__ Wt,     // [N,1024]
    const float* __restrict__ bias,
    float* __restrict__ Cout,
    int mode)
{
    extern __shared__ char smc[];
    uint32_t smb = smem_u32(smc);
    int tid  = threadIdx.x;
    int wid  = tid >> 5, lane = tid & 31;
    int m0 = blockIdx.y * 128, n0 = blockIdx.x * 128;
    int warp_m = (wid & 1) * 64;
    int warp_n = (wid >> 1) * 32;

    const __half* a_src = A + (size_t)(m0 + (tid >> 1)) * DMODEL + (tid & 1) * 16;
    const __half* b_src = Wt + (size_t)(n0 + (tid >> 1)) * DMODEL + (tid & 1) * 16;
    uint32_t a_dst = smb + (tid >> 1) * 80 + (tid & 1) * 32;
    uint32_t b_dst = a_dst + TILE_H * 2;

    auto load_stage = [&](int s, int c) {
        int kc = c * 32;
        uint32_t so = s * STAGE_B;
#pragma unroll
        for (int q = 0; q < 2; q++) {
            CP_ASYNC16(a_dst + so + q * 16, a_src + kc + q * 8);
            CP_ASYNC16(b_dst + so + q * 16, b_src + kc + q * 8);
        }
    };

    float acc[4][4][4];
#pragma unroll
    for (int i = 0; i < 4; i++)
#pragma unroll
        for (int j = 0; j < 4; j++)
#pragma unroll
            for (int k = 0; k < 4; k++) acc[i][j][k] = 0.f;

    // ldmatrix lane addresses (byte offsets within a stage)
    int lrow = lane & 7, lt = lane >> 3;
    uint32_t aA[4], bA[2];
#pragma unroll
    for (int mt = 0; mt < 4; mt++)
        aA[mt] = smb + (warp_m + mt * 16 + lrow + (lt & 1) * 8) * 80 + (lt >> 1) * 16;
#pragma unroll
    for (int p = 0; p < 2; p++)
        bA[p] = smb + TILE_H * 2
              + (warp_n + p * 16 + lrow + (lt >> 1) * 8) * 80 + (lt & 1) * 16;

    load_stage(0, 0); CP_COMMIT;
    load_stage(1, 1); CP_COMMIT;
    load_stage(2, 2); CP_COMMIT;

    for (int c = 0; c < 32; c++) {
        int s = c % 3;
        uint32_t so = s * STAGE_B;
        CP_WAIT2;
        __syncthreads();

#pragma unroll
        for (int step = 0; step < 2; step++) {
            uint32_t kbb = so + step * 32;      // 16 halves = 32 B per k16 step
            uint32_t af[4][4], bf[2][4];
#pragma unroll
            for (int mt = 0; mt < 4; mt++)
                LDSM_X4(af[mt][0], af[mt][1], af[mt][2], af[mt][3], aA[mt] + kbb);
#pragma unroll
            for (int p = 0; p < 2; p++)
                LDSM_X4(bf[p][0], bf[p][1], bf[p][2], bf[p][3], bA[p] + kbb);
#pragma unroll
            for (int mt = 0; mt < 4; mt++)
#pragma unroll
                for (int p = 0; p < 2; p++) {
                    mma_f16(acc[mt][2 * p], af[mt][0], af[mt][1], af[mt][2], af[mt][3],
                            bf[p][0], bf[p][1]);
                    mma_f16(acc[mt][2 * p + 1], af[mt][0], af[mt][1], af[mt][2], af[mt][3],
                            bf[p][2], bf[p][3]);
                }
        }
        __syncthreads();
        if (c + 3 < 32) load_stage(s, c + 3);
        CP_COMMIT;
    }

    int crow = lane >> 2, ccol2 = (lane & 3) * 2;
#pragma unroll
    for (int mt = 0; mt < 4; mt++) {
#pragma unroll
        for (int nt = 0; nt < 4; nt++) {
            int n = n0 + warp_n + nt * 8 + ccol2;
            float bx = bias[n], by = bias[n + 1];
#pragma unroll
            for (int half = 0; half < 2; half++) {
                int m = m0 + warp_m + mt * 16 + crow + half * 8;
                float2 v;
                v.x = acc[mt][nt][half * 2 + 0] + bx;
                v.y = acc[mt][nt][half * 2 + 1] + by;
                if (mode == 1) {
                    *(float2*)(Cout + (size_t)m * DMODEL + n) = v;
                } else {
                    int b = m >> 11, srow = m & (SEQ - 1);
                    int chunk = n >> 10;
                    int cc = n & (DMODEL - 1);
                    int h = cc >> 6, d0 = cc & (DH - 1);
                    if (chunk == 2) {        // V -> fp16, transposed [bh][d][s]
                        size_t base = ((size_t)(b << 4) + h) * DH;
                        g_Vh[(base + d0) * SEQ + srow]     = __float2half_rn(v.x);
                        g_Vh[(base + d0 + 1) * SEQ + srow] = __float2half_rn(v.y);
                    } else {                 // K or Q -> bf16 hi/lo split
                        size_t off = (((size_t)(b << 4) + h) * SEQ + srow) * DH + d0;
                        __nv_bfloat16 hx = __float2bfloat16_rn(v.x);
                        __nv_bfloat16 hy = __float2bfloat16_rn(v.y);
                        __nv_bfloat16 lx = __float2bfloat16_rn(v.x - __bfloat162float(hx));
                        __nv_bfloat16 ly = __float2bfloat16_rn(v.y - __bfloat162float(hy));
                        __nv_bfloat162 hi; hi.x = hx; hi.y = hy;
                        __nv_bfloat162 lo; lo.x = lx; lo.y = ly;
                        if (chunk == 0) {
                            *(__nv_bfloat162*)(g_Khb + off) = hi;
                            *(__nv_bfloat162*)(g_Klb + off) = lo;
                        } else {
                            *(__nv_bfloat162*)(g_Qhb + off) = hi;
                            *(__nv_bfloat162*)(g_Qlb + off) = lo;
                        }
                    }
                }
            }
        }
    }
}

// ============================================================================
// Flash attention. Br=128, Bc=64, 8 warps x 16 q-rows, 2 CTAs/SM.
// QK^T: 3-term bf16 split (m16n8k16). PV: fp16 m16n8k16, P register-resident.
// ============================================================================
#define QSW 36   // Q/K/V row stride in words (72 halves)
#define QH_OFF 0
#define QL_OFF 4608                    // 128*36
#define KH_OFF 9216                    // + s*2304  (64*36)
#define KL_OFF 13824
#define V_OFF  18432
#define AT_WORDS 23040
#define AT_BYTES (AT_WORDS * 4)        // 92160 B

__global__ __launch_bounds__(256, 2) void attn_mma_kernel()
{
    extern __shared__ uint32_t smw[];
    int tid = threadIdx.x;
    int wid = tid >> 5, lane = tid & 31;
    int bh = blockIdx.y;
    int q0 = blockIdx.x * 128;

    const __nv_bfloat16* QhG = g_Qhb + ((size_t)bh * SEQ + q0) * DH;
    const __nv_bfloat16* QlG = g_Qlb + ((size_t)bh * SEQ + q0) * DH;
    const __nv_bfloat16* KhG = g_Khb + (size_t)bh * SEQ * DH;
    const __nv_bfloat16* KlG = g_Klb + (size_t)bh * SEQ * DH;
    const __half* VhG = g_Vh + (size_t)bh * SEQ * DH;   // [d][s]

    uint32_t smb = smem_u32(smw);

    // ---- Q tile [128x64] bf16 hi+lo via cp.async ----
    {
        int row = tid >> 1, half = (tid & 1);
#pragma unroll
        for (int q = 0; q < 4; q++) {
            int eo = half * 32 + q * 8;
            CP_ASYNC16(smb + QH_OFF * 4 + row * 144 + half * 64 + q * 16,
                       QhG + row * DH + eo);
            CP_ASYNC16(smb + QL_OFF * 4 + row * 144 + half * 64 + q * 16,
                       QlG + row * DH + eo);
        }
    }
    // ---- K (bf16 hi/lo) + V (fp16, [d][s]) tile loader ----
    int krow = tid >> 2, kc4 = tid & 3;
    auto load_kv = [&](int s, int kt) {
        const __nv_bfloat16* kh = KhG + ((size_t)kt * 64 + krow) * DH;
        const __nv_bfloat16* kl = KlG + ((size_t)kt * 64 + krow) * DH;
        const __half* vp = VhG + (size_t)krow * SEQ + kt * 64;
#pragma unroll
        for (int q = 0; q < 2; q++) {
            int eo = kc4 * 16 + q * 8;
            CP_ASYNC16(smb + (KH_OFF + s * 2304) * 4 + krow * 144 + kc4 * 32 + q * 16,
                       kh + eo);
            CP_ASYNC16(smb + (KL_OFF + s * 2304) * 4 + krow * 144 + kc4 * 32 + q * 16,
                       kl + eo);
            CP_ASYNC16(smb + (V_OFF + s * 2304) * 4 + krow * 144 + kc4 * 32 + q * 16,
                       vp + eo);
        }
    };

    load_kv(0, 0);
    CP_COMMIT;           // group: Q + KV0
    load_kv(1, 1);
    CP_COMMIT;           // group: KV1

    float m0v = -INFINITY, m1v = -INFINITY, l0v = 0.f, l1v = 0.f;
    float o[8][4];
#pragma unroll
    for (int nt = 0; nt < 8; nt++)
#pragma unroll
        for (int j = 0; j < 4; j++) o[nt][j] = 0.f;

    int r0 = wid * 16 + (lane >> 2);  // query row (first half)
    int kq = lane & 3;
    int nq = lane >> 2;

    const uint32_t* Qh = smw + QH_OFF;
    const uint32_t* Ql = smw + QL_OFF;

    for (int kt = 0; kt < SEQ / 64; kt++) {
        int s = kt & 1;
        CP_WAIT1;
        __syncthreads();

        const uint32_t* Kh = smw + KH_OFF + s * 2304;
        const uint32_t* Kl = smw + KL_OFF + s * 2304;
        const uint32_t* Vs = smw + V_OFF  + s * 2304;

        // ---- S = Q K^T, bf16 3-term split, m16n8k16 ----
        float sc[8][4];
#pragma unroll
        for (int nt = 0; nt < 8; nt++)
#pragma unroll
            for (int j = 0; j < 4; j++) sc[nt][j] = 0.f;
#pragma unroll
        for (int ks = 0; ks < 4; ks++) {
            int kb = ks * 8;
            uint32_t ah0 = Qh[r0 * QSW + kb + kq];
            uint32_t ah1 = Qh[(r0 + 8) * QSW + kb + kq];
            uint32_t ah2 = Qh[r0 * QSW + kb + kq + 4];
            uint32_t ah3 = Qh[(r0 + 8) * QSW + kb + kq + 4];
            uint32_t al0 = Ql[r0 * QSW + kb + kq];
            uint32_t al1 = Ql[(r0 + 8) * QSW + kb + kq];
            uint32_t al2 = Ql[r0 * QSW + kb + kq + 4];
            uint32_t al3 = Ql[(r0 + 8) * QSW + kb + kq + 4];
#pragma unroll
            for (int nt = 0; nt < 8; nt++) {
                int n = nt * 8 + nq;
                uint32_t bh0 = Kh[n * QSW + kb + kq];
                uint32_t bh1 = Kh[n * QSW + kb + kq + 4];
                uint32_t bl0 = Kl[n * QSW + kb + kq];
                uint32_t bl1 = Kl[n * QSW + kb + kq + 4];
                mma_bf16(sc[nt], ah0, ah1, ah2, ah3, bh0, bh1);
                mma_bf16(sc[nt], ah0, ah1, ah2, ah3, bl0, bl1);
                mma_bf16(sc[nt], al0, al1, al2, al3, bh0, bh1);
            }
        }

        // ---- online softmax (rows r0, r0+8; scale 1/8); P -> fp16 regs ----
        float mx0 = sc[0][0], mx1 = sc[0][2];
#pragma unroll
        for (int nt = 0; nt < 8; nt++) {
            mx0 = fmaxf(mx0, fmaxf(sc[nt][0], sc[nt][1]));
            mx1 = fmaxf(mx1, fmaxf(sc[nt][2], sc[nt][3]));
        }
        mx0 = fmaxf(mx0, __shfl_xor_sync(0xffffffffu, mx0, 1));
        mx0 = fmaxf(mx0, __shfl_xor_sync(0xffffffffu, mx0, 2));
        mx1 = fmaxf(mx1, __shfl_xor_sync(0xffffffffu, mx1, 1));
        mx1 = fmaxf(mx1, __shfl_xor_sync(0xffffffffu, mx1, 2));
        float mn0 = fmaxf(m0v, mx0 * 0.125f);
        float mn1 = fmaxf(m1v, mx1 * 0.125f);
        float alf0 = __expf(m0v - mn0), alf1 = __expf(m1v - mn1);
        m0v = mn0; m1v = mn1;
        float rs0 = 0.f, rs1 = 0.f;
        uint32_t pa[4][4];
#pragma unroll
        for (int nt = 0; nt < 8; nt++) {
            float p0 = __expf(sc[nt][0] * 0.125f - mn0);
            float p1 = __expf(sc[nt][1] * 0.125f - mn0);
            float p2 = __expf(sc[nt][2] * 0.125f - mn1);
            float p3 = __expf(sc[nt][3] * 0.125f - mn1);
            rs0 += p0 + p1; rs1 += p2 + p3;
            int t = nt >> 1, hi = (nt & 1) * 2;
            pa[t][hi]     = pack_h2(p0, p1);
            pa[t][hi + 1] = pack_h2(p2, p3);
            o[nt][0] *= alf0; o[nt][1] *= alf0;
            o[nt][2] *= alf1; o[nt][3] *= alf1;
        }
        rs0 += __shfl_xor_sync(0xffffffffu, rs0, 1);
        rs0 += __shfl_xor_sync(0xffffffffu, rs0, 2);
        rs1 += __shfl_xor_sync(0xffffffffu, rs1, 1);
        rs1 += __shfl_xor_sync(0xffffffffu, rs1, 2);
        l0v = l0v * alf0 + rs0;
        l1v = l1v * alf1 + rs1;

        // ---- O += P V  (fp16 m16n8k16, P from registers) ----
#pragma unroll
        for (int t = 0; t < 4; t++) {
#pragma unroll
            for (int nt = 0; nt < 8; nt++) {
                int n = nt * 8 + nq;            // d column
                uint32_t vb0 = Vs[n * QSW + t * 8 + kq];
                uint32_t vb1 = Vs[n * QSW + t * 8 + kq + 4];
                mma_f16(o[nt], pa[t][0], pa[t][1], pa[t][2], pa[t][3], vb0, vb1);
            }
        }

        __syncthreads();
        if (kt + 2 < SEQ / 64) {
            load_kv(s, kt + 2);
            CP_COMMIT;
        }
    }

    // ---- epilogue: normalize, fp16 for GEMM2, merge heads ----
    float inv0 = 1.f / l0v, inv1 = 1.f / l1v;
    int b = bh >> 4, h = bh & (NH - 1);
    int q = q0 + r0;
    __half* dst0 = g_Oh + ((size_t)(b * SEQ + q)) * DMODEL + h * DH;
    __half* dst1 = dst0 + 8 * DMODEL;
#pragma unroll
    for (int nt = 0; nt < 8; nt++) {
        int cb = nt * 8 + 2 * kq;
        *(uint32_t*)(dst0 + cb) = pack_h2(o[nt][0] * inv0, o[nt][1] * inv0);
        *(uint32_t*)(dst1 + cb) = pack_h2(o[nt][2] * inv1, o[nt][3] * inv1);
    }
}

// ---------------------------------------------------------------------------
extern "C" void kernel_launch(void* const* d_in, const int* in_sizes, int n_in,
                              void* d_out, int out_size) {
    (void)in_sizes; (void)n_in; (void)out_size;
    const float* x     = (const float*)d_in[0];
    const float* w_in  = (const float*)d_in[1];
    const float* b_in  = (const float*)d_in[2];
    const float* w_out = (const float*)d_in[3];
    const float* b_out = (const float*)d_in[4];
    float* out = (float*)d_out;

    cudaFuncSetAttribute(gemm_h_kernel,
                         cudaFuncAttributeMaxDynamicSharedMemorySize, GSM_BYTES);
    cudaFuncSetAttribute(attn_mma_kernel,
                         cudaFuncAttributeMaxDynamicSharedMemorySize, AT_BYTES);

    __half *gxh, *gw1t, *gw2t, *gOh;
    cudaGetSymbolAddress((void**)&gxh,  g_xh);
    cudaGetSymbolAddress((void**)&gw1t, g_w1t);
    cudaGetSymbolAddress((void**)&gw2t, g_w2t);
    cudaGetSymbolAddress((void**)&gOh,  g_Oh);

    // Pre: x -> fp16, weights -> transposed fp16
    {
        int n4 = ROWS * DMODEL / 4;
        cvt_h_kernel<<<(n4 + 255) / 256, 256>>>((const float4*)x, (uint2*)gxh, n4);
        transp_h_kernel<<<dim3(N_QKV / 32, DMODEL / 32), 256>>>(w_in, gw1t, DMODEL, N_QKV);
        transp_h_kernel<<<dim3(DMODEL / 32, DMODEL / 32), 256>>>(w_out, gw2t, DMODEL, DMODEL);
    }

    // GEMM1: QKV projection + split-scatter  (M=8192, N=3072)
    gemm_h_kernel<<<dim3(N_QKV / 128, ROWS / 128), 256, GSM_BYTES>>>(
        gxh, gw1t, b_in, nullptr, 0);
    // Attention: 16 q-tiles x 64 (b,h)
    attn_mma_kernel<<<dim3(SEQ / 128, B_SZ * NH), 256, AT_BYTES>>>();
    // GEMM2: output projection  (M=8192, N=1024)
    gemm_h_kernel<<<dim3(DMODEL / 128, ROWS / 128), 256, GSM_BYTES>>>(
        gOh, gw2t, b_out, out, 1);
}

// round 11
// speedup vs baseline: 6.6297x; 1.2660x over previous
#include <cuda_runtime.h>
#include <cuda_fp16.h>
#include <math.h>
#include <cstdint>

#define B_SZ   4
#define SEQ    2048
#define DMODEL 1024
#define NH     16
#define DH     64
#define ROWS   (B_SZ*SEQ)     // 8192
#define N_QKV  (3*DMODEL)     // 3072

// Scratch (allocation-free: device globals)
__device__ __half g_Qh[B_SZ*NH*SEQ*DH];  // fp16(Q), [bh][s][d]
__device__ __half g_Kh[B_SZ*NH*SEQ*DH];  // fp16(K), [bh][s][d]
__device__ __half g_Vh[B_SZ*NH*SEQ*DH];  // fp16(V), TRANSPOSED [bh][d][s]
__device__ __half g_Oh[ROWS*DMODEL];     // attention out fp16 (GEMM2 A)
__device__ __half g_xh[ROWS*DMODEL];     // fp16(x), [m][k]
__device__ __half g_w1t[N_QKV*DMODEL];   // fp16(w_in^T), [n][k]
__device__ __half g_w2t[DMODEL*DMODEL];  // fp16(w_out^T), [n][k]

// ============================================================================
// Helpers
// ============================================================================
__device__ __forceinline__ uint32_t pack_h2(float x, float y) {
    __half2 h = __floats2half2_rn(x, y);
    return *reinterpret_cast<uint32_t*>(&h);
}
__device__ __forceinline__ void mma_f16(float c[4],
    uint32_t a0, uint32_t a1, uint32_t a2, uint32_t a3,
    uint32_t b0, uint32_t b1)
{
    asm volatile(
        "mma.sync.aligned.m16n8k16.row.col.f32.f16.f16.f32 "
        "{%0,%1,%2,%3}, {%4,%5,%6,%7}, {%8,%9}, {%0,%1,%2,%3};"
        : "+f"(c[0]), "+f"(c[1]), "+f"(c[2]), "+f"(c[3])
        : "r"(a0), "r"(a1), "r"(a2), "r"(a3), "r"(b0), "r"(b1));
}
__device__ __forceinline__ uint32_t smem_u32(const void* p) {
    uint32_t a;
    asm("{ .reg .u64 t; cvta.to.shared.u64 t, %1; cvt.u32.u64 %0, t; }"
        : "=r"(a) : "l"(p));
    return a;
}
#define LDSM_X4(r0, r1, r2, r3, addr) \
    asm volatile("ldmatrix.sync.aligned.m8n8.x4.shared.b16 {%0,%1,%2,%3}, [%4];" \
        : "=r"(r0), "=r"(r1), "=r"(r2), "=r"(r3) : "r"(addr))
#define CP_ASYNC16(dst_u32, src_ptr) \
    asm volatile("cp.async.cg.shared.global [%0], [%1], 16;" \
                 :: "r"(dst_u32), "l"(src_ptr) : "memory")
#define CP_COMMIT  asm volatile("cp.async.commit_group;" ::: "memory")
#define CP_WAIT1   asm volatile("cp.async.wait_group 1;" ::: "memory")

// ============================================================================
// Pre-kernels: fp16 convert (x) and transpose+convert (weights)
// ============================================================================
__global__ __launch_bounds__(256) void cvt_h_kernel(
    const float4* __restrict__ src, uint2* __restrict__ dst, int n4)
{
    int i = blockIdx.x * blockDim.x + threadIdx.x;
    if (i < n4) {
        float4 v = src[i];
        uint2 o;
        o.x = pack_h2(v.x, v.y);
        o.y = pack_h2(v.z, v.w);
        dst[i] = o;
    }
}

// dst[n][k] = fp16(src[k][n]);  K,N multiples of 32
__global__ __launch_bounds__(256) void transp_h_kernel(
    const float* __restrict__ src, __half* __restrict__ dst, int K, int N)
{
    __shared__ float tile[32][33];
    int k0 = blockIdx.y * 32, n0 = blockIdx.x * 32;
    int tx = threadIdx.x & 31, ty = threadIdx.x >> 5;   // 32 x 8
#pragma unroll
    for (int i = 0; i < 32; i += 8)
        tile[ty + i][tx] = src[(size_t)(k0 + ty + i) * N + n0 + tx];
    __syncthreads();
#pragma unroll
    for (int i = 0; i < 32; i += 8)
        dst[(size_t)(n0 + ty + i) * K + k0 + tx] = __float2half_rn(tile[tx][ty + i]);
}

// ============================================================================
// fp16 mma.sync GEMM: C[M,N] = A[M,1024] @ Wt[N,1024]^T + bias
// CTA 128x128, 256 thr (8 warps of 64x32), K-chunk 32, 3-slot/2-preload ring,
// ONE barrier per k-chunk.
// mode 0: scatter (Q/K -> fp16 [bh][s][d], V -> fp16 transposed [bh][d][s])
// mode 1: Cout fp32 row-major
// ============================================================================
#define TILE_H (128 * 40)              // halves per A or B tile (80 B rows)
#define STAGE_B (2 * TILE_H * 2)       // bytes per stage: 20480
#define GSM_BYTES (3 * STAGE_B)        // 61440

__global__ __launch_bounds__(256, 2) void gemm_h_kernel(
    const __half* __restrict__ A,      // [M,1024]
    const __half* __restrict__ Wt,     // [N,1024]
    const float* __restrict__ bias,
    float* __restrict__ Cout,
    int mode)
{
    extern __shared__ char smc[];
    uint32_t smb = smem_u32(smc);
    int tid  = threadIdx.x;
    int wid  = tid >> 5, lane = tid & 31;
    int m0 = blockIdx.y * 128, n0 = blockIdx.x * 128;
    int warp_m = (wid & 1) * 64;
    int warp_n = (wid >> 1) * 32;

    const __half* a_src = A + (size_t)(m0 + (tid >> 1)) * DMODEL + (tid & 1) * 16;
    const __half* b_src = Wt + (size_t)(n0 + (tid >> 1)) * DMODEL + (tid & 1) * 16;
    uint32_t a_dst = smb + (tid >> 1) * 80 + (tid & 1) * 32;
    uint32_t b_dst = a_dst + TILE_H * 2;

    auto load_stage = [&](int s, int c) {
        int kc = c * 32;
        uint32_t so = s * STAGE_B;
#pragma unroll
        for (int q = 0; q < 2; q++) {
            CP_ASYNC16(a_dst + so + q * 16, a_src + kc + q * 8);
            CP_ASYNC16(b_dst + so + q * 16, b_src + kc + q * 8);
        }
    };

    float acc[4][4][4];
#pragma unroll
    for (int i = 0; i < 4; i++)
#pragma unroll
        for (int j = 0; j < 4; j++)
#pragma unroll
            for (int k = 0; k < 4; k++) acc[i][j][k] = 0.f;

    // ldmatrix lane addresses (byte offsets within a stage)
    int lrow = lane & 7, lt = lane >> 3;
    uint32_t aA[4], bA[2];
#pragma unroll
    for (int mt = 0; mt < 4; mt++)
        aA[mt] = smb + (warp_m + mt * 16 + lrow + (lt & 1) * 8) * 80 + (lt >> 1) * 16;
#pragma unroll
    for (int p = 0; p < 2; p++)
        bA[p] = smb + TILE_H * 2
              + (warp_n + p * 16 + lrow + (lt >> 1) * 8) * 80 + (lt & 1) * 16;

    load_stage(0, 0); CP_COMMIT;
    load_stage(1, 1); CP_COMMIT;

    for (int c = 0; c < 32; c++) {
        int s = c % 3;
        uint32_t so = s * STAGE_B;
        CP_WAIT1;                 // chunk c resident
        __syncthreads();          // all warps done with slot (c+2)%3's old data
        if (c + 2 < 32) load_stage((c + 2) % 3, c + 2);
        CP_COMMIT;

#pragma unroll
        for (int step = 0; step < 2; step++) {
            uint32_t kbb = so + step * 32;
            uint32_t af[4][4], bf[2][4];
#pragma unroll
            for (int mt = 0; mt < 4; mt++)
                LDSM_X4(af[mt][0], af[mt][1], af[mt][2], af[mt][3], aA[mt] + kbb);
#pragma unroll
            for (int p = 0; p < 2; p++)
                LDSM_X4(bf[p][0], bf[p][1], bf[p][2], bf[p][3], bA[p] + kbb);
#pragma unroll
            for (int mt = 0; mt < 4; mt++)
#pragma unroll
                for (int p = 0; p < 2; p++) {
                    mma_f16(acc[mt][2 * p], af[mt][0], af[mt][1], af[mt][2], af[mt][3],
                            bf[p][0], bf[p][1]);
                    mma_f16(acc[mt][2 * p + 1], af[mt][0], af[mt][1], af[mt][2], af[mt][3],
                            bf[p][2], bf[p][3]);
                }
        }
    }

    int crow = lane >> 2, ccol2 = (lane & 3) * 2;
#pragma unroll
    for (int mt = 0; mt < 4; mt++) {
#pragma unroll
        for (int nt = 0; nt < 4; nt++) {
            int n = n0 + warp_n + nt * 8 + ccol2;
            float bx = bias[n], by = bias[n + 1];
#pragma unroll
            for (int half = 0; half < 2; half++) {
                int m = m0 + warp_m + mt * 16 + crow + half * 8;
                float2 v;
                v.x = acc[mt][nt][half * 2 + 0] + bx;
                v.y = acc[mt][nt][half * 2 + 1] + by;
                if (mode == 1) {
                    *(float2*)(Cout + (size_t)m * DMODEL + n) = v;
                } else {
                    int b = m >> 11, srow = m & (SEQ - 1);
                    int chunk = n >> 10;
                    int cc = n & (DMODEL - 1);
                    int h = cc >> 6, d0 = cc & (DH - 1);
                    if (chunk == 2) {        // V -> fp16, transposed [bh][d][s]
                        size_t base = ((size_t)(b << 4) + h) * DH;
                        g_Vh[(base + d0) * SEQ + srow]     = __float2half_rn(v.x);
                        g_Vh[(base + d0 + 1) * SEQ + srow] = __float2half_rn(v.y);
                    } else {                 // K or Q -> fp16 [bh][s][d]
                        size_t off = (((size_t)(b << 4) + h) * SEQ + srow) * DH + d0;
                        uint32_t pk = pack_h2(v.x, v.y);
                        if (chunk == 0) *(uint32_t*)(g_Kh + off) = pk;
                        else            *(uint32_t*)(g_Qh + off) = pk;
                    }
                }
            }
        }
    }
}

// ============================================================================
// Flash attention. Br=128, Bc=64, 8 warps x 16 q-rows, 2 CTAs/SM.
// QK^T: fp16 m16n8k16 (Q frags hoisted to regs). PV: fp16, P register-resident.
// 3-slot cp.async K/V ring, ONE barrier per tile.
// ============================================================================
#define QSW 36   // Q/K/V row stride in words (72 halves, 144 B)
#define Q_OFF  0
#define K_OFF  4608                    // + s*2304  (64*36)
#define V_OFF  11520                   // + s*2304
#define AT_WORDS 18432
#define AT_BYTES (AT_WORDS * 4)        // 73728 B

__global__ __launch_bounds__(256, 2) void attn_mma_kernel()
{
    extern __shared__ uint32_t smw[];
    int tid = threadIdx.x;
    int wid = tid >> 5, lane = tid & 31;
    int bh = blockIdx.y;
    int q0 = blockIdx.x * 128;

    const __half* QG = g_Qh + ((size_t)bh * SEQ + q0) * DH;
    const __half* KG = g_Kh + (size_t)bh * SEQ * DH;
    const __half* VG = g_Vh + (size_t)bh * SEQ * DH;   // [d][s]

    uint32_t smb = smem_u32(smw);

    int krow = tid >> 2, kc4 = tid & 3;
    auto load_kv = [&](int s, int kt) {
        const __half* kp = KG + ((size_t)kt * 64 + krow) * DH;
        const __half* vp = VG + (size_t)krow * SEQ + kt * 64;
#pragma unroll
        for (int q = 0; q < 2; q++) {
            int eo = kc4 * 16 + q * 8;
            CP_ASYNC16(smb + (K_OFF + s * 2304) * 4 + krow * 144 + kc4 * 32 + q * 16,
                       kp + eo);
            CP_ASYNC16(smb + (V_OFF + s * 2304) * 4 + krow * 144 + kc4 * 32 + q * 16,
                       vp + eo);
        }
    };

    // group 0: Q tile + KV tile 0
    {
        int row = tid >> 1, half = (tid & 1);
#pragma unroll
        for (int q = 0; q < 4; q++) {
            int eo = half * 32 + q * 8;
            CP_ASYNC16(smb + Q_OFF * 4 + row * 144 + half * 64 + q * 16,
                       QG + row * DH + eo);
        }
    }
    load_kv(0, 0);
    CP_COMMIT;
    load_kv(1, 1);
    CP_COMMIT;

    int r0 = wid * 16 + (lane >> 2);  // query row (first half)
    int kq = lane & 3;
    int nq = lane >> 2;

    // ---- hoist Q fragments to registers (Q constant over kt loop) ----
    CP_WAIT1;                 // group 0 (Q + KV0) done
    __syncthreads();
    uint32_t qf[4][4];
    const uint32_t* Qs = smw + Q_OFF;
#pragma unroll
    for (int ks = 0; ks < 4; ks++) {
        qf[ks][0] = Qs[r0 * QSW + ks * 8 + kq];
        qf[ks][1] = Qs[(r0 + 8) * QSW + ks * 8 + kq];
        qf[ks][2] = Qs[r0 * QSW + ks * 8 + kq + 4];
        qf[ks][3] = Qs[(r0 + 8) * QSW + ks * 8 + kq + 4];
    }

    float m0v = -INFINITY, m1v = -INFINITY, l0v = 0.f, l1v = 0.f;
    float o[8][4];
#pragma unroll
    for (int nt = 0; nt < 8; nt++)
#pragma unroll
        for (int j = 0; j < 4; j++) o[nt][j] = 0.f;

    for (int kt = 0; kt < SEQ / 64; kt++) {
        int s = kt % 3;
        CP_WAIT1;
        __syncthreads();
        if (kt + 2 < SEQ / 64) load_kv((kt + 2) % 3, kt + 2);
        CP_COMMIT;

        const uint32_t* Ks = smw + K_OFF + s * 2304;
        const uint32_t* Vs = smw + V_OFF + s * 2304;

        // ---- S = Q K^T (fp16) ----
        float sc[8][4];
#pragma unroll
        for (int nt = 0; nt < 8; nt++)
#pragma unroll
            for (int j = 0; j < 4; j++) sc[nt][j] = 0.f;
#pragma unroll
        for (int ks = 0; ks < 4; ks++) {
            int kb = ks * 8;
#pragma unroll
            for (int nt = 0; nt < 8; nt++) {
                int n = nt * 8 + nq;
                uint32_t b0 = Ks[n * QSW + kb + kq];
                uint32_t b1 = Ks[n * QSW + kb + kq + 4];
                mma_f16(sc[nt], qf[ks][0], qf[ks][1], qf[ks][2], qf[ks][3], b0, b1);
            }
        }

        // ---- online softmax (rows r0, r0+8; scale 1/8); P -> fp16 regs ----
        float mx0 = sc[0][0], mx1 = sc[0][2];
#pragma unroll
        for (int nt = 0; nt < 8; nt++) {
            mx0 = fmaxf(mx0, fmaxf(sc[nt][0], sc[nt][1]));
            mx1 = fmaxf(mx1, fmaxf(sc[nt][2], sc[nt][3]));
        }
        mx0 = fmaxf(mx0, __shfl_xor_sync(0xffffffffu, mx0, 1));
        mx0 = fmaxf(mx0, __shfl_xor_sync(0xffffffffu, mx0, 2));
        mx1 = fmaxf(mx1, __shfl_xor_sync(0xffffffffu, mx1, 1));
        mx1 = fmaxf(mx1, __shfl_xor_sync(0xffffffffu, mx1, 2));
        float mn0 = fmaxf(m0v, mx0 * 0.125f);
        float mn1 = fmaxf(m1v, mx1 * 0.125f);
        float alf0 = __expf(m0v - mn0), alf1 = __expf(m1v - mn1);
        m0v = mn0; m1v = mn1;
        float rs0 = 0.f, rs1 = 0.f;
        uint32_t pa[4][4];
#pragma unroll
        for (int nt = 0; nt < 8; nt++) {
            float p0 = __expf(sc[nt][0] * 0.125f - mn0);
            float p1 = __expf(sc[nt][1] * 0.125f - mn0);
            float p2 = __expf(sc[nt][2] * 0.125f - mn1);
            float p3 = __expf(sc[nt][3] * 0.125f - mn1);
            rs0 += p0 + p1; rs1 += p2 + p3;
            int t = nt >> 1, hi = (nt & 1) * 2;
            pa[t][hi]     = pack_h2(p0, p1);
            pa[t][hi + 1] = pack_h2(p2, p3);
            o[nt][0] *= alf0; o[nt][1] *= alf0;
            o[nt][2] *= alf1; o[nt][3] *= alf1;
        }
        rs0 += __shfl_xor_sync(0xffffffffu, rs0, 1);
        rs0 += __shfl_xor_sync(0xffffffffu, rs0, 2);
        rs1 += __shfl_xor_sync(0xffffffffu, rs1, 1);
        rs1 += __shfl_xor_sync(0xffffffffu, rs1, 2);
        l0v = l0v * alf0 + rs0;
        l1v = l1v * alf1 + rs1;

        // ---- O += P V  (fp16, P from registers) ----
#pragma unroll
        for (int t = 0; t < 4; t++) {
#pragma unroll
            for (int nt = 0; nt < 8; nt++) {
                int n = nt * 8 + nq;            // d column
                uint32_t vb0 = Vs[n * QSW + t * 8 + kq];
                uint32_t vb1 = Vs[n * QSW + t * 8 + kq + 4];
                mma_f16(o[nt], pa[t][0], pa[t][1], pa[t][2], pa[t][3], vb0, vb1);
            }
        }
    }

    // ---- epilogue: normalize, fp16 for GEMM2, merge heads ----
    float inv0 = 1.f / l0v, inv1 = 1.f / l1v;
    int b = bh >> 4, h = bh & (NH - 1);
    int q = q0 + r0;
    __half* dst0 = g_Oh + ((size_t)(b * SEQ + q)) * DMODEL + h * DH;
    __half* dst1 = dst0 + 8 * DMODEL;
#pragma unroll
    for (int nt = 0; nt < 8; nt++) {
        int cb = nt * 8 + 2 * kq;
        *(uint32_t*)(dst0 + cb) = pack_h2(o[nt][0] * inv0, o[nt][1] * inv0);
        *(uint32_t*)(dst1 + cb) = pack_h2(o[nt][2] * inv1, o[nt][3] * inv1);
    }
}

// ---------------------------------------------------------------------------
extern "C" void kernel_launch(void* const* d_in, const int* in_sizes, int n_in,
                              void* d_out, int out_size) {
    (void)in_sizes; (void)n_in; (void)out_size;
    const float* x     = (const float*)d_in[0];
    const float* w_in  = (const float*)d_in[1];
    const float* b_in  = (const float*)d_in[2];
    const float* w_out = (const float*)d_in[3];
    const float* b_out = (const float*)d_in[4];
    float* out = (float*)d_out;

    cudaFuncSetAttribute(gemm_h_kernel,
                         cudaFuncAttributeMaxDynamicSharedMemorySize, GSM_BYTES);
    cudaFuncSetAttribute(attn_mma_kernel,
                         cudaFuncAttributeMaxDynamicSharedMemorySize, AT_BYTES);

    __half *gxh, *gw1t, *gw2t, *gOh;
    cudaGetSymbolAddress((void**)&gxh,  g_xh);
    cudaGetSymbolAddress((void**)&gw1t, g_w1t);
    cudaGetSymbolAddress((void**)&gw2t, g_w2t);
    cudaGetSymbolAddress((void**)&gOh,  g_Oh);

    // Pre: x -> fp16, weights -> transposed fp16
    {
        int n4 = ROWS * DMODEL / 4;
        cvt_h_kernel<<<(n4 + 255) / 256, 256>>>((const float4*)x, (uint2*)gxh, n4);
        transp_h_kernel<<<dim3(N_QKV / 32, DMODEL / 32), 256>>>(w_in, gw1t, DMODEL, N_QKV);
        transp_h_kernel<<<dim3(DMODEL / 32, DMODEL / 32), 256>>>(w_out, gw2t, DMODEL, DMODEL);
    }

    // GEMM1: QKV projection + scatter  (M=8192, N=3072)
    gemm_h_kernel<<<dim3(N_QKV / 128, ROWS / 128), 256, GSM_BYTES>>>(
        gxh, gw1t, b_in, nullptr, 0);
    // Attention: 16 q-tiles x 64 (b,h)
    attn_mma_kernel<<<dim3(SEQ / 128, B_SZ * NH), 256, AT_BYTES>>>();
    // GEMM2: output projection  (M=8192, N=1024)
    gemm_h_kernel<<<dim3(DMODEL / 128, ROWS / 128), 256, GSM_BYTES>>>(
        gOh, gw2t, b_out, out, 1);
}

// round 13
// speedup vs baseline: 6.9545x; 1.0490x over previous
#include <cuda_runtime.h>
#include <cuda_fp16.h>
#include <math.h>
#include <cstdint>

#define B_SZ   4
#define SEQ    2048
#define DMODEL 1024
#define NH     16
#define DH     64
#define ROWS   (B_SZ*SEQ)     // 8192
#define N_QKV  (3*DMODEL)     // 3072

// Scratch (allocation-free: device globals)
__device__ __half g_Qh[B_SZ*NH*SEQ*DH];  // fp16(Q), [bh][s][d]
__device__ __half g_Kh[B_SZ*NH*SEQ*DH];  // fp16(K), [bh][s][d]
__device__ __half g_Vh[B_SZ*NH*SEQ*DH];  // fp16(V), TRANSPOSED [bh][d][s]
__device__ __half g_Oh[ROWS*DMODEL];     // attention out fp16 (GEMM2 A)
__device__ __half g_xh[ROWS*DMODEL];     // fp16(x), [m][k]
__device__ __half g_w1t[N_QKV*DMODEL];   // fp16(w_in^T), [n][k]
__device__ __half g_w2t[DMODEL*DMODEL];  // fp16(w_out^T), [n][k]

// ============================================================================
// Helpers
// ============================================================================
__device__ __forceinline__ uint32_t pack_h2(float x, float y) {
    __half2 h = __floats2half2_rn(x, y);
    return *reinterpret_cast<uint32_t*>(&h);
}
// 2^x for a pair of floats -> packed fp16x2 (one cvt + one MUFU)
__device__ __forceinline__ uint32_t ex2_h2(float x, float y) {
    uint32_t h = pack_h2(x, y);
    uint32_t r;
    asm("ex2.approx.f16x2 %0, %1;" : "=r"(r) : "r"(h));
    return r;
}
__device__ __forceinline__ float ex2f(float x) {
    float r; asm("ex2.approx.f32 %0, %1;" : "=f"(r) : "f"(x)); return r;
}
__device__ __forceinline__ void mma_f16(float c[4],
    uint32_t a0, uint32_t a1, uint32_t a2, uint32_t a3,
    uint32_t b0, uint32_t b1)
{
    asm volatile(
        "mma.sync.aligned.m16n8k16.row.col.f32.f16.f16.f32 "
        "{%0,%1,%2,%3}, {%4,%5,%6,%7}, {%8,%9}, {%0,%1,%2,%3};"
        : "+f"(c[0]), "+f"(c[1]), "+f"(c[2]), "+f"(c[3])
        : "r"(a0), "r"(a1), "r"(a2), "r"(a3), "r"(b0), "r"(b1));
}
__device__ __forceinline__ uint32_t smem_u32(const void* p) {
    uint32_t a;
    asm("{ .reg .u64 t; cvta.to.shared.u64 t, %1; cvt.u32.u64 %0, t; }"
        : "=r"(a) : "l"(p));
    return a;
}
#define LDSM_X4(r0, r1, r2, r3, addr) \
    asm volatile("ldmatrix.sync.aligned.m8n8.x4.shared.b16 {%0,%1,%2,%3}, [%4];" \
        : "=r"(r0), "=r"(r1), "=r"(r2), "=r"(r3) : "r"(addr))
#define CP_ASYNC16(dst_u32, src_ptr) \
    asm volatile("cp.async.cg.shared.global [%0], [%1], 16;" \
                 :: "r"(dst_u32), "l"(src_ptr) : "memory")
#define CP_COMMIT  asm volatile("cp.async.commit_group;" ::: "memory")
#define CP_WAIT1   asm volatile("cp.async.wait_group 1;" ::: "memory")
#define CP_WAIT2   asm volatile("cp.async.wait_group 2;" ::: "memory")

#define H_ONES 0x3C003C00u   // half2(1.0, 1.0)

// ============================================================================
// Pre-kernels: fp16 convert (x) and transpose+convert (weights)
// ============================================================================
__global__ __launch_bounds__(256) void cvt_h_kernel(
    const float4* __restrict__ src, uint2* __restrict__ dst, int n4)
{
    int i = blockIdx.x * blockDim.x + threadIdx.x;
    if (i < n4) {
        float4 v = src[i];
        uint2 o;
        o.x = pack_h2(v.x, v.y);
        o.y = pack_h2(v.z, v.w);
        dst[i] = o;
    }
}

// dst[n][k] = fp16(src[k][n]);  K,N multiples of 32
__global__ __launch_bounds__(256) void transp_h_kernel(
    const float* __restrict__ src, __half* __restrict__ dst, int K, int N)
{
    __shared__ float tile[32][33];
    int k0 = blockIdx.y * 32, n0 = blockIdx.x * 32;
    int tx = threadIdx.x & 31, ty = threadIdx.x >> 5;   // 32 x 8
#pragma unroll
    for (int i = 0; i < 32; i += 8)
        tile[ty + i][tx] = src[(size_t)(k0 + ty + i) * N + n0 + tx];
    __syncthreads();
#pragma unroll
    for (int i = 0; i < 32; i += 8)
        dst[(size_t)(n0 + ty + i) * K + k0 + tx] = __float2half_rn(tile[tx][ty + i]);
}

// ============================================================================
// fp16 mma.sync GEMM: C[M,N] = A[M,1024] @ Wt[N,1024]^T + bias
// CTA 128x128, 256 thr (8 warps of 64x32), K-chunk 32, 4-slot/3-preload ring,
// ONE barrier per k-chunk.
// mode 0: scatter (Q/K -> fp16 [bh][s][d], V -> fp16 transposed [bh][d][s])
// mode 1: Cout fp32 row-major
// ============================================================================
#define TILE_H (128 * 40)              // halves per A or B tile (80 B rows)
#define STAGE_B (2 * TILE_H * 2)       // bytes per stage: 20480
#define GSM_BYTES (4 * STAGE_B)        // 81920

__global__ __launch_bounds__(256, 2) void gemm_h_kernel(
    const __half* __restrict__ A,      // [M,1024]
    const __half* __restrict__ Wt,     // [N,1024]
    const float* __restrict__ bias,
    float* __restrict__ Cout,
    int mode)
{
    extern __shared__ char smc[];
    uint32_t smb = smem_u32(smc);
    int tid  = threadIdx.x;
    int wid  = tid >> 5, lane = tid & 31;
    int m0 = blockIdx.y * 128, n0 = blockIdx.x * 128;
    int warp_m = (wid & 1) * 64;
    int warp_n = (wid >> 1) * 32;

    const __half* a_src = A + (size_t)(m0 + (tid >> 1)) * DMODEL + (tid & 1) * 16;
    const __half* b_src = Wt + (size_t)(n0 + (tid >> 1)) * DMODEL + (tid & 1) * 16;
    uint32_t a_dst = smb + (tid >> 1) * 80 + (tid & 1) * 32;
    uint32_t b_dst = a_dst + TILE_H * 2;

    auto load_stage = [&](int s, int c) {
        int kc = c * 32;
        uint32_t so = s * STAGE_B;
#pragma unroll
        for (int q = 0; q < 2; q++) {
            CP_ASYNC16(a_dst + so + q * 16, a_src + kc + q * 8);
            CP_ASYNC16(b_dst + so + q * 16, b_src + kc + q * 8);
        }
    };

    float acc[4][4][4];
#pragma unroll
    for (int i = 0; i < 4; i++)
#pragma unroll
        for (int j = 0; j < 4; j++)
#pragma unroll
            for (int k = 0; k < 4; k++) acc[i][j][k] = 0.f;

    // ldmatrix lane addresses (byte offsets within a stage)
    int lrow = lane & 7, lt = lane >> 3;
    uint32_t aA[4], bA[2];
#pragma unroll
    for (int mt = 0; mt < 4; mt++)
        aA[mt] = smb + (warp_m + mt * 16 + lrow + (lt & 1) * 8) * 80 + (lt >> 1) * 16;
#pragma unroll
    for (int p = 0; p < 2; p++)
        bA[p] = smb + TILE_H * 2
              + (warp_n + p * 16 + lrow + (lt >> 1) * 8) * 80 + (lt & 1) * 16;

    load_stage(0, 0); CP_COMMIT;
    load_stage(1, 1); CP_COMMIT;
    load_stage(2, 2); CP_COMMIT;

    for (int c = 0; c < 32; c++) {
        int s = c & 3;
        uint32_t so = s * STAGE_B;
        CP_WAIT2;                 // chunk c resident (2 groups may be pending)
        __syncthreads();          // all warps done with chunk c-1 (slot (c+3)&3)
        if (c + 3 < 32) load_stage((c + 3) & 3, c + 3);
        CP_COMMIT;

#pragma unroll
        for (int step = 0; step < 2; step++) {
            uint32_t kbb = so + step * 32;
            uint32_t af[4][4], bf[2][4];
#pragma unroll
            for (int mt = 0; mt < 4; mt++)
                LDSM_X4(af[mt][0], af[mt][1], af[mt][2], af[mt][3], aA[mt] + kbb);
#pragma unroll
            for (int p = 0; p < 2; p++)
                LDSM_X4(bf[p][0], bf[p][1], bf[p][2], bf[p][3], bA[p] + kbb);
#pragma unroll
            for (int mt = 0; mt < 4; mt++)
#pragma unroll
                for (int p = 0; p < 2; p++) {
                    mma_f16(acc[mt][2 * p], af[mt][0], af[mt][1], af[mt][2], af[mt][3],
                            bf[p][0], bf[p][1]);
                    mma_f16(acc[mt][2 * p + 1], af[mt][0], af[mt][1], af[mt][2], af[mt][3],
                            bf[p][2], bf[p][3]);
                }
        }
    }

    int crow = lane >> 2, ccol2 = (lane & 3) * 2;
#pragma unroll
    for (int mt = 0; mt < 4; mt++) {
#pragma unroll
        for (int nt = 0; nt < 4; nt++) {
            int n = n0 + warp_n + nt * 8 + ccol2;
            float bx = bias[n], by = bias[n + 1];
#pragma unroll
            for (int half = 0; half < 2; half++) {
                int m = m0 + warp_m + mt * 16 + crow + half * 8;
                float2 v;
                v.x = acc[mt][nt][half * 2 + 0] + bx;
                v.y = acc[mt][nt][half * 2 + 1] + by;
                if (mode == 1) {
                    *(float2*)(Cout + (size_t)m * DMODEL + n) = v;
                } else {
                    int b = m >> 11, srow = m & (SEQ - 1);
                    int chunk = n >> 10;
                    int cc = n & (DMODEL - 1);
                    int h = cc >> 6, d0 = cc & (DH - 1);
                    if (chunk == 2) {        // V -> fp16, transposed [bh][d][s]
                        size_t base = ((size_t)(b << 4) + h) * DH;
                        g_Vh[(base + d0) * SEQ + srow]     = __float2half_rn(v.x);
                        g_Vh[(base + d0 + 1) * SEQ + srow] = __float2half_rn(v.y);
                    } else {                 // K or Q -> fp16 [bh][s][d]
                        size_t off = (((size_t)(b << 4) + h) * SEQ + srow) * DH + d0;
                        uint32_t pk = pack_h2(v.x, v.y);
                        if (chunk == 0) *(uint32_t*)(g_Kh + off) = pk;
                        else            *(uint32_t*)(g_Qh + off) = pk;
                    }
                }
            }
        }
    }
}

// ============================================================================
// Flash attention. Br=128, Bc=64, 8 warps x 16 q-rows, 2 CTAs/SM.
// QK^T fp16 (Q frags in regs). Softmax in log2 domain with ex2.approx.f16x2;
// row sums via ones-MMA. PV fp16, P register-resident. 3-slot cp.async ring.
// ============================================================================
#define QSW 36   // Q/K/V row stride in words (72 halves, 144 B)
#define Q_OFF  0
#define K_OFF  4608                    // + s*2304  (64*36)
#define V_OFF  11520                   // + s*2304
#define AT_WORDS 18432
#define AT_BYTES (AT_WORDS * 4)        // 73728 B

__global__ __launch_bounds__(256, 2) void attn_mma_kernel()
{
    extern __shared__ uint32_t smw[];
    int tid = threadIdx.x;
    int wid = tid >> 5, lane = tid & 31;
    int bh = blockIdx.y;
    int q0 = blockIdx.x * 128;

    const __half* QG = g_Qh + ((size_t)bh * SEQ + q0) * DH;
    const __half* KG = g_Kh + (size_t)bh * SEQ * DH;
    const __half* VG = g_Vh + (size_t)bh * SEQ * DH;   // [d][s]

    uint32_t smb = smem_u32(smw);

    int krow = tid >> 2, kc4 = tid & 3;
    auto load_kv = [&](int s, int kt) {
        const __half* kp = KG + ((size_t)kt * 64 + krow) * DH;
        const __half* vp = VG + (size_t)krow * SEQ + kt * 64;
#pragma unroll
        for (int q = 0; q < 2; q++) {
            int eo = kc4 * 16 + q * 8;
            CP_ASYNC16(smb + (K_OFF + s * 2304) * 4 + krow * 144 + kc4 * 32 + q * 16,
                       kp + eo);
            CP_ASYNC16(smb + (V_OFF + s * 2304) * 4 + krow * 144 + kc4 * 32 + q * 16,
                       vp + eo);
        }
    };

    // group 0: Q tile + KV tile 0
    {
        int row = tid >> 1, half = (tid & 1);
#pragma unroll
        for (int q = 0; q < 4; q++) {
            int eo = half * 32 + q * 8;
            CP_ASYNC16(smb + Q_OFF * 4 + row * 144 + half * 64 + q * 16,
                       QG + row * DH + eo);
        }
    }
    load_kv(0, 0);
    CP_COMMIT;
    load_kv(1, 1);
    CP_COMMIT;

    int r0 = wid * 16 + (lane >> 2);  // query row (first half)
    int kq = lane & 3;
    int nq = lane >> 2;

    // ---- hoist Q fragments to registers ----
    CP_WAIT1;
    __syncthreads();
    uint32_t qf[4][4];
    const uint32_t* Qs = smw + Q_OFF;
#pragma unroll
    for (int ks = 0; ks < 4; ks++) {
        qf[ks][0] = Qs[r0 * QSW + ks * 8 + kq];
        qf[ks][1] = Qs[(r0 + 8) * QSW + ks * 8 + kq];
        qf[ks][2] = Qs[r0 * QSW + ks * 8 + kq + 4];
        qf[ks][3] = Qs[(r0 + 8) * QSW + ks * 8 + kq + 4];
    }

    // running max in log2 units: M = m * log2e; score coeff folds 1/8 * log2e
    const float c1 = 0.18033688011112042f;   // 0.125 * log2(e)
    float M0v = -INFINITY, M1v = -INFINITY, l0v = 0.f, l1v = 0.f;
    float o[8][4];
#pragma unroll
    for (int nt = 0; nt < 8; nt++)
#pragma unroll
        for (int j = 0; j < 4; j++) o[nt][j] = 0.f;

    for (int kt = 0; kt < SEQ / 64; kt++) {
        int s = kt % 3;
        CP_WAIT1;
        __syncthreads();
        if (kt + 2 < SEQ / 64) load_kv((kt + 2) % 3, kt + 2);
        CP_COMMIT;

        const uint32_t* Ks = smw + K_OFF + s * 2304;
        const uint32_t* Vs = smw + V_OFF + s * 2304;

        // ---- S = Q K^T (fp16) ----
        float sc[8][4];
#pragma unroll
        for (int nt = 0; nt < 8; nt++)
#pragma unroll
            for (int j = 0; j < 4; j++) sc[nt][j] = 0.f;
#pragma unroll
        for (int ks = 0; ks < 4; ks++) {
            int kb = ks * 8;
#pragma unroll
            for (int nt = 0; nt < 8; nt++) {
                int n = nt * 8 + nq;
                uint32_t b0 = Ks[n * QSW + kb + kq];
                uint32_t b1 = Ks[n * QSW + kb + kq + 4];
                mma_f16(sc[nt], qf[ks][0], qf[ks][1], qf[ks][2], qf[ks][3], b0, b1);
            }
        }

        // ---- softmax (log2 domain), P -> fp16x2 via ex2.approx.f16x2 ----
        float mx0 = sc[0][0], mx1 = sc[0][2];
#pragma unroll
        for (int nt = 0; nt < 8; nt++) {
            mx0 = fmaxf(mx0, fmaxf(sc[nt][0], sc[nt][1]));
            mx1 = fmaxf(mx1, fmaxf(sc[nt][2], sc[nt][3]));
        }
        mx0 = fmaxf(mx0, __shfl_xor_sync(0xffffffffu, mx0, 1));
        mx0 = fmaxf(mx0, __shfl_xor_sync(0xffffffffu, mx0, 2));
        mx1 = fmaxf(mx1, __shfl_xor_sync(0xffffffffu, mx1, 1));
        mx1 = fmaxf(mx1, __shfl_xor_sync(0xffffffffu, mx1, 2));
        float Mn0 = fmaxf(M0v, mx0 * c1);
        float Mn1 = fmaxf(M1v, mx1 * c1);
        float alf0 = ex2f(M0v - Mn0), alf1 = ex2f(M1v - Mn1);
        M0v = Mn0; M1v = Mn1;
        uint32_t pa[4][4];
#pragma unroll
        for (int nt = 0; nt < 8; nt++) {
            float u0 = fmaf(sc[nt][0], c1, -Mn0);
            float u1 = fmaf(sc[nt][1], c1, -Mn0);
            float u2 = fmaf(sc[nt][2], c1, -Mn1);
            float u3 = fmaf(sc[nt][3], c1, -Mn1);
            int t = nt >> 1, hi = (nt & 1) * 2;
            pa[t][hi]     = ex2_h2(u0, u1);
            pa[t][hi + 1] = ex2_h2(u2, u3);
            o[nt][0] *= alf0; o[nt][1] *= alf0;
            o[nt][2] *= alf1; o[nt][3] *= alf1;
        }

        // ---- O += P V ; row sums via ones-MMA ----
        float lacc[4] = {0.f, 0.f, 0.f, 0.f};
#pragma unroll
        for (int t = 0; t < 4; t++) {
            mma_f16(lacc, pa[t][0], pa[t][1], pa[t][2], pa[t][3], H_ONES, H_ONES);
#pragma unroll
            for (int nt = 0; nt < 8; nt++) {
                int n = nt * 8 + nq;            // d column
                uint32_t vb0 = Vs[n * QSW + t * 8 + kq];
                uint32_t vb1 = Vs[n * QSW + t * 8 + kq + 4];
                mma_f16(o[nt], pa[t][0], pa[t][1], pa[t][2], pa[t][3], vb0, vb1);
            }
        }
        l0v = l0v * alf0 + lacc[0];
        l1v = l1v * alf1 + lacc[2];
    }

    // ---- epilogue: normalize, fp16 for GEMM2, merge heads ----
    float inv0 = 1.f / l0v, inv1 = 1.f / l1v;
    int b = bh >> 4, h = bh & (NH - 1);
    int q = q0 + r0;
    __half* dst0 = g_Oh + ((size_t)(b * SEQ + q)) * DMODEL + h * DH;
    __half* dst1 = dst0 + 8 * DMODEL;
#pragma unroll
    for (int nt = 0; nt < 8; nt++) {
        int cb = nt * 8 + 2 * kq;
        *(uint32_t*)(dst0 + cb) = pack_h2(o[nt][0] * inv0, o[nt][1] * inv0);
        *(uint32_t*)(dst1 + cb) = pack_h2(o[nt][2] * inv1, o[nt][3] * inv1);
    }
}

// ---------------------------------------------------------------------------
extern "C" void kernel_launch(void* const* d_in, const int* in_sizes, int n_in,
                              void* d_out, int out_size) {
    (void)in_sizes; (void)n_in; (void)out_size;
    const float* x     = (const float*)d_in[0];
    const float* w_in  = (const float*)d_in[1];
    const float* b_in  = (const float*)d_in[2];
    const float* w_out = (const float*)d_in[3];
    const float* b_out = (const float*)d_in[4];
    float* out = (float*)d_out;

    cudaFuncSetAttribute(gemm_h_kernel,
                         cudaFuncAttributeMaxDynamicSharedMemorySize, GSM_BYTES);
    cudaFuncSetAttribute(attn_mma_kernel,
                         cudaFuncAttributeMaxDynamicSharedMemorySize, AT_BYTES);

    __half *gxh, *gw1t, *gw2t, *gOh;
    cudaGetSymbolAddress((void**)&gxh,  g_xh);
    cudaGetSymbolAddress((void**)&gw1t, g_w1t);
    cudaGetSymbolAddress((void**)&gw2t, g_w2t);
    cudaGetSymbolAddress((void**)&gOh,  g_Oh);

    // Pre: x -> fp16, weights -> transposed fp16
    {
        int n4 = ROWS * DMODEL / 4;
        cvt_h_kernel<<<(n4 + 255) / 256, 256>>>((const float4*)x, (uint2*)gxh, n4);
        transp_h_kernel<<<dim3(N_QKV / 32, DMODEL / 32), 256>>>(w_in, gw1t, DMODEL, N_QKV);
        transp_h_kernel<<<dim3(DMODEL / 32, DMODEL / 32), 256>>>(w_out, gw2t, DMODEL, DMODEL);
    }

    // GEMM1: QKV projection + scatter  (M=8192, N=3072)
    gemm_h_kernel<<<dim3(N_QKV / 128, ROWS / 128), 256, GSM_BYTES>>>(
        gxh, gw1t, b_in, nullptr, 0);
    // Attention: 16 q-tiles x 64 (b,h)
    attn_mma_kernel<<<dim3(SEQ / 128, B_SZ * NH), 256, AT_BYTES>>>();
    // GEMM2: output projection  (M=8192, N=1024)
    gemm_h_kernel<<<dim3(DMODEL / 128, ROWS / 128), 256, GSM_BYTES>>>(
        gOh, gw2t, b_out, out, 1);
}

// round 15
// speedup vs baseline: 7.3105x; 1.0512x over previous
#include <cuda_runtime.h>
#include <cuda_fp16.h>
#include <math.h>
#include <cstdint>

#define B_SZ   4
#define SEQ    2048
#define DMODEL 1024
#define NH     16
#define DH     64
#define ROWS   (B_SZ*SEQ)     // 8192
#define N_QKV  (3*DMODEL)     // 3072

// Scratch (allocation-free: device globals)
__device__ __half g_Qh[B_SZ*NH*SEQ*DH];  // fp16(Q), [bh][s][d]
__device__ __half g_Kh[B_SZ*NH*SEQ*DH];  // fp16(K), [bh][s][d]
__device__ __half g_Vh[B_SZ*NH*SEQ*DH];  // fp16(V), TRANSPOSED [bh][d][s]
__device__ __half g_Oh[ROWS*DMODEL];     // attention out fp16 (GEMM2 A)
__device__ __half g_xh[ROWS*DMODEL];     // fp16(x), [m][k]
__device__ __half g_w1t[N_QKV*DMODEL];   // fp16(w_in^T), [n][k]
__device__ __half g_w2t[DMODEL*DMODEL];  // fp16(w_out^T), [n][k]

// ============================================================================
// Helpers
// ============================================================================
__device__ __forceinline__ uint32_t pack_h2(float x, float y) {
    __half2 h = __floats2half2_rn(x, y);
    return *reinterpret_cast<uint32_t*>(&h);
}
// 2^x for a pair of floats -> packed fp16x2 (one cvt + one MUFU)
__device__ __forceinline__ uint32_t ex2_h2(float x, float y) {
    uint32_t h = pack_h2(x, y);
    uint32_t r;
    asm("ex2.approx.f16x2 %0, %1;" : "=r"(r) : "r"(h));
    return r;
}
__device__ __forceinline__ float ex2f(float x) {
    float r; asm("ex2.approx.f32 %0, %1;" : "=f"(r) : "f"(x)); return r;
}
__device__ __forceinline__ void mma_f16(float c[4],
    uint32_t a0, uint32_t a1, uint32_t a2, uint32_t a3,
    uint32_t b0, uint32_t b1)
{
    asm volatile(
        "mma.sync.aligned.m16n8k16.row.col.f32.f16.f16.f32 "
        "{%0,%1,%2,%3}, {%4,%5,%6,%7}, {%8,%9}, {%0,%1,%2,%3};"
        : "+f"(c[0]), "+f"(c[1]), "+f"(c[2]), "+f"(c[3])
        : "r"(a0), "r"(a1), "r"(a2), "r"(a3), "r"(b0), "r"(b1));
}
__device__ __forceinline__ uint32_t smem_u32(const void* p) {
    uint32_t a;
    asm("{ .reg .u64 t; cvta.to.shared.u64 t, %1; cvt.u32.u64 %0, t; }"
        : "=r"(a) : "l"(p));
    return a;
}
#define LDSM_X4(r0, r1, r2, r3, addr) \
    asm volatile("ldmatrix.sync.aligned.m8n8.x4.shared.b16 {%0,%1,%2,%3}, [%4];" \
        : "=r"(r0), "=r"(r1), "=r"(r2), "=r"(r3) : "r"(addr))
#define CP_ASYNC16(dst_u32, src_ptr) \
    asm volatile("cp.async.cg.shared.global [%0], [%1], 16;" \
                 :: "r"(dst_u32), "l"(src_ptr) : "memory")
#define CP_COMMIT  asm volatile("cp.async.commit_group;" ::: "memory")
#define CP_WAIT1   asm volatile("cp.async.wait_group 1;" ::: "memory")
#define CP_WAIT2   asm volatile("cp.async.wait_group 2;" ::: "memory")

#define H_ONES 0x3C003C00u   // half2(1.0, 1.0)

// ============================================================================
// Pre-kernels: fp16 convert (x) and transpose+convert (weights)
// ============================================================================
__global__ __launch_bounds__(256) void cvt_h_kernel(
    const float4* __restrict__ src, uint2* __restrict__ dst, int n4)
{
    int i = blockIdx.x * blockDim.x + threadIdx.x;
    if (i < n4) {
        float4 v = src[i];
        uint2 o;
        o.x = pack_h2(v.x, v.y);
        o.y = pack_h2(v.z, v.w);
        dst[i] = o;
    }
}

// dst[n][k] = fp16(src[k][n]);  K,N multiples of 32
__global__ __launch_bounds__(256) void transp_h_kernel(
    const float* __restrict__ src, __half* __restrict__ dst, int K, int N)
{
    __shared__ float tile[32][33];
    int k0 = blockIdx.y * 32, n0 = blockIdx.x * 32;
    int tx = threadIdx.x & 31, ty = threadIdx.x >> 5;   // 32 x 8
#pragma unroll
    for (int i = 0; i < 32; i += 8)
        tile[ty + i][tx] = src[(size_t)(k0 + ty + i) * N + n0 + tx];
    __syncthreads();
#pragma unroll
    for (int i = 0; i < 32; i += 8)
        dst[(size_t)(n0 + ty + i) * K + k0 + tx] = __float2half_rn(tile[tx][ty + i]);
}

// ============================================================================
// fp16 mma.sync GEMM: C[M,N] = A[M,1024] @ Wt[N,1024]^T + bias
// CTA 128x128, 256 thr (8 warps of 64x32), K-chunk 32, 4-slot/3-preload ring,
// ONE barrier per k-chunk.  (unchanged from R13)
// ============================================================================
#define TILE_H (128 * 40)              // halves per A or B tile (80 B rows)
#define STAGE_B (2 * TILE_H * 2)       // bytes per stage: 20480
#define GSM_BYTES (4 * STAGE_B)        // 81920

__global__ __launch_bounds__(256, 2) void gemm_h_kernel(
    const __half* __restrict__ A,      // [M,1024]
    const __half* __restrict__ Wt,     // [N,1024]
    const float* __restrict__ bias,
    float* __restrict__ Cout,
    int mode)
{
    extern __shared__ char smc[];
    uint32_t smb = smem_u32(smc);
    int tid  = threadIdx.x;
    int wid  = tid >> 5, lane = tid & 31;
    int m0 = blockIdx.y * 128, n0 = blockIdx.x * 128;
    int warp_m = (wid & 1) * 64;
    int warp_n = (wid >> 1) * 32;

    const __half* a_src = A + (size_t)(m0 + (tid >> 1)) * DMODEL + (tid & 1) * 16;
    const __half* b_src = Wt + (size_t)(n0 + (tid >> 1)) * DMODEL + (tid & 1) * 16;
    uint32_t a_dst = smb + (tid >> 1) * 80 + (tid & 1) * 32;
    uint32_t b_dst = a_dst + TILE_H * 2;

    auto load_stage = [&](int s, int c) {
        int kc = c * 32;
        uint32_t so = s * STAGE_B;
#pragma unroll
        for (int q = 0; q < 2; q++) {
            CP_ASYNC16(a_dst + so + q * 16, a_src + kc + q * 8);
            CP_ASYNC16(b_dst + so + q * 16, b_src + kc + q * 8);
        }
    };

    float acc[4][4][4];
#pragma unroll
    for (int i = 0; i < 4; i++)
#pragma unroll
        for (int j = 0; j < 4; j++)
#pragma unroll
            for (int k = 0; k < 4; k++) acc[i][j][k] = 0.f;

    // ldmatrix lane addresses (byte offsets within a stage)
    int lrow = lane & 7, lt = lane >> 3;
    uint32_t aA[4], bA[2];
#pragma unroll
    for (int mt = 0; mt < 4; mt++)
        aA[mt] = smb + (warp_m + mt * 16 + lrow + (lt & 1) * 8) * 80 + (lt >> 1) * 16;
#pragma unroll
    for (int p = 0; p < 2; p++)
        bA[p] = smb + TILE_H * 2
              + (warp_n + p * 16 + lrow + (lt >> 1) * 8) * 80 + (lt & 1) * 16;

    load_stage(0, 0); CP_COMMIT;
    load_stage(1, 1); CP_COMMIT;
    load_stage(2, 2); CP_COMMIT;

    for (int c = 0; c < 32; c++) {
        int s = c & 3;
        uint32_t so = s * STAGE_B;
        CP_WAIT2;
        __syncthreads();
        if (c + 3 < 32) load_stage((c + 3) & 3, c + 3);
        CP_COMMIT;

#pragma unroll
        for (int step = 0; step < 2; step++) {
            uint32_t kbb = so + step * 32;
            uint32_t af[4][4], bf[2][4];
#pragma unroll
            for (int mt = 0; mt < 4; mt++)
                LDSM_X4(af[mt][0], af[mt][1], af[mt][2], af[mt][3], aA[mt] + kbb);
#pragma unroll
            for (int p = 0; p < 2; p++)
                LDSM_X4(bf[p][0], bf[p][1], bf[p][2], bf[p][3], bA[p] + kbb);
#pragma unroll
            for (int mt = 0; mt < 4; mt++)
#pragma unroll
                for (int p = 0; p < 2; p++) {
                    mma_f16(acc[mt][2 * p], af[mt][0], af[mt][1], af[mt][2], af[mt][3],
                            bf[p][0], bf[p][1]);
                    mma_f16(acc[mt][2 * p + 1], af[mt][0], af[mt][1], af[mt][2], af[mt][3],
                            bf[p][2], bf[p][3]);
                }
        }
    }

    int crow = lane >> 2, ccol2 = (lane & 3) * 2;
#pragma unroll
    for (int mt = 0; mt < 4; mt++) {
#pragma unroll
        for (int nt = 0; nt < 4; nt++) {
            int n = n0 + warp_n + nt * 8 + ccol2;
            float bx = bias[n], by = bias[n + 1];
#pragma unroll
            for (int half = 0; half < 2; half++) {
                int m = m0 + warp_m + mt * 16 + crow + half * 8;
                float2 v;
                v.x = acc[mt][nt][half * 2 + 0] + bx;
                v.y = acc[mt][nt][half * 2 + 1] + by;
                if (mode == 1) {
                    *(float2*)(Cout + (size_t)m * DMODEL + n) = v;
                } else {
                    int b = m >> 11, srow = m & (SEQ - 1);
                    int chunk = n >> 10;
                    int cc = n & (DMODEL - 1);
                    int h = cc >> 6, d0 = cc & (DH - 1);
                    if (chunk == 2) {        // V -> fp16, transposed [bh][d][s]
                        size_t base = ((size_t)(b << 4) + h) * DH;
                        g_Vh[(base + d0) * SEQ + srow]     = __float2half_rn(v.x);
                        g_Vh[(base + d0 + 1) * SEQ + srow] = __float2half_rn(v.y);
                    } else {                 // K or Q -> fp16 [bh][s][d]
                        size_t off = (((size_t)(b << 4) + h) * SEQ + srow) * DH + d0;
                        uint32_t pk = pack_h2(v.x, v.y);
                        if (chunk == 0) *(uint32_t*)(g_Kh + off) = pk;
                        else            *(uint32_t*)(g_Qh + off) = pk;
                    }
                }
            }
        }
    }
}

// ============================================================================
// Flash attention. Br=128, Bc=64, 8 warps x 16 q-rows, 2 CTAs/SM.
// QK^T fp16 (Q frags in regs, K/V frags via ldmatrix.x4). log2-domain softmax
// with ex2.approx.f16x2; row sums via ones-MMA; P register-resident.
// ============================================================================
#define QSW 36   // Q/K/V row stride in words (72 halves, 144 B)
#define Q_OFF  0
#define K_OFF  4608                    // + s*2304  (64*36)
#define V_OFF  11520                   // + s*2304
#define AT_WORDS 18432
#define AT_BYTES (AT_WORDS * 4)        // 73728 B

__global__ __launch_bounds__(256, 2) void attn_mma_kernel()
{
    extern __shared__ uint32_t smw[];
    int tid = threadIdx.x;
    int wid = tid >> 5, lane = tid & 31;
    int bh = blockIdx.y;
    int q0 = blockIdx.x * 128;

    const __half* QG = g_Qh + ((size_t)bh * SEQ + q0) * DH;
    const __half* KG = g_Kh + (size_t)bh * SEQ * DH;
    const __half* VG = g_Vh + (size_t)bh * SEQ * DH;   // [d][s]

    uint32_t smb = smem_u32(smw);

    int krow = tid >> 2, kc4 = tid & 3;
    auto load_kv = [&](int s, int kt) {
        const __half* kp = KG + ((size_t)kt * 64 + krow) * DH;
        const __half* vp = VG + (size_t)krow * SEQ + kt * 64;
#pragma unroll
        for (int q = 0; q < 2; q++) {
            int eo = kc4 * 16 + q * 8;
            CP_ASYNC16(smb + (K_OFF + s * 2304) * 4 + krow * 144 + kc4 * 32 + q * 16,
                       kp + eo);
            CP_ASYNC16(smb + (V_OFF + s * 2304) * 4 + krow * 144 + kc4 * 32 + q * 16,
                       vp + eo);
        }
    };

    // group 0: Q tile + KV tile 0
    {
        int row = tid >> 1, half = (tid & 1);
#pragma unroll
        for (int q = 0; q < 4; q++) {
            int eo = half * 32 + q * 8;
            CP_ASYNC16(smb + Q_OFF * 4 + row * 144 + half * 64 + q * 16,
                       QG + row * DH + eo);
        }
    }
    load_kv(0, 0);
    CP_COMMIT;
    load_kv(1, 1);
    CP_COMMIT;

    int r0 = wid * 16 + (lane >> 2);  // query row (first half)
    int kq = lane & 3;

    // ldmatrix lane addresses for K/V fragments (base, slot 0)
    int lrow = lane & 7, lt = lane >> 3;
    uint32_t kA[4], vA[4];
#pragma unroll
    for (int g = 0; g < 4; g++) {
        uint32_t roff = (g * 16 + lrow + (lt >> 1) * 8) * 144 + (lt & 1) * 16;
        kA[g] = smb + K_OFF * 4 + roff;
        vA[g] = smb + V_OFF * 4 + roff;
    }

    // ---- hoist Q fragments to registers ----
    CP_WAIT1;
    __syncthreads();
    uint32_t qf[4][4];
    const uint32_t* Qs = smw + Q_OFF;
#pragma unroll
    for (int ks = 0; ks < 4; ks++) {
        qf[ks][0] = Qs[r0 * QSW + ks * 8 + kq];
        qf[ks][1] = Qs[(r0 + 8) * QSW + ks * 8 + kq];
        qf[ks][2] = Qs[r0 * QSW + ks * 8 + kq + 4];
        qf[ks][3] = Qs[(r0 + 8) * QSW + ks * 8 + kq + 4];
    }

    // running max in log2 units: M = m * log2e; score coeff folds 1/8 * log2e
    const float c1 = 0.18033688011112042f;   // 0.125 * log2(e)
    float M0v = -INFINITY, M1v = -INFINITY, l0v = 0.f, l1v = 0.f;
    float o[8][4];
#pragma unroll
    for (int nt = 0; nt < 8; nt++)
#pragma unroll
        for (int j = 0; j < 4; j++) o[nt][j] = 0.f;

    for (int kt = 0; kt < SEQ / 64; kt++) {
        int s = kt % 3;
        uint32_t so = s * 9216;    // slot byte offset (2304 words)
        CP_WAIT1;
        __syncthreads();
        if (kt + 2 < SEQ / 64) load_kv((kt + 2) % 3, kt + 2);
        CP_COMMIT;

        // ---- S = Q K^T (fp16, K frags via ldmatrix) ----
        float sc[8][4];
#pragma unroll
        for (int nt = 0; nt < 8; nt++)
#pragma unroll
            for (int j = 0; j < 4; j++) sc[nt][j] = 0.f;
#pragma unroll
        for (int ks = 0; ks < 4; ks++) {
            uint32_t kbb = so + ks * 32;
#pragma unroll
            for (int g = 0; g < 4; g++) {
                uint32_t bf0, bf1, bf2, bf3;
                LDSM_X4(bf0, bf1, bf2, bf3, kA[g] + kbb);
                mma_f16(sc[2 * g],     qf[ks][0], qf[ks][1], qf[ks][2], qf[ks][3], bf0, bf1);
                mma_f16(sc[2 * g + 1], qf[ks][0], qf[ks][1], qf[ks][2], qf[ks][3], bf2, bf3);
            }
        }

        // ---- softmax (log2 domain), P -> fp16x2 via ex2.approx.f16x2 ----
        float mx0 = sc[0][0], mx1 = sc[0][2];
#pragma unroll
        for (int nt = 0; nt < 8; nt++) {
            mx0 = fmaxf(mx0, fmaxf(sc[nt][0], sc[nt][1]));
            mx1 = fmaxf(mx1, fmaxf(sc[nt][2], sc[nt][3]));
        }
        mx0 = fmaxf(mx0, __shfl_xor_sync(0xffffffffu, mx0, 1));
        mx0 = fmaxf(mx0, __shfl_xor_sync(0xffffffffu, mx0, 2));
        mx1 = fmaxf(mx1, __shfl_xor_sync(0xffffffffu, mx1, 1));
        mx1 = fmaxf(mx1, __shfl_xor_sync(0xffffffffu, mx1, 2));
        float Mn0 = fmaxf(M0v, mx0 * c1);
        float Mn1 = fmaxf(M1v, mx1 * c1);
        float alf0 = ex2f(M0v - Mn0), alf1 = ex2f(M1v - Mn1);
        M0v = Mn0; M1v = Mn1;
        uint32_t pa[4][4];
#pragma unroll
        for (int nt = 0; nt < 8; nt++) {
            float u0 = fmaf(sc[nt][0], c1, -Mn0);
            float u1 = fmaf(sc[nt][1], c1, -Mn0);
            float u2 = fmaf(sc[nt][2], c1, -Mn1);
            float u3 = fmaf(sc[nt][3], c1, -Mn1);
            int t = nt >> 1, hi = (nt & 1) * 2;
            pa[t][hi]     = ex2_h2(u0, u1);
            pa[t][hi + 1] = ex2_h2(u2, u3);
            o[nt][0] *= alf0; o[nt][1] *= alf0;
            o[nt][2] *= alf1; o[nt][3] *= alf1;
        }

        // ---- O += P V (V frags via ldmatrix) ; row sums via ones-MMA ----
        float lacc[4] = {0.f, 0.f, 0.f, 0.f};
#pragma unroll
        for (int t = 0; t < 4; t++) {
            uint32_t kbb = so + t * 32;
            mma_f16(lacc, pa[t][0], pa[t][1], pa[t][2], pa[t][3], H_ONES, H_ONES);
#pragma unroll
            for (int g = 0; g < 4; g++) {
                uint32_t bf0, bf1, bf2, bf3;
                LDSM_X4(bf0, bf1, bf2, bf3, vA[g] + kbb);
                mma_f16(o[2 * g],     pa[t][0], pa[t][1], pa[t][2], pa[t][3], bf0, bf1);
                mma_f16(o[2 * g + 1], pa[t][0], pa[t][1], pa[t][2], pa[t][3], bf2, bf3);
            }
        }
        l0v = l0v * alf0 + lacc[0];
        l1v = l1v * alf1 + lacc[2];
    }

    // ---- epilogue: normalize, fp16 for GEMM2, merge heads ----
    float inv0 = 1.f / l0v, inv1 = 1.f / l1v;
    int b = bh >> 4, h = bh & (NH - 1);
    int q = q0 + r0;
    __half* dst0 = g_Oh + ((size_t)(b * SEQ + q)) * DMODEL + h * DH;
    __half* dst1 = dst0 + 8 * DMODEL;
#pragma unroll
    for (int nt = 0; nt < 8; nt++) {
        int cb = nt * 8 + 2 * kq;
        *(uint32_t*)(dst0 + cb) = pack_h2(o[nt][0] * inv0, o[nt][1] * inv0);
        *(uint32_t*)(dst1 + cb) = pack_h2(o[nt][2] * inv1, o[nt][3] * inv1);
    }
}

// ---------------------------------------------------------------------------
extern "C" void kernel_launch(void* const* d_in, const int* in_sizes, int n_in,
                              void* d_out, int out_size) {
    (void)in_sizes; (void)n_in; (void)out_size;
    const float* x     = (const float*)d_in[0];
    const float* w_in  = (const float*)d_in[1];
    const float* b_in  = (const float*)d_in[2];
    const float* w_out = (const float*)d_in[3];
    const float* b_out = (const float*)d_in[4];
    float* out = (float*)d_out;

    cudaFuncSetAttribute(gemm_h_kernel,
                         cudaFuncAttributeMaxDynamicSharedMemorySize, GSM_BYTES);
    cudaFuncSetAttribute(attn_mma_kernel,
                         cudaFuncAttributeMaxDynamicSharedMemorySize, AT_BYTES);

    __half *gxh, *gw1t, *gw2t, *gOh;
    cudaGetSymbolAddress((void**)&gxh,  g_xh);
    cudaGetSymbolAddress((void**)&gw1t, g_w1t);
    cudaGetSymbolAddress((void**)&gw2t, g_w2t);
    cudaGetSymbolAddress((void**)&gOh,  g_Oh);

    // Pre: x -> fp16, weights -> transposed fp16
    {
        int n4 = ROWS * DMODEL / 4;
        cvt_h_kernel<<<(n4 + 255) / 256, 256>>>((const float4*)x, (uint2*)gxh, n4);
        transp_h_kernel<<<dim3(N_QKV / 32, DMODEL / 32), 256>>>(w_in, gw1t, DMODEL, N_QKV);
        transp_h_kernel<<<dim3(DMODEL / 32, DMODEL / 32), 256>>>(w_out, gw2t, DMODEL, DMODEL);
    }

    // GEMM1: QKV projection + scatter  (M=8192, N=3072)
    gemm_h_kernel<<<dim3(N_QKV / 128, ROWS / 128), 256, GSM_BYTES>>>(
        gxh, gw1t, b_in, nullptr, 0);
    // Attention: 16 q-tiles x 64 (b,h)
    attn_mma_kernel<<<dim3(SEQ / 128, B_SZ * NH), 256, AT_BYTES>>>();
    // GEMM2: output projection  (M=8192, N=1024)
    gemm_h_kernel<<<dim3(DMODEL / 128, ROWS / 128), 256, GSM_BYTES>>>(
        gOh, gw2t, b_out, out, 1);
}